// round 10
// baseline (speedup 1.0000x reference)
#include <cuda_runtime.h>
#include <cuda_fp16.h>
#include <cstdint>

// ---------------- problem constants ----------------
constexpr int NEg   = 100000;
constexpr int NAg   = 5000;
constexpr int DDg   = 512;
constexpr int DTg   = 64;
constexpr int NCBF  = 16;

constexpr float INV_SQRT2 = 0.70710678118654752f;
constexpr float ACT_SCALE = 1.0f / 0.6f;

// ---------------- scratch pool (float units) ----------------
constexpr size_t NE512  = (size_t)NEg * DDg;
constexpr size_t NE64   = (size_t)NEg * DTg;
constexpr size_t NE1024 = (size_t)NEg * 1024;
constexpr size_t NE16   = (size_t)NEg * 16;
constexpr size_t NA512  = (size_t)NAg * DDg;

constexpr size_t OFF_XCA  = 0;                       // fp32 NE512
constexpr size_t OFF_TMP  = OFF_XCA + NE512;         // fp32 NE512
constexpr size_t OFF_UP   = OFF_TMP + NE512;         // fp32 NE512 (UP2 spans UP+MB)
constexpr size_t OFF_MB   = OFF_UP  + NE512;         // fp32 NE512
constexpr size_t OFF_A1   = OFF_MB  + NE512;         // fp32 NA512
constexpr size_t OFF_A2   = OFF_A1  + NA512;         // fp32 NA512
// half regions
constexpr size_t OFF_MH   = OFF_A2   + NA512;
constexpr size_t OFF_TMPH = OFF_MH   + NE512 / 2;
constexpr size_t OFF_XCAH = OFF_TMPH + NE512 / 2;
constexpr size_t OFF_MBH  = OFF_XCAH + NE512 / 2;
constexpr size_t OFF_DWNH = OFF_MBH  + NE512 / 2;
constexpr size_t OFF_XBH  = OFF_DWNH + NE64 / 2;
constexpr size_t OFF_T2H  = OFF_XBH  + NE64 / 2;
constexpr size_t OFF_R3H  = OFF_T2H  + NE1024 / 2;
constexpr size_t OFF_RHH  = OFF_R3H  + NE16 / 2;
constexpr size_t OFF_A1H  = OFF_RHH  + NE16 / 2;
constexpr size_t OFF_A2H  = OFF_A1H  + NA512 / 2;
constexpr size_t OFF_A3H  = OFF_A2H  + NA512 / 2;
constexpr size_t OFF_OHH  = OFF_A3H  + NA512 / 2;
constexpr size_t OFF_WTSH = OFF_OHH  + NA512 / 2;
constexpr size_t WTSH_FLOATS = 3u * 1024 * 1024;
constexpr size_t POOL_TOTAL = OFF_WTSH + WTSH_FLOATS;

__device__ __align__(256) float g_pool[POOL_TOTAL];

// ---------------- helpers ----------------
__device__ __forceinline__ float scaled_silu(float x) {
    return x * (1.0f / (1.0f + __expf(-x))) * ACT_SCALE;
}
__device__ __forceinline__ void mma_f16(float4& d, const uint32_t a[4], const uint32_t b[2]) {
    asm volatile(
        "mma.sync.aligned.m16n8k16.row.col.f32.f16.f16.f32 "
        "{%0,%1,%2,%3}, {%4,%5,%6,%7}, {%8,%9}, {%0,%1,%2,%3};"
        : "+f"(d.x), "+f"(d.y), "+f"(d.z), "+f"(d.w)
        : "r"(a[0]), "r"(a[1]), "r"(a[2]), "r"(a[3]), "r"(b[0]), "r"(b[1]));
}
__device__ __forceinline__ void ldsm_x4(uint32_t& r0, uint32_t& r1, uint32_t& r2, uint32_t& r3,
                                        uint32_t addr) {
    asm volatile("ldmatrix.sync.aligned.m8n8.x4.shared.b16 {%0,%1,%2,%3}, [%4];"
                 : "=r"(r0), "=r"(r1), "=r"(r2), "=r"(r3) : "r"(addr));
}
__device__ __forceinline__ void cp16(uint32_t smem_dst, const void* gsrc, int szbytes) {
    asm volatile("cp.async.cg.shared.global [%0], [%1], 16, %2;"
                 :: "r"(smem_dst), "l"(gsrc), "r"(szbytes));
}
__device__ __forceinline__ void cp_commit() { asm volatile("cp.async.commit_group;"); }
template <int N> __device__ __forceinline__ void cp_wait() {
    asm volatile("cp.async.wait_group %0;" :: "n"(N));
}

// ---------------- fp16 tensor-core GEMM ----------------
enum { F_ACT = 1, F_MUL = 2, F_ADD1 = 4, F_ADD2 = 8, F_CAT = 16, F_HALF = 32, F_NOF32 = 64,
       F_MULH = 128 };

constexpr int SAK = 40;
constexpr int NSTAGE = 4;
constexpr int AS_BYTES = 128 * SAK * 2;
constexpr int STAGE_BYTES = 2 * AS_BYTES;
constexpr int SMEM_DYN = NSTAGE * STAGE_BYTES;        // 81920

__device__ __forceinline__ void epi2(float* C, __half* Ct, size_t idx, float vx, float vy,
                                     int flags, const float* Emul, const __half* Emulh,
                                     const float* Add1, float c1,
                                     const float* Add2, float c2) {
    if (flags & F_ACT)  { vx = scaled_silu(vx);       vy = scaled_silu(vy); }
    if (flags & F_MUL)  { vx *= Emul[idx];            vy *= Emul[idx + 1]; }
    if (flags & F_MULH) {
        float2 e = __half22float2(*(const __half2*)(Emulh + idx));
        vx *= e.x; vy *= e.y;
    }
    if (flags & F_ADD1) { vx = (Add1[idx] + vx) * c1; vy = (Add1[idx + 1] + vy) * c1; }
    if (flags & F_ADD2) { vx = (vx + Add2[idx]) * c2; vy = (vy + Add2[idx + 1]) * c2; }
    if (flags & F_HALF) *(__half2*)(Ct + idx) = __floats2half2_rn(vx, vy);
    if (!(flags & F_NOF32)) { C[idx] = vx; C[idx + 1] = vy; }
}

__global__ __launch_bounds__(256, 2)
void mma_gemm_kernel(const __half* __restrict__ A, const __half* __restrict__ Bt,
                     float* __restrict__ C, __half* __restrict__ Ct,
                     int M, int N, int K, int flags,
                     const float* __restrict__ Emul, const __half* __restrict__ Emulh,
                     const float* __restrict__ Add1, float c1,
                     const float* __restrict__ Add2, float c2,
                     const __half* __restrict__ Hg, const int* __restrict__ idxs,
                     const int* __restrict__ idxt, const __half* __restrict__ Mg)
{
    extern __shared__ __align__(16) char dyn_smem[];

    const int t = threadIdx.x;
    const int lane = t & 31;
    const int warp = t >> 5;
    const int wm = (warp >> 2) * 64;
    const int wn = (warp & 3) * 32;
    const int rowC0 = blockIdx.y * 128;
    const int colC0 = blockIdx.x * 128;

    const uint32_t smem0 = (uint32_t)__cvta_generic_to_shared(dyn_smem);

    const int arow_l = t & 127;
    const int ako = (t >> 7) * 16;
    const int arow = rowC0 + arow_l;
    const bool aok = arow < M;
    int isg = 0, itg = 0;
    if ((flags & F_CAT) && aok) { isg = idxs[arow]; itg = idxt[arow]; }
    const uint32_t a_dst = smem0 + (uint32_t)(arow_l * SAK + ako) * 2;

    const int brow_l = t & 127;
    const bool bok = (colC0 + brow_l) < N;
    const __half* brp = Bt + (size_t)(bok ? (colC0 + brow_l) : 0) * K;
    const uint32_t b_dst = smem0 + AS_BYTES + (uint32_t)(brow_l * SAK + ako) * 2;

    const int a_row_lm = wm + (lane & 15);
    const int a_kh_lm  = (lane >> 4) * 8;
    const int b_row_lm = wn + (lane & 7) + (lane >> 4) * 8;
    const int b_kh_lm  = ((lane >> 3) & 1) * 8;

    float4 acc[4][4];
#pragma unroll
    for (int i = 0; i < 4; i++)
#pragma unroll
        for (int j = 0; j < 4; j++) acc[i][j] = make_float4(0.f, 0.f, 0.f, 0.f);

    auto loadTile = [&](int s, int k0) {
        const uint32_t soff = (uint32_t)s * STAGE_BYTES;
        const __half* ap;
        if (!(flags & F_CAT)) {
            ap = A + (size_t)(aok ? arow : 0) * K + k0 + ako;
        } else {
            const int k = k0 + ako;
            if (k < 512)       ap = Hg + (size_t)isg * 512 + k;
            else if (k < 1024) ap = Hg + (size_t)itg * 512 + (k - 512);
            else               ap = Mg + (size_t)(aok ? arow : 0) * 512 + (k - 1024);
        }
#pragma unroll
        for (int ch = 0; ch < 2; ch++) {
            const bool ok = aok && (k0 + ako + ch * 8) < K;
            cp16(a_dst + soff + 16u * ch, ok ? (const void*)(ap + 8 * ch) : (const void*)A,
                 ok ? 16 : 0);
        }
        const __half* bp = brp + k0 + ako;
#pragma unroll
        for (int ch = 0; ch < 2; ch++) {
            const bool ok = bok && (k0 + ako + ch * 8) < K;
            cp16(b_dst + soff + 16u * ch, ok ? (const void*)(bp + 8 * ch) : (const void*)Bt,
                 ok ? 16 : 0);
        }
    };

    auto computeTile = [&](int s) {
        const uint32_t abase = smem0 + (uint32_t)s * STAGE_BYTES;
        const uint32_t bbase = abase + AS_BYTES;
#pragma unroll
        for (int g = 0; g < 2; g++) {
            uint32_t af[4][4];
            uint32_t bf[4][2];
#pragma unroll
            for (int mt = 0; mt < 4; mt++)
                ldsm_x4(af[mt][0], af[mt][1], af[mt][2], af[mt][3],
                        abase + (uint32_t)((a_row_lm + mt * 16) * SAK + g * 16 + a_kh_lm) * 2);
#pragma unroll
            for (int p = 0; p < 2; p++)
                ldsm_x4(bf[2 * p][0], bf[2 * p][1], bf[2 * p + 1][0], bf[2 * p + 1][1],
                        bbase + (uint32_t)((b_row_lm + p * 16) * SAK + g * 16 + b_kh_lm) * 2);
#pragma unroll
            for (int mt = 0; mt < 4; mt++)
#pragma unroll
                for (int nt = 0; nt < 4; nt++)
                    mma_f16(acc[mt][nt], af[mt], bf[nt]);
        }
    };

    const int nK = (K + 31) >> 5;
    const int pre = nK < (NSTAGE - 1) ? nK : (NSTAGE - 1);
    for (int s = 0; s < pre; s++) { loadTile(s, s * 32); cp_commit(); }

    for (int i = 0; i < nK; ++i) {
        const int rem = nK - 1 - i;
        if (rem >= 2)      cp_wait<2>();
        else if (rem == 1) cp_wait<1>();
        else               cp_wait<0>();
        __syncthreads();
        if (i + NSTAGE - 1 < nK) { loadTile((i + NSTAGE - 1) & 3, (i + NSTAGE - 1) * 32); cp_commit(); }
        computeTile(i & 3);
    }

#pragma unroll
    for (int mt = 0; mt < 4; mt++) {
        const int r = rowC0 + wm + mt * 16 + (lane >> 2);
#pragma unroll
        for (int nt = 0; nt < 4; nt++) {
            const int cc = colC0 + wn + nt * 8 + (lane & 3) * 2;
            if (cc >= N) continue;
            const float4 v = acc[mt][nt];
            if (r < M)
                epi2(C, Ct, (size_t)r * N + cc, v.x, v.y, flags, Emul, Emulh, Add1, c1, Add2, c2);
            if (r + 8 < M)
                epi2(C, Ct, (size_t)(r + 8) * N + cc, v.z, v.w, flags, Emul, Emulh, Add1, c1, Add2, c2);
        }
    }
}

// ---------------- fp32 -> fp16 conversion ----------------
__global__ void conv_half_kernel(const float* __restrict__ src, __half* __restrict__ dst, int n4) {
    const int i = blockIdx.x * blockDim.x + threadIdx.x;
    if (i >= n4) return;
    float4 v = ((const float4*)src)[i];
    __half2* d = (__half2*)dst + 2 * i;
    d[0] = __floats2half2_rn(v.x, v.y);
    d[1] = __floats2half2_rn(v.z, v.w);
}

// ---------------- batched 512x512 weight transpose via pointer table ----------------
struct TPtrs { const float* src[16]; __half* dst[16]; };

__global__ void transpose512_batch_kernel(TPtrs p) {
    __shared__ float tile[32][33];
    const float* src = p.src[blockIdx.z];
    __half* dst = p.dst[blockIdx.z];
    const int kb = blockIdx.y * 32, nb = blockIdx.x * 32;
    const int tx = threadIdx.x, ty = threadIdx.y;
#pragma unroll
    for (int dy = 0; dy < 32; dy += 8)
        tile[ty + dy][tx] = src[(size_t)(kb + ty + dy) * 512 + nb + tx];
    __syncthreads();
#pragma unroll
    for (int dy = 0; dy < 32; dy += 8)
        dst[(size_t)(nb + ty + dy) * 512 + kb + tx] = __float2half_rn(tile[tx][ty + dy]);
}

// generic transpose -> half (non-square / odd shapes)
__global__ void transpose_half_kernel(const float* __restrict__ src, __half* __restrict__ dst,
                                      int K, int N) {
    __shared__ float tile[32][33];
    const int kb = blockIdx.y * 32, nb = blockIdx.x * 32;
    const int tx = threadIdx.x, ty = threadIdx.y;
#pragma unroll
    for (int dy = 0; dy < 32; dy += 8) {
        const int k = kb + ty + dy, n = nb + tx;
        if (k < K && n < N) tile[ty + dy][tx] = src[(size_t)k * N + n];
    }
    __syncthreads();
#pragma unroll
    for (int dy = 0; dy < 32; dy += 8) {
        const int n = nb + ty + dy, k = kb + tx;
        if (n < N && k < K) dst[(size_t)n * K + k] = __float2half_rn(tile[tx][ty + dy]);
    }
}

// ---------------- triplet tmp2 ----------------
__global__ void triplet_tmp2_kernel(const __half* __restrict__ down,
                                    const int* __restrict__ id3_ba,
                                    const float* __restrict__ sph,
                                    const float* __restrict__ rbfw1,
                                    __half* __restrict__ t2)
{
    __shared__ int   sIdx[256];
    __shared__ float sS[16 * 112];
    __shared__ float sR[16 * 112];

    const int tid = threadIdx.x;
    const int e0 = blockIdx.x * 16;

    sIdx[tid] = id3_ba[(size_t)e0 * 16 + tid];
    for (int r = tid; r < 16 * 112; r += 256) {
        sS[r] = sph  [(size_t)e0 * 112 + r];
        sR[r] = rbfw1[(size_t)e0 * 112 + r];
    }
    __syncthreads();

    const int team = tid >> 4;
    const int j = tid & 15;
    const int edge = e0 + team;

    float4 G[16];
#pragma unroll
    for (int k = 0; k < 16; k++) {
        const int row = sIdx[team * 16 + k];
        const __half2* dp = (const __half2*)(down + (size_t)row * 64 + j * 4);
        float2 lo = __half22float2(dp[0]);
        float2 hi = __half22float2(dp[1]);
        G[k] = make_float4(lo.x, lo.y, hi.x, hi.y);
    }

    float4 t1[7];
#pragma unroll
    for (int s = 0; s < 7; s++) {
        float4 a = make_float4(0.f, 0.f, 0.f, 0.f);
#pragma unroll
        for (int k = 0; k < 16; k++) {
            const float f = sS[team * 112 + s * 16 + k];
            a.x = fmaf(f, G[k].x, a.x); a.y = fmaf(f, G[k].y, a.y);
            a.z = fmaf(f, G[k].z, a.z); a.w = fmaf(f, G[k].w, a.w);
        }
        t1[s] = a;
    }

#pragma unroll
    for (int i = 0; i < 16; i++) {
        float4 a = make_float4(0.f, 0.f, 0.f, 0.f);
#pragma unroll
        for (int s = 0; s < 7; s++) {
            const float f = sR[team * 112 + i * 7 + s];
            a.x = fmaf(f, t1[s].x, a.x); a.y = fmaf(f, t1[s].y, a.y);
            a.z = fmaf(f, t1[s].z, a.z); a.w = fmaf(f, t1[s].w, a.w);
        }
        __half2* out = (__half2*)(t2 + (size_t)edge * 1024 + i * 64 + j * 4);
        out[0] = __floats2half2_rn(a.x, a.y);
        out[1] = __floats2half2_rn(a.z, a.w);
    }
}

// W_bil[e,i,o] -> WBPh[o][i*64+e]
__global__ void permute_wbil_kernel(const float* __restrict__ wb, __half* __restrict__ out) {
    const int idx = blockIdx.x * blockDim.x + threadIdx.x;
    const int o = idx & 63;
    const int i = (idx >> 6) & 15;
    const int e = idx >> 10;
    out[(size_t)o * 1024 + i * 64 + e] = __float2half_rn(wb[((size_t)(e * 16 + i)) * 64 + o]);
}

// x = (xca_skip + (up2[:,0:512] + up2[id_swap,512:1024])*c)*c
__global__ void combine_x_kernel(float* xca, __half* xcah, const float* __restrict__ up2,
                                 const int* __restrict__ id_swap) {
    const int idx = blockIdx.x * blockDim.x + threadIdx.x;   // NE*128 float4s
    const int e = idx >> 7;
    const int c = idx & 127;
    const int es = id_swap[e];
    float4 a = ((const float4*)up2)[(size_t)e * 256 + c];
    float4 b = ((const float4*)up2)[(size_t)es * 256 + 128 + c];
    float4 x = ((float4*)xca)[idx];
    x.x = (x.x + (a.x + b.x) * INV_SQRT2) * INV_SQRT2;
    x.y = (x.y + (a.y + b.y) * INV_SQRT2) * INV_SQRT2;
    x.z = (x.z + (a.z + b.z) * INV_SQRT2) * INV_SQRT2;
    x.w = (x.w + (a.w + b.w) * INV_SQRT2) * INV_SQRT2;
    ((float4*)xca)[idx] = x;
    __half2* xh = (__half2*)xcah + 2 * idx;
    xh[0] = __floats2half2_rn(x.x, x.y);
    xh[1] = __floats2half2_rn(x.z, x.w);
}

// segment-sum: out[idx_t[e]] += m[e]*r2h[e]
__global__ void scatter_atoms_kernel(const float* __restrict__ m, const __half* __restrict__ r2h,
                                     const int* __restrict__ idx_t, float* out) {
    const int idx = blockIdx.x * blockDim.x + threadIdx.x;
    const int e = idx >> 7;
    const int c = idx & 127;
    const int t = idx_t[e];
    float4 a = ((const float4*)m)[idx];
    const __half2* bp = (const __half2*)r2h + 2 * idx;
    float2 b0 = __half22float2(bp[0]);
    float2 b1 = __half22float2(bp[1]);
    float* dst = out + (size_t)t * 512 + c * 4;
    atomicAdd(dst + 0, a.x * b0.x);
    atomicAdd(dst + 1, a.y * b0.y);
    atomicAdd(dst + 2, a.z * b1.x);
    atomicAdd(dst + 3, a.w * b1.y);
}

// ---------------- host orchestration ----------------
static void run_gemm(const __half* A, const __half* Bt, float* C, int M, int N, int K, int flags,
                     __half* Ct = nullptr,
                     const float* E = nullptr, const __half* Eh = nullptr,
                     const float* Ad1 = nullptr, float c1 = 1.f,
                     const float* Ad2 = nullptr, float c2 = 1.f,
                     const __half* Hg = nullptr, const int* isx = nullptr,
                     const int* itx = nullptr, const __half* Mg = nullptr)
{
    static bool attr_set = false;
    if (!attr_set) {
        cudaFuncSetAttribute(mma_gemm_kernel, cudaFuncAttributeMaxDynamicSharedMemorySize, SMEM_DYN);
        attr_set = true;
    }
    dim3 grid((N + 127) / 128, (M + 127) / 128);
    mma_gemm_kernel<<<grid, 256, SMEM_DYN>>>(A, Bt, C, Ct, M, N, K, flags,
                                             E, Eh, Ad1, c1, Ad2, c2, Hg, isx, itx, Mg);
}
static void run_conv(const float* src, __half* dst, size_t n) {
    const int n4 = (int)(n / 4);
    conv_half_kernel<<<(n4 + 255) / 256, 256>>>(src, dst, n4);
}
static void run_transpose(const float* src, __half* dst, int K, int N) {
    dim3 grid((N + 31) / 32, (K + 31) / 32);
    transpose_half_kernel<<<grid, dim3(32, 8)>>>(src, dst, K, N);
}

extern "C" void kernel_launch(void* const* d_in, const int* in_sizes, int n_in,
                              void* d_out, int out_size)
{
    const float* h_in    = (const float*)d_in[0];
    const float* m_in    = (const float*)d_in[1];
    const float* rbf3    = (const float*)d_in[2];
    const float* rbf_w1  = (const float*)d_in[3];
    const float* sph     = (const float*)d_in[4];
    const float* rbf_h   = (const float*)d_in[5];
    const int*   id3_ba  = (const int*)d_in[6];
    const int*   id_swap = (const int*)d_in[9];
    const int*   idx_s   = (const int*)d_in[10];
    const int*   idx_t   = (const int*)d_in[11];
    const float* W_dense_ca = (const float*)d_in[12];
    const float* W_ba    = (const float*)d_in[13];
    const float* W_rbf3  = (const float*)d_in[14];
    const float* W_down  = (const float*)d_in[15];
    const float* W_bil   = (const float*)d_in[16];
    const float* W_up_ca = (const float*)d_in[17];
    const float* W_up_ac = (const float*)d_in[18];
    const float* W_bs    = (const float*)d_in[19];
    const float* W_as    = (const float*)d_in[20];
    const float* W_au_rbf= (const float*)d_in[21];
    const float* W_au_d1 = (const float*)d_in[22];
    const float* W_au_res= (const float*)d_in[23];
    const float* W_cat   = (const float*)d_in[24];
    const float* W_res_m = (const float*)d_in[25];

    float* pool = nullptr;
    cudaGetSymbolAddress((void**)&pool, g_pool);
    float*  XCA  = pool + OFF_XCA;
    float*  TMP  = pool + OFF_TMP;
    float*  UP2  = pool + OFF_UP;     // spans UP+MB when used as [NE][1024]
    float*  Mb   = pool + OFF_MB;
    float*  A1   = pool + OFF_A1;
    float*  A2   = pool + OFF_A2;
    __half* Mh   = (__half*)(pool + OFF_MH);
    __half* TMPh = (__half*)(pool + OFF_TMPH);
    __half* XCAh = (__half*)(pool + OFF_XCAH);
    __half* Mbh  = (__half*)(pool + OFF_MBH);
    __half* DWNh = (__half*)(pool + OFF_DWNH);
    __half* XBh  = (__half*)(pool + OFF_XBH);
    __half* T2h  = (__half*)(pool + OFF_T2H);
    __half* R3h  = (__half*)(pool + OFF_R3H);
    __half* RHh  = (__half*)(pool + OFF_RHH);
    __half* A1h  = (__half*)(pool + OFF_A1H);
    __half* A2h  = (__half*)(pool + OFF_A2H);
    __half* A3h  = (__half*)(pool + OFF_A3H);
    __half* OHh  = (__half*)(pool + OFF_OHH);
    __half* WH   = (__half*)(pool + OFF_WTSH);

    const size_t W2 = (size_t)DDg * DDg;
    __half* Wh_dense_ca = WH;            size_t woff = W2;
    __half* Wh_ba       = WH + woff;     woff += W2;
    __half* Wh_rbf3     = WH + woff;     woff += (size_t)DDg * 16;
    __half* Wh_down     = WH + woff;     woff += (size_t)DTg * DDg;
    __half* Wh_up_ca    = WH + woff;     woff += (size_t)DDg * DTg;
    __half* Wh_up_ac    = WH + woff;     woff += (size_t)DDg * DTg;   // contiguous after up_ca
    __half* Wh_bs       = WH + woff;     woff += 2 * W2;
    __half* Wh_as       = WH + woff;     woff += 4 * W2;
    __half* Wh_au_rbf   = WH + woff;     woff += (size_t)DDg * 16;
    __half* Wh_au_d1    = WH + woff;     woff += W2;
    __half* Wh_au_res   = WH + woff;     woff += 6 * W2;
    __half* Wh_cat      = WH + woff;     woff += 3 * W2;
    __half* Wh_res_m    = WH + woff;     woff += 2 * W2;
    __half* WBPh        = WH + woff;     woff += (size_t)DTg * 1024;

    float* OUT_H = (float*)d_out;
    float* OUT_M = (float*)d_out + NA512;

    const float C = INV_SQRT2;

    // ---- pre-conversions ----
    run_conv(m_in, Mh, NE512);
    run_conv(rbf3, R3h, NE16);
    run_conv(rbf_h, RHh, NE16);
    // batched 512x512 transposes (15 matrices)
    {
        TPtrs tp{};
        int n = 0;
        tp.src[n] = W_dense_ca; tp.dst[n] = Wh_dense_ca; n++;
        tp.src[n] = W_ba;       tp.dst[n] = Wh_ba;       n++;
        tp.src[n] = W_au_d1;    tp.dst[n] = Wh_au_d1;    n++;
        for (int i = 0; i < 2; i++) { tp.src[n] = W_bs + i * W2;     tp.dst[n] = Wh_bs + i * W2;     n++; }
        for (int i = 0; i < 4; i++) { tp.src[n] = W_as + i * W2;     tp.dst[n] = Wh_as + i * W2;     n++; }
        for (int i = 0; i < 6; i++) { tp.src[n] = W_au_res + i * W2; tp.dst[n] = Wh_au_res + i * W2; n++; }
        dim3 grid(16, 16, n);
        transpose512_batch_kernel<<<grid, dim3(32, 8)>>>(tp);
    }
    {
        TPtrs tp{};
        tp.src[0] = W_res_m;      tp.dst[0] = Wh_res_m;
        tp.src[1] = W_res_m + W2; tp.dst[1] = Wh_res_m + W2;
        transpose512_batch_kernel<<<dim3(16, 16, 2), dim3(32, 8)>>>(tp);
    }
    run_transpose(W_rbf3, Wh_rbf3, 16, DDg);
    run_transpose(W_down, Wh_down, DDg, DTg);
    run_transpose(W_up_ca, Wh_up_ca, DTg, DDg);
    run_transpose(W_up_ac, Wh_up_ac, DTg, DDg);
    run_transpose(W_au_rbf, Wh_au_rbf, 16, DDg);
    run_transpose(W_cat, Wh_cat, 3 * DDg, DDg);
    permute_wbil_kernel<<<(NCBF * DTg * DTg) / 256, 256>>>(W_bil, WBPh);

    // ---- pipeline ----
    // Rh (half) = rbf3 @ W_rbf3  (stored in XCAh, free until combine_x)
    run_gemm(R3h, Wh_rbf3, nullptr, NEg, DDg, 16, F_HALF | F_NOF32, XCAh);
    // TMPh = half(act(m @ W_ba) * Rh)
    run_gemm(Mh, Wh_ba, nullptr, NEg, DDg, DDg, F_ACT | F_MULH | F_HALF | F_NOF32,
             TMPh, nullptr, XCAh);
    run_gemm(TMPh, Wh_down, nullptr, NEg, DTg, DDg, F_ACT | F_HALF | F_NOF32, DWNh);
    run_gemm(Mh, Wh_dense_ca, XCA, NEg, DDg, DDg, F_ACT);

    triplet_tmp2_kernel<<<NEg / 16, 256>>>(DWNh, id3_ba, sph, rbf_w1, T2h);
    run_gemm(T2h, WBPh, nullptr, NEg, DTg, NCBF * DTg, F_HALF | F_NOF32, XBh);

    // merged up projection: N=1024 (Wh_up_ca ++ Wh_up_ac contiguous), out UP2 fp32
    run_gemm(XBh, Wh_up_ca, UP2, NEg, 1024, DTg, F_ACT);
    combine_x_kernel<<<(NEg * 128) / 256, 256>>>(XCA, XCAh, UP2, id_swap);

    run_gemm(XCAh, Wh_bs, nullptr, NEg, DDg, DDg, F_ACT | F_HALF | F_NOF32, TMPh);
    run_gemm(TMPh, Wh_bs + W2, Mb, NEg, DDg, DDg, F_ACT | F_ADD1 | F_ADD2 | F_HALF,
             Mbh, nullptr, nullptr, XCA, C, m_in, C);

    run_gemm(Mbh, Wh_as + 0 * W2, nullptr, NEg, DDg, DDg, F_ACT | F_HALF | F_NOF32, TMPh);
    run_gemm(TMPh, Wh_as + 1 * W2, Mb, NEg, DDg, DDg, F_ACT | F_ADD1 | F_HALF,
             Mbh, nullptr, nullptr, Mb, C);
    run_gemm(Mbh, Wh_as + 2 * W2, nullptr, NEg, DDg, DDg, F_ACT | F_HALF | F_NOF32, TMPh);
    run_gemm(TMPh, Wh_as + 3 * W2, Mb, NEg, DDg, DDg, F_ACT | F_ADD1 | F_HALF,
             Mbh, nullptr, nullptr, Mb, C);

    // R2h (half) = rbf_h @ W_au_rbf  (stored in TMPh, free in this window)
    run_gemm(RHh, Wh_au_rbf, nullptr, NEg, DDg, 16, F_HALF | F_NOF32, TMPh);
    cudaMemsetAsync(A1, 0, NA512 * sizeof(float));
    scatter_atoms_kernel<<<(NEg * 128) / 256, 256>>>(Mb, TMPh, idx_t, A1);
    run_conv(A1, A1h, NA512);
    run_gemm(A1h, Wh_au_d1, A2, NAg, DDg, DDg, F_ACT | F_HALF, A2h);
    run_gemm(A2h, Wh_au_res + 0 * W2, nullptr, NAg, DDg, DDg, F_ACT | F_HALF | F_NOF32, A3h);
    run_gemm(A3h, Wh_au_res + 1 * W2, A2, NAg, DDg, DDg, F_ACT | F_ADD1 | F_HALF,
             A2h, nullptr, nullptr, A2, C);
    run_gemm(A2h, Wh_au_res + 2 * W2, nullptr, NAg, DDg, DDg, F_ACT | F_HALF | F_NOF32, A3h);
    run_gemm(A3h, Wh_au_res + 3 * W2, A2, NAg, DDg, DDg, F_ACT | F_ADD1 | F_HALF,
             A2h, nullptr, nullptr, A2, C);
    run_gemm(A2h, Wh_au_res + 4 * W2, nullptr, NAg, DDg, DDg, F_ACT | F_HALF | F_NOF32, A3h);
    run_gemm(A3h, Wh_au_res + 5 * W2, OUT_H, NAg, DDg, DDg,
             F_ACT | F_ADD1 | F_ADD2 | F_HALF, OHh, nullptr, nullptr, A2, C, h_in, C);

    run_gemm(nullptr, Wh_cat, XCA, NEg, DDg, 3 * DDg, F_ACT | F_CAT | F_HALF,
             XCAh, nullptr, nullptr, nullptr, 1.f, nullptr, 1.f, OHh, idx_s, idx_t, Mbh);

    run_gemm(XCAh, Wh_res_m, nullptr, NEg, DDg, DDg, F_ACT | F_HALF | F_NOF32, TMPh);
    run_gemm(TMPh, Wh_res_m + W2, OUT_M, NEg, DDg, DDg, F_ACT | F_ADD1 | F_ADD2,
             nullptr, nullptr, nullptr, XCA, C, Mb, C);

    (void)in_sizes; (void)n_in; (void)out_size;
}

// round 11
// speedup vs baseline: 1.0385x; 1.0385x over previous
#include <cuda_runtime.h>
#include <cuda_fp16.h>
#include <cstdint>

// ---------------- problem constants ----------------
constexpr int NEg   = 100000;
constexpr int NAg   = 5000;
constexpr int DDg   = 512;
constexpr int DTg   = 64;
constexpr int NCBF  = 16;

constexpr float INV_SQRT2 = 0.70710678118654752f;
constexpr float ACT_SCALE = 1.0f / 0.6f;

// ---------------- scratch pool (float units) ----------------
constexpr size_t NE512  = (size_t)NEg * DDg;
constexpr size_t NE64   = (size_t)NEg * DTg;
constexpr size_t NE1024 = (size_t)NEg * 1024;
constexpr size_t NE16   = (size_t)NEg * 16;
constexpr size_t NA512  = (size_t)NAg * DDg;

constexpr size_t OFF_XCA  = 0;
constexpr size_t OFF_TMP  = OFF_XCA + NE512;
constexpr size_t OFF_UP   = OFF_TMP + NE512;         // UP2 spans UP+MB
constexpr size_t OFF_MB   = OFF_UP  + NE512;
constexpr size_t OFF_A1   = OFF_MB  + NE512;
constexpr size_t OFF_A2   = OFF_A1  + NA512;
constexpr size_t OFF_MH   = OFF_A2   + NA512;
constexpr size_t OFF_TMPH = OFF_MH   + NE512 / 2;
constexpr size_t OFF_XCAH = OFF_TMPH + NE512 / 2;
constexpr size_t OFF_MBH  = OFF_XCAH + NE512 / 2;
constexpr size_t OFF_DWNH = OFF_MBH  + NE512 / 2;
constexpr size_t OFF_XBH  = OFF_DWNH + NE64 / 2;
constexpr size_t OFF_T2H  = OFF_XBH  + NE64 / 2;
constexpr size_t OFF_R3H  = OFF_T2H  + NE1024 / 2;
constexpr size_t OFF_RHH  = OFF_R3H  + NE16 / 2;
constexpr size_t OFF_A1H  = OFF_RHH  + NE16 / 2;
constexpr size_t OFF_A2H  = OFF_A1H  + NA512 / 2;
constexpr size_t OFF_A3H  = OFF_A2H  + NA512 / 2;
constexpr size_t OFF_OHH  = OFF_A3H  + NA512 / 2;
constexpr size_t OFF_WTSH = OFF_OHH  + NA512 / 2;
constexpr size_t WTSH_FLOATS = 3u * 1024 * 1024;
constexpr size_t POOL_TOTAL = OFF_WTSH + WTSH_FLOATS;

__device__ __align__(256) float g_pool[POOL_TOTAL];

// ---------------- helpers ----------------
__device__ __forceinline__ float scaled_silu(float x) {
    return x * (1.0f / (1.0f + __expf(-x))) * ACT_SCALE;
}
__device__ __forceinline__ void mma_f16(float4& d, const uint32_t a[4], const uint32_t b[2]) {
    asm volatile(
        "mma.sync.aligned.m16n8k16.row.col.f32.f16.f16.f32 "
        "{%0,%1,%2,%3}, {%4,%5,%6,%7}, {%8,%9}, {%0,%1,%2,%3};"
        : "+f"(d.x), "+f"(d.y), "+f"(d.z), "+f"(d.w)
        : "r"(a[0]), "r"(a[1]), "r"(a[2]), "r"(a[3]), "r"(b[0]), "r"(b[1]));
}
__device__ __forceinline__ void ldsm_x4(uint32_t& r0, uint32_t& r1, uint32_t& r2, uint32_t& r3,
                                        uint32_t addr) {
    asm volatile("ldmatrix.sync.aligned.m8n8.x4.shared.b16 {%0,%1,%2,%3}, [%4];"
                 : "=r"(r0), "=r"(r1), "=r"(r2), "=r"(r3) : "r"(addr));
}
__device__ __forceinline__ void cp16(uint32_t smem_dst, const void* gsrc, int szbytes) {
    asm volatile("cp.async.cg.shared.global [%0], [%1], 16, %2;"
                 :: "r"(smem_dst), "l"(gsrc), "r"(szbytes));
}
__device__ __forceinline__ void cp_commit() { asm volatile("cp.async.commit_group;"); }
template <int N> __device__ __forceinline__ void cp_wait() {
    asm volatile("cp.async.wait_group %0;" :: "n"(N));
}

// ---------------- fp16 tensor-core GEMM ----------------
enum { F_ACT = 1, F_MUL = 2, F_ADD1 = 4, F_ADD2 = 8, F_CAT = 16, F_HALF = 32, F_NOF32 = 64,
       F_RBFMUL = 128, F_SCATH = 256 };

constexpr int SAK = 40;
constexpr int NSTAGE = 4;
constexpr int AS_BYTES = 128 * SAK * 2;
constexpr int STAGE_BYTES = 2 * AS_BYTES;
constexpr int SMEM_DYN = NSTAGE * STAGE_BYTES;        // 81920

// rbf epilogue tiles: 128 rows x 16 halves, row stride 24 halves (conflict-free ldmatrix)
constexpr int RBS = 24;
constexpr int RB_BYTES = 128 * RBS * 2;               // 6144
constexpr int RB_B_OFF = RB_BYTES;

__device__ __forceinline__ void epi2(float* C, __half* Ct, __half* Sc, size_t idx,
                                     float vx, float vy, float mx, float my,
                                     int flags, const float* Add1, float c1,
                                     const float* Add2, float c2) {
    if (flags & F_ACT)    { vx = scaled_silu(vx);       vy = scaled_silu(vy); }
    if (flags & F_RBFMUL) { vx *= mx;                   vy *= my; }
    if (flags & F_ADD1)   { vx = (Add1[idx] + vx) * c1; vy = (Add1[idx + 1] + vy) * c1; }
    if (flags & F_ADD2)   { vx = (vx + Add2[idx]) * c2; vy = (vy + Add2[idx + 1]) * c2; }
    if (flags & F_SCATH)  *(__half2*)(Sc + idx) = __floats2half2_rn(vx * mx, vy * my);
    if (flags & F_HALF)   *(__half2*)(Ct + idx) = __floats2half2_rn(vx, vy);
    if (!(flags & F_NOF32)) { C[idx] = vx; C[idx + 1] = vy; }
}

__global__ __launch_bounds__(256, 2)
void mma_gemm_kernel(const __half* __restrict__ A, const __half* __restrict__ Bt,
                     float* __restrict__ C, __half* __restrict__ Ct,
                     int M, int N, int K, int flags,
                     const float* __restrict__ Add1, float c1,
                     const float* __restrict__ Add2, float c2,
                     const __half* __restrict__ Hg, const int* __restrict__ idxs,
                     const int* __restrict__ idxt, const __half* __restrict__ Mg,
                     const __half* __restrict__ Rbf, const __half* __restrict__ Wrb,
                     __half* __restrict__ Scath)
{
    extern __shared__ __align__(16) char dyn_smem[];

    const int t = threadIdx.x;
    const int lane = t & 31;
    const int warp = t >> 5;
    const int wm = (warp >> 2) * 64;
    const int wn = (warp & 3) * 32;
    const int rowC0 = blockIdx.y * 128;
    const int colC0 = blockIdx.x * 128;

    const uint32_t smem0 = (uint32_t)__cvta_generic_to_shared(dyn_smem);

    const int arow_l = t & 127;
    const int ako = (t >> 7) * 16;
    const int arow = rowC0 + arow_l;
    const bool aok = arow < M;
    int isg = 0, itg = 0;
    if ((flags & F_CAT) && aok) { isg = idxs[arow]; itg = idxt[arow]; }
    const uint32_t a_dst = smem0 + (uint32_t)(arow_l * SAK + ako) * 2;

    const int brow_l = t & 127;
    const bool bok = (colC0 + brow_l) < N;
    const __half* brp = Bt + (size_t)(bok ? (colC0 + brow_l) : 0) * K;
    const uint32_t b_dst = smem0 + AS_BYTES + (uint32_t)(brow_l * SAK + ako) * 2;

    const int a_row_lm = wm + (lane & 15);
    const int a_kh_lm  = (lane >> 4) * 8;
    const int b_row_lm = wn + (lane & 7) + (lane >> 4) * 8;
    const int b_kh_lm  = ((lane >> 3) & 1) * 8;

    float4 acc[4][4];
#pragma unroll
    for (int i = 0; i < 4; i++)
#pragma unroll
        for (int j = 0; j < 4; j++) acc[i][j] = make_float4(0.f, 0.f, 0.f, 0.f);

    auto loadTile = [&](int s, int k0) {
        const uint32_t soff = (uint32_t)s * STAGE_BYTES;
        const __half* ap;
        if (!(flags & F_CAT)) {
            ap = A + (size_t)(aok ? arow : 0) * K + k0 + ako;
        } else {
            const int k = k0 + ako;
            if (k < 512)       ap = Hg + (size_t)isg * 512 + k;
            else if (k < 1024) ap = Hg + (size_t)itg * 512 + (k - 512);
            else               ap = Mg + (size_t)(aok ? arow : 0) * 512 + (k - 1024);
        }
#pragma unroll
        for (int ch = 0; ch < 2; ch++) {
            const bool ok = aok && (k0 + ako + ch * 8) < K;
            cp16(a_dst + soff + 16u * ch, ok ? (const void*)(ap + 8 * ch) : (const void*)A,
                 ok ? 16 : 0);
        }
        const __half* bp = brp + k0 + ako;
#pragma unroll
        for (int ch = 0; ch < 2; ch++) {
            const bool ok = bok && (k0 + ako + ch * 8) < K;
            cp16(b_dst + soff + 16u * ch, ok ? (const void*)(bp + 8 * ch) : (const void*)Bt,
                 ok ? 16 : 0);
        }
    };

    auto computeTile = [&](int s) {
        const uint32_t abase = smem0 + (uint32_t)s * STAGE_BYTES;
        const uint32_t bbase = abase + AS_BYTES;
#pragma unroll
        for (int g = 0; g < 2; g++) {
            uint32_t af[4][4];
            uint32_t bf[4][2];
#pragma unroll
            for (int mt = 0; mt < 4; mt++)
                ldsm_x4(af[mt][0], af[mt][1], af[mt][2], af[mt][3],
                        abase + (uint32_t)((a_row_lm + mt * 16) * SAK + g * 16 + a_kh_lm) * 2);
#pragma unroll
            for (int p = 0; p < 2; p++)
                ldsm_x4(bf[2 * p][0], bf[2 * p][1], bf[2 * p + 1][0], bf[2 * p + 1][1],
                        bbase + (uint32_t)((b_row_lm + p * 16) * SAK + g * 16 + b_kh_lm) * 2);
#pragma unroll
            for (int mt = 0; mt < 4; mt++)
#pragma unroll
                for (int nt = 0; nt < 4; nt++)
                    mma_f16(acc[mt][nt], af[mt], bf[nt]);
        }
    };

    const int nK = (K + 31) >> 5;
    const int pre = nK < (NSTAGE - 1) ? nK : (NSTAGE - 1);
    for (int s = 0; s < pre; s++) { loadTile(s, s * 32); cp_commit(); }

    for (int i = 0; i < nK; ++i) {
        const int rem = nK - 1 - i;
        if (rem >= 2)      cp_wait<2>();
        else if (rem == 1) cp_wait<1>();
        else               cp_wait<0>();
        __syncthreads();
        if (i + NSTAGE - 1 < nK) { loadTile((i + NSTAGE - 1) & 3, (i + NSTAGE - 1) * 32); cp_commit(); }
        computeTile(i & 3);
    }

    // ---- optional rbf-multiplier epilogue tiles (K=16 MMA) ----
    const bool use_rbf = (flags & (F_RBFMUL | F_SCATH)) != 0;
    uint32_t bfr[4][2];
    if (use_rbf) {
        __syncthreads();   // all warps done reading stage smem
        {
            const int r = t & 127;
            const int off = (t >> 7) * 8;       // 0 or 8 halves
            const int gr = rowC0 + r;
            uint4 av = make_uint4(0, 0, 0, 0);
            if (gr < M) av = *(const uint4*)(Rbf + (size_t)gr * 16 + off);
            *(uint4*)(dyn_smem + ((size_t)r * RBS + off) * 2) = av;
            const int gc = colC0 + r;
            uint4 bv = make_uint4(0, 0, 0, 0);
            if (gc < N) bv = *(const uint4*)(Wrb + (size_t)gc * 16 + off);
            *(uint4*)(dyn_smem + RB_B_OFF + ((size_t)r * RBS + off) * 2) = bv;
        }
        __syncthreads();
        const uint32_t bb = smem0 + RB_B_OFF;
#pragma unroll
        for (int p = 0; p < 2; p++)
            ldsm_x4(bfr[2 * p][0], bfr[2 * p][1], bfr[2 * p + 1][0], bfr[2 * p + 1][1],
                    bb + (uint32_t)((b_row_lm + p * 16) * RBS + b_kh_lm) * 2);
    }

    // epilogue
#pragma unroll
    for (int mt = 0; mt < 4; mt++) {
        float4 mul[4];
        if (use_rbf) {
            uint32_t afr[4];
            ldsm_x4(afr[0], afr[1], afr[2], afr[3],
                    smem0 + (uint32_t)((a_row_lm + mt * 16) * RBS + a_kh_lm) * 2);
#pragma unroll
            for (int nt = 0; nt < 4; nt++) {
                mul[nt] = make_float4(0.f, 0.f, 0.f, 0.f);
                mma_f16(mul[nt], afr, bfr[nt]);
            }
        } else {
#pragma unroll
            for (int nt = 0; nt < 4; nt++) mul[nt] = make_float4(1.f, 1.f, 1.f, 1.f);
        }
        const int r = rowC0 + wm + mt * 16 + (lane >> 2);
#pragma unroll
        for (int nt = 0; nt < 4; nt++) {
            const int cc = colC0 + wn + nt * 8 + (lane & 3) * 2;
            if (cc >= N) continue;
            const float4 v = acc[mt][nt];
            const float4 mv = mul[nt];
            if (r < M)
                epi2(C, Ct, Scath, (size_t)r * N + cc, v.x, v.y, mv.x, mv.y,
                     flags, Add1, c1, Add2, c2);
            if (r + 8 < M)
                epi2(C, Ct, Scath, (size_t)(r + 8) * N + cc, v.z, v.w, mv.z, mv.w,
                     flags, Add1, c1, Add2, c2);
        }
    }
}

// ---------------- fp32 -> fp16 conversion ----------------
__global__ void conv_half_kernel(const float* __restrict__ src, __half* __restrict__ dst, int n4) {
    const int i = blockIdx.x * blockDim.x + threadIdx.x;
    if (i >= n4) return;
    float4 v = ((const float4*)src)[i];
    __half2* d = (__half2*)dst + 2 * i;
    d[0] = __floats2half2_rn(v.x, v.y);
    d[1] = __floats2half2_rn(v.z, v.w);
}

// ---------------- batched 512x512 transpose ----------------
struct TPtrs { const float* src[16]; __half* dst[16]; };

__global__ void transpose512_batch_kernel(TPtrs p) {
    __shared__ float tile[32][33];
    const float* src = p.src[blockIdx.z];
    __half* dst = p.dst[blockIdx.z];
    const int kb = blockIdx.y * 32, nb = blockIdx.x * 32;
    const int tx = threadIdx.x, ty = threadIdx.y;
#pragma unroll
    for (int dy = 0; dy < 32; dy += 8)
        tile[ty + dy][tx] = src[(size_t)(kb + ty + dy) * 512 + nb + tx];
    __syncthreads();
#pragma unroll
    for (int dy = 0; dy < 32; dy += 8)
        dst[(size_t)(nb + ty + dy) * 512 + kb + tx] = __float2half_rn(tile[tx][ty + dy]);
}

__global__ void transpose_half_kernel(const float* __restrict__ src, __half* __restrict__ dst,
                                      int K, int N) {
    __shared__ float tile[32][33];
    const int kb = blockIdx.y * 32, nb = blockIdx.x * 32;
    const int tx = threadIdx.x, ty = threadIdx.y;
#pragma unroll
    for (int dy = 0; dy < 32; dy += 8) {
        const int k = kb + ty + dy, n = nb + tx;
        if (k < K && n < N) tile[ty + dy][tx] = src[(size_t)k * N + n];
    }
    __syncthreads();
#pragma unroll
    for (int dy = 0; dy < 32; dy += 8) {
        const int n = nb + ty + dy, k = kb + tx;
        if (n < N && k < K) dst[(size_t)n * K + k] = __float2half_rn(tile[tx][ty + dy]);
    }
}

// ---------------- triplet tmp2 ----------------
__global__ void triplet_tmp2_kernel(const __half* __restrict__ down,
                                    const int* __restrict__ id3_ba,
                                    const float* __restrict__ sph,
                                    const float* __restrict__ rbfw1,
                                    __half* __restrict__ t2)
{
    __shared__ int   sIdx[256];
    __shared__ float sS[16 * 112];
    __shared__ float sR[16 * 112];

    const int tid = threadIdx.x;
    const int e0 = blockIdx.x * 16;

    sIdx[tid] = id3_ba[(size_t)e0 * 16 + tid];
    for (int r = tid; r < 16 * 112; r += 256) {
        sS[r] = sph  [(size_t)e0 * 112 + r];
        sR[r] = rbfw1[(size_t)e0 * 112 + r];
    }
    __syncthreads();

    const int team = tid >> 4;
    const int j = tid & 15;
    const int edge = e0 + team;

    float4 G[16];
#pragma unroll
    for (int k = 0; k < 16; k++) {
        const int row = sIdx[team * 16 + k];
        const __half2* dp = (const __half2*)(down + (size_t)row * 64 + j * 4);
        float2 lo = __half22float2(dp[0]);
        float2 hi = __half22float2(dp[1]);
        G[k] = make_float4(lo.x, lo.y, hi.x, hi.y);
    }

    float4 t1[7];
#pragma unroll
    for (int s = 0; s < 7; s++) {
        float4 a = make_float4(0.f, 0.f, 0.f, 0.f);
#pragma unroll
        for (int k = 0; k < 16; k++) {
            const float f = sS[team * 112 + s * 16 + k];
            a.x = fmaf(f, G[k].x, a.x); a.y = fmaf(f, G[k].y, a.y);
            a.z = fmaf(f, G[k].z, a.z); a.w = fmaf(f, G[k].w, a.w);
        }
        t1[s] = a;
    }

#pragma unroll
    for (int i = 0; i < 16; i++) {
        float4 a = make_float4(0.f, 0.f, 0.f, 0.f);
#pragma unroll
        for (int s = 0; s < 7; s++) {
            const float f = sR[team * 112 + i * 7 + s];
            a.x = fmaf(f, t1[s].x, a.x); a.y = fmaf(f, t1[s].y, a.y);
            a.z = fmaf(f, t1[s].z, a.z); a.w = fmaf(f, t1[s].w, a.w);
        }
        __half2* out = (__half2*)(t2 + (size_t)edge * 1024 + i * 64 + j * 4);
        out[0] = __floats2half2_rn(a.x, a.y);
        out[1] = __floats2half2_rn(a.z, a.w);
    }
}

// W_bil[e,i,o] -> WBPh[o][i*64+e]
__global__ void permute_wbil_kernel(const float* __restrict__ wb, __half* __restrict__ out) {
    const int idx = blockIdx.x * blockDim.x + threadIdx.x;
    const int o = idx & 63;
    const int i = (idx >> 6) & 15;
    const int e = idx >> 10;
    out[(size_t)o * 1024 + i * 64 + e] = __float2half_rn(wb[((size_t)(e * 16 + i)) * 64 + o]);
}

// x = (xca_skip + (up2[:,0:512] + up2[id_swap,512:1024])*c)*c
__global__ void combine_x_kernel(float* xca, __half* xcah, const float* __restrict__ up2,
                                 const int* __restrict__ id_swap) {
    const int idx = blockIdx.x * blockDim.x + threadIdx.x;
    const int e = idx >> 7;
    const int c = idx & 127;
    const int es = id_swap[e];
    float4 a = ((const float4*)up2)[(size_t)e * 256 + c];
    float4 b = ((const float4*)up2)[(size_t)es * 256 + 128 + c];
    float4 x = ((float4*)xca)[idx];
    x.x = (x.x + (a.x + b.x) * INV_SQRT2) * INV_SQRT2;
    x.y = (x.y + (a.y + b.y) * INV_SQRT2) * INV_SQRT2;
    x.z = (x.z + (a.z + b.z) * INV_SQRT2) * INV_SQRT2;
    x.w = (x.w + (a.w + b.w) * INV_SQRT2) * INV_SQRT2;
    ((float4*)xca)[idx] = x;
    __half2* xh = (__half2*)xcah + 2 * idx;
    xh[0] = __floats2half2_rn(x.x, x.y);
    xh[1] = __floats2half2_rn(x.z, x.w);
}

// segment-sum: out[idx_t[e]] += scath[e]  (scath = m*r2 precomputed in GEMM epilogue)
__global__ void scatter_atoms_kernel(const __half* __restrict__ scath,
                                     const int* __restrict__ idx_t, float* out) {
    const int idx = blockIdx.x * blockDim.x + threadIdx.x;
    const int e = idx >> 7;
    const int c = idx & 127;
    const int t = idx_t[e];
    const __half2* bp = (const __half2*)scath + 2 * idx;
    float2 b0 = __half22float2(bp[0]);
    float2 b1 = __half22float2(bp[1]);
    float* dst = out + (size_t)t * 512 + c * 4;
    atomicAdd(dst + 0, b0.x);
    atomicAdd(dst + 1, b0.y);
    atomicAdd(dst + 2, b1.x);
    atomicAdd(dst + 3, b1.y);
}

// ---------------- host orchestration ----------------
static void run_gemm(const __half* A, const __half* Bt, float* C, int M, int N, int K, int flags,
                     __half* Ct = nullptr,
                     const float* Ad1 = nullptr, float c1 = 1.f,
                     const float* Ad2 = nullptr, float c2 = 1.f,
                     const __half* Hg = nullptr, const int* isx = nullptr,
                     const int* itx = nullptr, const __half* Mg = nullptr,
                     const __half* Rbf = nullptr, const __half* Wrb = nullptr,
                     __half* Scath = nullptr)
{
    static bool attr_set = false;
    if (!attr_set) {
        cudaFuncSetAttribute(mma_gemm_kernel, cudaFuncAttributeMaxDynamicSharedMemorySize, SMEM_DYN);
        attr_set = true;
    }
    dim3 grid((N + 127) / 128, (M + 127) / 128);
    mma_gemm_kernel<<<grid, 256, SMEM_DYN>>>(A, Bt, C, Ct, M, N, K, flags,
                                             Ad1, c1, Ad2, c2, Hg, isx, itx, Mg,
                                             Rbf, Wrb, Scath);
}
static void run_conv(const float* src, __half* dst, size_t n) {
    const int n4 = (int)(n / 4);
    conv_half_kernel<<<(n4 + 255) / 256, 256>>>(src, dst, n4);
}
static void run_transpose(const float* src, __half* dst, int K, int N) {
    dim3 grid((N + 31) / 32, (K + 31) / 32);
    transpose_half_kernel<<<grid, dim3(32, 8)>>>(src, dst, K, N);
}

extern "C" void kernel_launch(void* const* d_in, const int* in_sizes, int n_in,
                              void* d_out, int out_size)
{
    const float* h_in    = (const float*)d_in[0];
    const float* m_in    = (const float*)d_in[1];
    const float* rbf3    = (const float*)d_in[2];
    const float* rbf_w1  = (const float*)d_in[3];
    const float* sph     = (const float*)d_in[4];
    const float* rbf_h   = (const float*)d_in[5];
    const int*   id3_ba  = (const int*)d_in[6];
    const int*   id_swap = (const int*)d_in[9];
    const int*   idx_s   = (const int*)d_in[10];
    const int*   idx_t   = (const int*)d_in[11];
    const float* W_dense_ca = (const float*)d_in[12];
    const float* W_ba    = (const float*)d_in[13];
    const float* W_rbf3  = (const float*)d_in[14];
    const float* W_down  = (const float*)d_in[15];
    const float* W_bil   = (const float*)d_in[16];
    const float* W_up_ca = (const float*)d_in[17];
    const float* W_up_ac = (const float*)d_in[18];
    const float* W_bs    = (const float*)d_in[19];
    const float* W_as    = (const float*)d_in[20];
    const float* W_au_rbf= (const float*)d_in[21];
    const float* W_au_d1 = (const float*)d_in[22];
    const float* W_au_res= (const float*)d_in[23];
    const float* W_cat   = (const float*)d_in[24];
    const float* W_res_m = (const float*)d_in[25];

    float* pool = nullptr;
    cudaGetSymbolAddress((void**)&pool, g_pool);
    float*  XCA  = pool + OFF_XCA;
    float*  TMP  = pool + OFF_TMP;
    float*  UP2  = pool + OFF_UP;
    float*  Mb   = pool + OFF_MB;
    float*  A1   = pool + OFF_A1;
    float*  A2   = pool + OFF_A2;
    __half* Mh   = (__half*)(pool + OFF_MH);
    __half* TMPh = (__half*)(pool + OFF_TMPH);
    __half* XCAh = (__half*)(pool + OFF_XCAH);
    __half* Mbh  = (__half*)(pool + OFF_MBH);
    __half* DWNh = (__half*)(pool + OFF_DWNH);
    __half* XBh  = (__half*)(pool + OFF_XBH);
    __half* T2h  = (__half*)(pool + OFF_T2H);
    __half* R3h  = (__half*)(pool + OFF_R3H);
    __half* RHh  = (__half*)(pool + OFF_RHH);
    __half* A1h  = (__half*)(pool + OFF_A1H);
    __half* A2h  = (__half*)(pool + OFF_A2H);
    __half* A3h  = (__half*)(pool + OFF_A3H);
    __half* OHh  = (__half*)(pool + OFF_OHH);
    __half* WH   = (__half*)(pool + OFF_WTSH);

    const size_t W2 = (size_t)DDg * DDg;
    __half* Wh_dense_ca = WH;            size_t woff = W2;
    __half* Wh_ba       = WH + woff;     woff += W2;
    __half* Wh_rbf3     = WH + woff;     woff += (size_t)DDg * 16;
    __half* Wh_down     = WH + woff;     woff += (size_t)DTg * DDg;
    __half* Wh_up_ca    = WH + woff;     woff += (size_t)DDg * DTg;
    __half* Wh_up_ac    = WH + woff;     woff += (size_t)DDg * DTg;
    __half* Wh_bs       = WH + woff;     woff += 2 * W2;
    __half* Wh_as       = WH + woff;     woff += 4 * W2;
    __half* Wh_au_rbf   = WH + woff;     woff += (size_t)DDg * 16;
    __half* Wh_au_d1    = WH + woff;     woff += W2;
    __half* Wh_au_res   = WH + woff;     woff += 6 * W2;
    __half* Wh_cat      = WH + woff;     woff += 3 * W2;
    __half* Wh_res_m    = WH + woff;     woff += 2 * W2;
    __half* WBPh        = WH + woff;     woff += (size_t)DTg * 1024;

    float* OUT_H = (float*)d_out;
    float* OUT_M = (float*)d_out + NA512;

    const float C = INV_SQRT2;

    // ---- pre-conversions ----
    run_conv(m_in, Mh, NE512);
    run_conv(rbf3, R3h, NE16);
    run_conv(rbf_h, RHh, NE16);
    {
        TPtrs tp{};
        int n = 0;
        tp.src[n] = W_dense_ca; tp.dst[n] = Wh_dense_ca; n++;
        tp.src[n] = W_ba;       tp.dst[n] = Wh_ba;       n++;
        tp.src[n] = W_au_d1;    tp.dst[n] = Wh_au_d1;    n++;
        for (int i = 0; i < 2; i++) { tp.src[n] = W_bs + i * W2;     tp.dst[n] = Wh_bs + i * W2;     n++; }
        for (int i = 0; i < 4; i++) { tp.src[n] = W_as + i * W2;     tp.dst[n] = Wh_as + i * W2;     n++; }
        for (int i = 0; i < 6; i++) { tp.src[n] = W_au_res + i * W2; tp.dst[n] = Wh_au_res + i * W2; n++; }
        transpose512_batch_kernel<<<dim3(16, 16, n), dim3(32, 8)>>>(tp);
    }
    {
        TPtrs tp{};
        tp.src[0] = W_res_m;      tp.dst[0] = Wh_res_m;
        tp.src[1] = W_res_m + W2; tp.dst[1] = Wh_res_m + W2;
        transpose512_batch_kernel<<<dim3(16, 16, 2), dim3(32, 8)>>>(tp);
    }
    run_transpose(W_rbf3, Wh_rbf3, 16, DDg);       // [512][16]
    run_transpose(W_down, Wh_down, DDg, DTg);
    run_transpose(W_up_ca, Wh_up_ca, DTg, DDg);
    run_transpose(W_up_ac, Wh_up_ac, DTg, DDg);
    run_transpose(W_au_rbf, Wh_au_rbf, 16, DDg);   // [512][16]
    run_transpose(W_cat, Wh_cat, 3 * DDg, DDg);
    permute_wbil_kernel<<<(NCBF * DTg * DTg) / 256, 256>>>(W_bil, WBPh);

    // ---- pipeline ----
    // TMPh = half(act(m @ W_ba) * (rbf3 @ W_rbf3))   [rbf mul fused via K=16 MMA epilogue]
    run_gemm(Mh, Wh_ba, nullptr, NEg, DDg, DDg, F_ACT | F_RBFMUL | F_HALF | F_NOF32,
             TMPh, nullptr, 1.f, nullptr, 1.f, nullptr, nullptr, nullptr, nullptr,
             R3h, Wh_rbf3, nullptr);
    run_gemm(TMPh, Wh_down, nullptr, NEg, DTg, DDg, F_ACT | F_HALF | F_NOF32, DWNh);
    run_gemm(Mh, Wh_dense_ca, XCA, NEg, DDg, DDg, F_ACT);

    triplet_tmp2_kernel<<<NEg / 16, 256>>>(DWNh, id3_ba, sph, rbf_w1, T2h);
    run_gemm(T2h, WBPh, nullptr, NEg, DTg, NCBF * DTg, F_HALF | F_NOF32, XBh);

    // merged up projection (N=1024)
    run_gemm(XBh, Wh_up_ca, UP2, NEg, 1024, DTg, F_ACT);
    combine_x_kernel<<<(NEg * 128) / 256, 256>>>(XCA, XCAh, UP2, id_swap);

    run_gemm(XCAh, Wh_bs, nullptr, NEg, DDg, DDg, F_ACT | F_HALF | F_NOF32, TMPh);
    run_gemm(TMPh, Wh_bs + W2, Mb, NEg, DDg, DDg, F_ACT | F_ADD1 | F_ADD2 | F_HALF,
             Mbh, XCA, C, m_in, C);

    run_gemm(Mbh, Wh_as + 0 * W2, nullptr, NEg, DDg, DDg, F_ACT | F_HALF | F_NOF32, TMPh);
    run_gemm(TMPh, Wh_as + 1 * W2, Mb, NEg, DDg, DDg, F_ACT | F_ADD1 | F_HALF,
             Mbh, Mb, C);
    run_gemm(Mbh, Wh_as + 2 * W2, nullptr, NEg, DDg, DDg, F_ACT | F_HALF | F_NOF32, TMPh);
    // last as-residual: also emit SCATh = half(m_final * (rbf_h @ W_au_rbf)) into XCAh
    run_gemm(TMPh, Wh_as + 3 * W2, Mb, NEg, DDg, DDg, F_ACT | F_ADD1 | F_HALF | F_SCATH,
             Mbh, Mb, C, nullptr, 1.f, nullptr, nullptr, nullptr, nullptr,
             RHh, Wh_au_rbf, XCAh);

    // AtomUpdate
    cudaMemsetAsync(A1, 0, NA512 * sizeof(float));
    scatter_atoms_kernel<<<(NEg * 128) / 256, 256>>>(XCAh, idx_t, A1);
    run_conv(A1, A1h, NA512);
    run_gemm(A1h, Wh_au_d1, A2, NAg, DDg, DDg, F_ACT | F_HALF, A2h);
    run_gemm(A2h, Wh_au_res + 0 * W2, nullptr, NAg, DDg, DDg, F_ACT | F_HALF | F_NOF32, A3h);
    run_gemm(A3h, Wh_au_res + 1 * W2, A2, NAg, DDg, DDg, F_ACT | F_ADD1 | F_HALF,
             A2h, A2, C);
    run_gemm(A2h, Wh_au_res + 2 * W2, nullptr, NAg, DDg, DDg, F_ACT | F_HALF | F_NOF32, A3h);
    run_gemm(A3h, Wh_au_res + 3 * W2, A2, NAg, DDg, DDg, F_ACT | F_ADD1 | F_HALF,
             A2h, A2, C);
    run_gemm(A2h, Wh_au_res + 4 * W2, nullptr, NAg, DDg, DDg, F_ACT | F_HALF | F_NOF32, A3h);
    run_gemm(A3h, Wh_au_res + 5 * W2, OUT_H, NAg, DDg, DDg,
             F_ACT | F_ADD1 | F_ADD2 | F_HALF, OHh, A2, C, h_in, C);

    // EdgeEmbedding (fused gather concat GEMM) -> overwrites XCA / XCAh
    run_gemm(nullptr, Wh_cat, XCA, NEg, DDg, 3 * DDg, F_ACT | F_CAT | F_HALF,
             XCAh, nullptr, 1.f, nullptr, 1.f, OHh, idx_s, idx_t, Mbh);

    run_gemm(XCAh, Wh_res_m, nullptr, NEg, DDg, DDg, F_ACT | F_HALF | F_NOF32, TMPh);
    run_gemm(TMPh, Wh_res_m + W2, OUT_M, NEg, DDg, DDg, F_ACT | F_ADD1 | F_ADD2,
             nullptr, XCA, C, Mb, C);

    (void)in_sizes; (void)n_in; (void)out_size;
}

// round 12
// speedup vs baseline: 1.0475x; 1.0086x over previous
#include <cuda_runtime.h>
#include <cuda_fp16.h>
#include <cstdint>

// ---------------- problem constants ----------------
constexpr int NEg   = 100000;
constexpr int NAg   = 5000;
constexpr int DDg   = 512;
constexpr int DTg   = 64;
constexpr int NCBF  = 16;

constexpr float INV_SQRT2 = 0.70710678118654752f;
constexpr float ACT_SCALE = 1.0f / 0.6f;

// ---------------- scratch pool (float units) ----------------
constexpr size_t NE512  = (size_t)NEg * DDg;
constexpr size_t NE64   = (size_t)NEg * DTg;
constexpr size_t NE1024 = (size_t)NEg * 1024;
constexpr size_t NE16   = (size_t)NEg * 16;
constexpr size_t NA512  = (size_t)NAg * DDg;

constexpr size_t OFF_XCA  = 0;
constexpr size_t OFF_TMP  = OFF_XCA + NE512;
constexpr size_t OFF_UP   = OFF_TMP + NE512;         // UP2 spans UP+MB
constexpr size_t OFF_MB   = OFF_UP  + NE512;
constexpr size_t OFF_A1   = OFF_MB  + NE512;
constexpr size_t OFF_A2   = OFF_A1  + NA512;
constexpr size_t OFF_MH   = OFF_A2   + NA512;
constexpr size_t OFF_TMPH = OFF_MH   + NE512 / 2;
constexpr size_t OFF_XCAH = OFF_TMPH + NE512 / 2;
constexpr size_t OFF_MBH  = OFF_XCAH + NE512 / 2;
constexpr size_t OFF_DWNH = OFF_MBH  + NE512 / 2;
constexpr size_t OFF_XBH  = OFF_DWNH + NE64 / 2;
constexpr size_t OFF_T2H  = OFF_XBH  + NE64 / 2;
constexpr size_t OFF_R3H  = OFF_T2H  + NE1024 / 2;
constexpr size_t OFF_RHH  = OFF_R3H  + NE16 / 2;
constexpr size_t OFF_A1H  = OFF_RHH  + NE16 / 2;
constexpr size_t OFF_A2H  = OFF_A1H  + NA512 / 2;
constexpr size_t OFF_A3H  = OFF_A2H  + NA512 / 2;
constexpr size_t OFF_OHH  = OFF_A3H  + NA512 / 2;
constexpr size_t OFF_WTSH = OFF_OHH  + NA512 / 2;
constexpr size_t WTSH_FLOATS = 3u * 1024 * 1024;
constexpr size_t POOL_TOTAL = OFF_WTSH + WTSH_FLOATS;

__device__ __align__(256) float g_pool[POOL_TOTAL];

// ---------------- helpers ----------------
__device__ __forceinline__ float scaled_silu(float x) {
    return x * (1.0f / (1.0f + __expf(-x))) * ACT_SCALE;
}
__device__ __forceinline__ void mma_f16(float4& d, const uint32_t a[4], const uint32_t b[2]) {
    asm volatile(
        "mma.sync.aligned.m16n8k16.row.col.f32.f16.f16.f32 "
        "{%0,%1,%2,%3}, {%4,%5,%6,%7}, {%8,%9}, {%0,%1,%2,%3};"
        : "+f"(d.x), "+f"(d.y), "+f"(d.z), "+f"(d.w)
        : "r"(a[0]), "r"(a[1]), "r"(a[2]), "r"(a[3]), "r"(b[0]), "r"(b[1]));
}
__device__ __forceinline__ void ldsm_x4(uint32_t& r0, uint32_t& r1, uint32_t& r2, uint32_t& r3,
                                        uint32_t addr) {
    asm volatile("ldmatrix.sync.aligned.m8n8.x4.shared.b16 {%0,%1,%2,%3}, [%4];"
                 : "=r"(r0), "=r"(r1), "=r"(r2), "=r"(r3) : "r"(addr));
}
__device__ __forceinline__ void cp16(uint32_t smem_dst, const void* gsrc, int szbytes) {
    asm volatile("cp.async.cg.shared.global [%0], [%1], 16, %2;"
                 :: "r"(smem_dst), "l"(gsrc), "r"(szbytes));
}
__device__ __forceinline__ void cp_commit() { asm volatile("cp.async.commit_group;"); }
template <int N> __device__ __forceinline__ void cp_wait() {
    asm volatile("cp.async.wait_group %0;" :: "n"(N));
}

// ---------------- fp16 tensor-core GEMM ----------------
enum { F_ACT = 1, F_MUL = 2, F_ADD1 = 4, F_ADD2 = 8, F_CAT = 16, F_HALF = 32, F_NOF32 = 64,
       F_RBFMUL = 128, F_SCATH = 256 };

constexpr int SAK = 40;
constexpr int NSTAGE = 4;
constexpr int AS_BYTES = 128 * SAK * 2;
constexpr int STAGE_BYTES = 2 * AS_BYTES;
constexpr int SMEM_DYN = NSTAGE * STAGE_BYTES;        // 81920

constexpr int RBS = 24;
constexpr int RB_BYTES = 128 * RBS * 2;
constexpr int RB_B_OFF = RB_BYTES;

__device__ __forceinline__ void epi2(float* C, __half* Ct, __half* Sc, size_t idx,
                                     float vx, float vy, float mx, float my,
                                     int flags, const float* Add1, float c1,
                                     const float* Add2, float c2) {
    if (flags & F_ACT)    { vx = scaled_silu(vx);       vy = scaled_silu(vy); }
    if (flags & F_RBFMUL) { vx *= mx;                   vy *= my; }
    if (flags & F_ADD1)   { vx = (Add1[idx] + vx) * c1; vy = (Add1[idx + 1] + vy) * c1; }
    if (flags & F_ADD2)   { vx = (vx + Add2[idx]) * c2; vy = (vy + Add2[idx + 1]) * c2; }
    if (flags & F_SCATH)  *(__half2*)(Sc + idx) = __floats2half2_rn(vx * mx, vy * my);
    if (flags & F_HALF)   *(__half2*)(Ct + idx) = __floats2half2_rn(vx, vy);
    if (!(flags & F_NOF32)) { C[idx] = vx; C[idx + 1] = vy; }
}

// NARROW=false: 128x128 tile, warp 64x32 (MT=4). NARROW=true: 128x64 tile, warp 32x32 (MT=2).
template <bool NARROW>
__global__ __launch_bounds__(256, 2)
void mma_gemm_kernel(const __half* __restrict__ A, const __half* __restrict__ Bt,
                     float* __restrict__ C, __half* __restrict__ Ct,
                     int M, int N, int K, int flags,
                     const float* __restrict__ Add1, float c1,
                     const float* __restrict__ Add2, float c2,
                     const __half* __restrict__ Hg, const int* __restrict__ idxs,
                     const int* __restrict__ idxt, const __half* __restrict__ Mg,
                     const __half* __restrict__ Rbf, const __half* __restrict__ Wrb,
                     __half* __restrict__ Scath)
{
    extern __shared__ __align__(16) char dyn_smem[];

    constexpr int MT = NARROW ? 2 : 4;

    const int t = threadIdx.x;
    const int lane = t & 31;
    const int warp = t >> 5;
    const int wm = NARROW ? (warp >> 1) * 32 : (warp >> 2) * 64;
    const int wn = NARROW ? (warp & 1) * 32 : (warp & 3) * 32;
    const int rowC0 = blockIdx.y * 128;
    const int colC0 = blockIdx.x * 128;

    const uint32_t smem0 = (uint32_t)__cvta_generic_to_shared(dyn_smem);

    const int arow_l = t & 127;
    const int ako = (t >> 7) * 16;
    const int arow = rowC0 + arow_l;
    const bool aok = arow < M;
    int isg = 0, itg = 0;
    if ((flags & F_CAT) && aok) { isg = idxs[arow]; itg = idxt[arow]; }
    const uint32_t a_dst = smem0 + (uint32_t)(arow_l * SAK + ako) * 2;

    const int brow_l = t & 127;
    const bool bok = (colC0 + brow_l) < N;
    const __half* brp = Bt + (size_t)(bok ? (colC0 + brow_l) : 0) * K;
    const uint32_t b_dst = smem0 + AS_BYTES + (uint32_t)(brow_l * SAK + ako) * 2;

    const int a_row_lm = wm + (lane & 15);
    const int a_kh_lm  = (lane >> 4) * 8;
    const int b_row_lm = wn + (lane & 7) + (lane >> 4) * 8;
    const int b_kh_lm  = ((lane >> 3) & 1) * 8;

    float4 acc[MT][4];
#pragma unroll
    for (int i = 0; i < MT; i++)
#pragma unroll
        for (int j = 0; j < 4; j++) acc[i][j] = make_float4(0.f, 0.f, 0.f, 0.f);

    auto loadTile = [&](int s, int k0) {
        const uint32_t soff = (uint32_t)s * STAGE_BYTES;
        const __half* ap;
        if (!(flags & F_CAT)) {
            ap = A + (size_t)(aok ? arow : 0) * K + k0 + ako;
        } else {
            const int k = k0 + ako;
            if (k < 512)       ap = Hg + (size_t)isg * 512 + k;
            else if (k < 1024) ap = Hg + (size_t)itg * 512 + (k - 512);
            else               ap = Mg + (size_t)(aok ? arow : 0) * 512 + (k - 1024);
        }
#pragma unroll
        for (int ch = 0; ch < 2; ch++) {
            const bool ok = aok && (k0 + ako + ch * 8) < K;
            cp16(a_dst + soff + 16u * ch, ok ? (const void*)(ap + 8 * ch) : (const void*)A,
                 ok ? 16 : 0);
        }
        const __half* bp = brp + k0 + ako;
#pragma unroll
        for (int ch = 0; ch < 2; ch++) {
            const bool ok = bok && (k0 + ako + ch * 8) < K;
            cp16(b_dst + soff + 16u * ch, ok ? (const void*)(bp + 8 * ch) : (const void*)Bt,
                 ok ? 16 : 0);
        }
    };

    auto computeTile = [&](int s) {
        const uint32_t abase = smem0 + (uint32_t)s * STAGE_BYTES;
        const uint32_t bbase = abase + AS_BYTES;
#pragma unroll
        for (int g = 0; g < 2; g++) {
            uint32_t af[MT][4];
            uint32_t bf[4][2];
#pragma unroll
            for (int mt = 0; mt < MT; mt++)
                ldsm_x4(af[mt][0], af[mt][1], af[mt][2], af[mt][3],
                        abase + (uint32_t)((a_row_lm + mt * 16) * SAK + g * 16 + a_kh_lm) * 2);
#pragma unroll
            for (int p = 0; p < 2; p++)
                ldsm_x4(bf[2 * p][0], bf[2 * p][1], bf[2 * p + 1][0], bf[2 * p + 1][1],
                        bbase + (uint32_t)((b_row_lm + p * 16) * SAK + g * 16 + b_kh_lm) * 2);
#pragma unroll
            for (int mt = 0; mt < MT; mt++)
#pragma unroll
                for (int nt = 0; nt < 4; nt++)
                    mma_f16(acc[mt][nt], af[mt], bf[nt]);
        }
    };

    const int nK = (K + 31) >> 5;
    const int pre = nK < (NSTAGE - 1) ? nK : (NSTAGE - 1);
    for (int s = 0; s < pre; s++) { loadTile(s, s * 32); cp_commit(); }

    for (int i = 0; i < nK; ++i) {
        const int rem = nK - 1 - i;
        if (rem >= 2)      cp_wait<2>();
        else if (rem == 1) cp_wait<1>();
        else               cp_wait<0>();
        __syncthreads();
        if (i + NSTAGE - 1 < nK) { loadTile((i + NSTAGE - 1) & 3, (i + NSTAGE - 1) * 32); cp_commit(); }
        computeTile(i & 3);
    }

    // ---- optional rbf-multiplier epilogue tiles (K=16 MMA) ----
    const bool use_rbf = (flags & (F_RBFMUL | F_SCATH)) != 0;
    uint32_t bfr[4][2];
    if (use_rbf) {
        __syncthreads();
        {
            const int r = t & 127;
            const int off = (t >> 7) * 8;
            const int gr = rowC0 + r;
            uint4 av = make_uint4(0, 0, 0, 0);
            if (gr < M) av = *(const uint4*)(Rbf + (size_t)gr * 16 + off);
            *(uint4*)(dyn_smem + ((size_t)r * RBS + off) * 2) = av;
            const int gc = colC0 + r;
            uint4 bv = make_uint4(0, 0, 0, 0);
            if (gc < N) bv = *(const uint4*)(Wrb + (size_t)gc * 16 + off);
            *(uint4*)(dyn_smem + RB_B_OFF + ((size_t)r * RBS + off) * 2) = bv;
        }
        __syncthreads();
        const uint32_t bb = smem0 + RB_B_OFF;
#pragma unroll
        for (int p = 0; p < 2; p++)
            ldsm_x4(bfr[2 * p][0], bfr[2 * p][1], bfr[2 * p + 1][0], bfr[2 * p + 1][1],
                    bb + (uint32_t)((b_row_lm + p * 16) * RBS + b_kh_lm) * 2);
    }

    // epilogue
#pragma unroll
    for (int mt = 0; mt < MT; mt++) {
        float4 mul[4];
        if (use_rbf) {
            uint32_t afr[4];
            ldsm_x4(afr[0], afr[1], afr[2], afr[3],
                    smem0 + (uint32_t)((a_row_lm + mt * 16) * RBS + a_kh_lm) * 2);
#pragma unroll
            for (int nt = 0; nt < 4; nt++) {
                mul[nt] = make_float4(0.f, 0.f, 0.f, 0.f);
                mma_f16(mul[nt], afr, bfr[nt]);
            }
        } else {
#pragma unroll
            for (int nt = 0; nt < 4; nt++) mul[nt] = make_float4(1.f, 1.f, 1.f, 1.f);
        }
        const int r = rowC0 + wm + mt * 16 + (lane >> 2);
#pragma unroll
        for (int nt = 0; nt < 4; nt++) {
            const int cc = colC0 + wn + nt * 8 + (lane & 3) * 2;
            if (cc >= N) continue;
            const float4 v = acc[mt][nt];
            const float4 mv = mul[nt];
            if (r < M)
                epi2(C, Ct, Scath, (size_t)r * N + cc, v.x, v.y, mv.x, mv.y,
                     flags, Add1, c1, Add2, c2);
            if (r + 8 < M)
                epi2(C, Ct, Scath, (size_t)(r + 8) * N + cc, v.z, v.w, mv.z, mv.w,
                     flags, Add1, c1, Add2, c2);
        }
    }
}

// ---------------- fp32 -> fp16 conversion ----------------
__global__ void conv_half_kernel(const float* __restrict__ src, __half* __restrict__ dst, int n4) {
    const int i = blockIdx.x * blockDim.x + threadIdx.x;
    if (i >= n4) return;
    float4 v = ((const float4*)src)[i];
    __half2* d = (__half2*)dst + 2 * i;
    d[0] = __floats2half2_rn(v.x, v.y);
    d[1] = __floats2half2_rn(v.z, v.w);
}

// ---------------- batched 512x512 transpose ----------------
struct TPtrs { const float* src[16]; __half* dst[16]; };

__global__ void transpose512_batch_kernel(TPtrs p) {
    __shared__ float tile[32][33];
    const float* src = p.src[blockIdx.z];
    __half* dst = p.dst[blockIdx.z];
    const int kb = blockIdx.y * 32, nb = blockIdx.x * 32;
    const int tx = threadIdx.x, ty = threadIdx.y;
#pragma unroll
    for (int dy = 0; dy < 32; dy += 8)
        tile[ty + dy][tx] = src[(size_t)(kb + ty + dy) * 512 + nb + tx];
    __syncthreads();
#pragma unroll
    for (int dy = 0; dy < 32; dy += 8)
        dst[(size_t)(nb + ty + dy) * 512 + kb + tx] = __float2half_rn(tile[tx][ty + dy]);
}

__global__ void transpose_half_kernel(const float* __restrict__ src, __half* __restrict__ dst,
                                      int K, int N) {
    __shared__ float tile[32][33];
    const int kb = blockIdx.y * 32, nb = blockIdx.x * 32;
    const int tx = threadIdx.x, ty = threadIdx.y;
#pragma unroll
    for (int dy = 0; dy < 32; dy += 8) {
        const int k = kb + ty + dy, n = nb + tx;
        if (k < K && n < N) tile[ty + dy][tx] = src[(size_t)k * N + n];
    }
    __syncthreads();
#pragma unroll
    for (int dy = 0; dy < 32; dy += 8) {
        const int n = nb + ty + dy, k = kb + tx;
        if (n < N && k < K) dst[(size_t)n * K + k] = __float2half_rn(tile[tx][ty + dy]);
    }
}

// ---------------- triplet tmp2 ----------------
__global__ void triplet_tmp2_kernel(const __half* __restrict__ down,
                                    const int* __restrict__ id3_ba,
                                    const float* __restrict__ sph,
                                    const float* __restrict__ rbfw1,
                                    __half* __restrict__ t2)
{
    __shared__ int   sIdx[256];
    __shared__ float sS[16 * 112];
    __shared__ float sR[16 * 112];

    const int tid = threadIdx.x;
    const int e0 = blockIdx.x * 16;

    sIdx[tid] = id3_ba[(size_t)e0 * 16 + tid];
    for (int r = tid; r < 16 * 112; r += 256) {
        sS[r] = sph  [(size_t)e0 * 112 + r];
        sR[r] = rbfw1[(size_t)e0 * 112 + r];
    }
    __syncthreads();

    const int team = tid >> 4;
    const int j = tid & 15;
    const int edge = e0 + team;

    float4 G[16];
#pragma unroll
    for (int k = 0; k < 16; k++) {
        const int row = sIdx[team * 16 + k];
        const __half2* dp = (const __half2*)(down + (size_t)row * 64 + j * 4);
        float2 lo = __half22float2(dp[0]);
        float2 hi = __half22float2(dp[1]);
        G[k] = make_float4(lo.x, lo.y, hi.x, hi.y);
    }

    float4 t1[7];
#pragma unroll
    for (int s = 0; s < 7; s++) {
        float4 a = make_float4(0.f, 0.f, 0.f, 0.f);
#pragma unroll
        for (int k = 0; k < 16; k++) {
            const float f = sS[team * 112 + s * 16 + k];
            a.x = fmaf(f, G[k].x, a.x); a.y = fmaf(f, G[k].y, a.y);
            a.z = fmaf(f, G[k].z, a.z); a.w = fmaf(f, G[k].w, a.w);
        }
        t1[s] = a;
    }

#pragma unroll
    for (int i = 0; i < 16; i++) {
        float4 a = make_float4(0.f, 0.f, 0.f, 0.f);
#pragma unroll
        for (int s = 0; s < 7; s++) {
            const float f = sR[team * 112 + i * 7 + s];
            a.x = fmaf(f, t1[s].x, a.x); a.y = fmaf(f, t1[s].y, a.y);
            a.z = fmaf(f, t1[s].z, a.z); a.w = fmaf(f, t1[s].w, a.w);
        }
        __half2* out = (__half2*)(t2 + (size_t)edge * 1024 + i * 64 + j * 4);
        out[0] = __floats2half2_rn(a.x, a.y);
        out[1] = __floats2half2_rn(a.z, a.w);
    }
}

// W_bil[e,i,o] -> WBPh[o][i*64+e]
__global__ void permute_wbil_kernel(const float* __restrict__ wb, __half* __restrict__ out) {
    const int idx = blockIdx.x * blockDim.x + threadIdx.x;
    const int o = idx & 63;
    const int i = (idx >> 6) & 15;
    const int e = idx >> 10;
    out[(size_t)o * 1024 + i * 64 + e] = __float2half_rn(wb[((size_t)(e * 16 + i)) * 64 + o]);
}

// x = (xca_skip + (up2[:,0:512] + up2[id_swap,512:1024])*c)*c
__global__ void combine_x_kernel(float* xca, __half* xcah, const float* __restrict__ up2,
                                 const int* __restrict__ id_swap) {
    const int idx = blockIdx.x * blockDim.x + threadIdx.x;
    const int e = idx >> 7;
    const int c = idx & 127;
    const int es = id_swap[e];
    float4 a = ((const float4*)up2)[(size_t)e * 256 + c];
    float4 b = ((const float4*)up2)[(size_t)es * 256 + 128 + c];
    float4 x = ((float4*)xca)[idx];
    x.x = (x.x + (a.x + b.x) * INV_SQRT2) * INV_SQRT2;
    x.y = (x.y + (a.y + b.y) * INV_SQRT2) * INV_SQRT2;
    x.z = (x.z + (a.z + b.z) * INV_SQRT2) * INV_SQRT2;
    x.w = (x.w + (a.w + b.w) * INV_SQRT2) * INV_SQRT2;
    ((float4*)xca)[idx] = x;
    __half2* xh = (__half2*)xcah + 2 * idx;
    xh[0] = __floats2half2_rn(x.x, x.y);
    xh[1] = __floats2half2_rn(x.z, x.w);
}

// segment-sum: out[idx_t[e]] += scath[e]
__global__ void scatter_atoms_kernel(const __half* __restrict__ scath,
                                     const int* __restrict__ idx_t, float* out) {
    const int idx = blockIdx.x * blockDim.x + threadIdx.x;
    const int e = idx >> 7;
    const int c = idx & 127;
    const int t = idx_t[e];
    const __half2* bp = (const __half2*)scath + 2 * idx;
    float2 b0 = __half22float2(bp[0]);
    float2 b1 = __half22float2(bp[1]);
    float* dst = out + (size_t)t * 512 + c * 4;
    atomicAdd(dst + 0, b0.x);
    atomicAdd(dst + 1, b0.y);
    atomicAdd(dst + 2, b1.x);
    atomicAdd(dst + 3, b1.y);
}

// ---------------- host orchestration ----------------
static void run_gemm_impl(bool narrow,
                          const __half* A, const __half* Bt, float* C, int M, int N, int K,
                          int flags, __half* Ct,
                          const float* Ad1, float c1, const float* Ad2, float c2,
                          const __half* Hg, const int* isx, const int* itx, const __half* Mg,
                          const __half* Rbf, const __half* Wrb, __half* Scath)
{
    static bool attr_set = false;
    if (!attr_set) {
        cudaFuncSetAttribute(mma_gemm_kernel<false>, cudaFuncAttributeMaxDynamicSharedMemorySize, SMEM_DYN);
        cudaFuncSetAttribute(mma_gemm_kernel<true>,  cudaFuncAttributeMaxDynamicSharedMemorySize, SMEM_DYN);
        attr_set = true;
    }
    if (narrow) {
        dim3 grid((N + 63) / 64, (M + 127) / 128);
        mma_gemm_kernel<true><<<grid, 256, SMEM_DYN>>>(A, Bt, C, Ct, M, N, K, flags,
                                                       Ad1, c1, Ad2, c2, Hg, isx, itx, Mg,
                                                       Rbf, Wrb, Scath);
    } else {
        dim3 grid((N + 127) / 128, (M + 127) / 128);
        mma_gemm_kernel<false><<<grid, 256, SMEM_DYN>>>(A, Bt, C, Ct, M, N, K, flags,
                                                        Ad1, c1, Ad2, c2, Hg, isx, itx, Mg,
                                                        Rbf, Wrb, Scath);
    }
}
static void run_gemm(const __half* A, const __half* Bt, float* C, int M, int N, int K, int flags,
                     __half* Ct = nullptr,
                     const float* Ad1 = nullptr, float c1 = 1.f,
                     const float* Ad2 = nullptr, float c2 = 1.f,
                     const __half* Hg = nullptr, const int* isx = nullptr,
                     const int* itx = nullptr, const __half* Mg = nullptr,
                     const __half* Rbf = nullptr, const __half* Wrb = nullptr,
                     __half* Scath = nullptr)
{
    run_gemm_impl(N <= 64, A, Bt, C, M, N, K, flags, Ct, Ad1, c1, Ad2, c2,
                  Hg, isx, itx, Mg, Rbf, Wrb, Scath);
}
static void run_conv(const float* src, __half* dst, size_t n) {
    const int n4 = (int)(n / 4);
    conv_half_kernel<<<(n4 + 255) / 256, 256>>>(src, dst, n4);
}
static void run_transpose(const float* src, __half* dst, int K, int N) {
    dim3 grid((N + 31) / 32, (K + 31) / 32);
    transpose_half_kernel<<<grid, dim3(32, 8)>>>(src, dst, K, N);
}

extern "C" void kernel_launch(void* const* d_in, const int* in_sizes, int n_in,
                              void* d_out, int out_size)
{
    const float* h_in    = (const float*)d_in[0];
    const float* m_in    = (const float*)d_in[1];
    const float* rbf3    = (const float*)d_in[2];
    const float* rbf_w1  = (const float*)d_in[3];
    const float* sph     = (const float*)d_in[4];
    const float* rbf_h   = (const float*)d_in[5];
    const int*   id3_ba  = (const int*)d_in[6];
    const int*   id_swap = (const int*)d_in[9];
    const int*   idx_s   = (const int*)d_in[10];
    const int*   idx_t   = (const int*)d_in[11];
    const float* W_dense_ca = (const float*)d_in[12];
    const float* W_ba    = (const float*)d_in[13];
    const float* W_rbf3  = (const float*)d_in[14];
    const float* W_down  = (const float*)d_in[15];
    const float* W_bil   = (const float*)d_in[16];
    const float* W_up_ca = (const float*)d_in[17];
    const float* W_up_ac = (const float*)d_in[18];
    const float* W_bs    = (const float*)d_in[19];
    const float* W_as    = (const float*)d_in[20];
    const float* W_au_rbf= (const float*)d_in[21];
    const float* W_au_d1 = (const float*)d_in[22];
    const float* W_au_res= (const float*)d_in[23];
    const float* W_cat   = (const float*)d_in[24];
    const float* W_res_m = (const float*)d_in[25];

    float* pool = nullptr;
    cudaGetSymbolAddress((void**)&pool, g_pool);
    float*  XCA  = pool + OFF_XCA;
    float*  TMP  = pool + OFF_TMP;
    float*  UP2  = pool + OFF_UP;
    float*  Mb   = pool + OFF_MB;
    float*  A1   = pool + OFF_A1;
    float*  A2   = pool + OFF_A2;
    __half* Mh   = (__half*)(pool + OFF_MH);
    __half* TMPh = (__half*)(pool + OFF_TMPH);
    __half* XCAh = (__half*)(pool + OFF_XCAH);
    __half* Mbh  = (__half*)(pool + OFF_MBH);
    __half* DWNh = (__half*)(pool + OFF_DWNH);
    __half* XBh  = (__half*)(pool + OFF_XBH);
    __half* T2h  = (__half*)(pool + OFF_T2H);
    __half* R3h  = (__half*)(pool + OFF_R3H);
    __half* RHh  = (__half*)(pool + OFF_RHH);
    __half* A1h  = (__half*)(pool + OFF_A1H);
    __half* A2h  = (__half*)(pool + OFF_A2H);
    __half* A3h  = (__half*)(pool + OFF_A3H);
    __half* OHh  = (__half*)(pool + OFF_OHH);
    __half* WH   = (__half*)(pool + OFF_WTSH);

    const size_t W2 = (size_t)DDg * DDg;
    __half* Wh_dense_ca = WH;            size_t woff = W2;
    __half* Wh_ba       = WH + woff;     woff += W2;
    __half* Wh_rbf3     = WH + woff;     woff += (size_t)DDg * 16;
    __half* Wh_down     = WH + woff;     woff += (size_t)DTg * DDg;
    __half* Wh_up_ca    = WH + woff;     woff += (size_t)DDg * DTg;
    __half* Wh_up_ac    = WH + woff;     woff += (size_t)DDg * DTg;
    __half* Wh_bs       = WH + woff;     woff += 2 * W2;
    __half* Wh_as       = WH + woff;     woff += 4 * W2;
    __half* Wh_au_rbf   = WH + woff;     woff += (size_t)DDg * 16;
    __half* Wh_au_d1    = WH + woff;     woff += W2;
    __half* Wh_au_res   = WH + woff;     woff += 6 * W2;
    __half* Wh_cat      = WH + woff;     woff += 3 * W2;
    __half* Wh_res_m    = WH + woff;     woff += 2 * W2;
    __half* WBPh        = WH + woff;     woff += (size_t)DTg * 1024;

    float* OUT_H = (float*)d_out;
    float* OUT_M = (float*)d_out + NA512;

    const float C = INV_SQRT2;

    // ---- pre-conversions ----
    run_conv(m_in, Mh, NE512);
    run_conv(rbf3, R3h, NE16);
    run_conv(rbf_h, RHh, NE16);
    {
        TPtrs tp{};
        int n = 0;
        tp.src[n] = W_dense_ca; tp.dst[n] = Wh_dense_ca; n++;
        tp.src[n] = W_ba;       tp.dst[n] = Wh_ba;       n++;
        tp.src[n] = W_au_d1;    tp.dst[n] = Wh_au_d1;    n++;
        for (int i = 0; i < 2; i++) { tp.src[n] = W_bs + i * W2;     tp.dst[n] = Wh_bs + i * W2;     n++; }
        for (int i = 0; i < 4; i++) { tp.src[n] = W_as + i * W2;     tp.dst[n] = Wh_as + i * W2;     n++; }
        for (int i = 0; i < 6; i++) { tp.src[n] = W_au_res + i * W2; tp.dst[n] = Wh_au_res + i * W2; n++; }
        transpose512_batch_kernel<<<dim3(16, 16, n), dim3(32, 8)>>>(tp);
    }
    {
        TPtrs tp{};
        tp.src[0] = W_res_m;      tp.dst[0] = Wh_res_m;
        tp.src[1] = W_res_m + W2; tp.dst[1] = Wh_res_m + W2;
        transpose512_batch_kernel<<<dim3(16, 16, 2), dim3(32, 8)>>>(tp);
    }
    run_transpose(W_rbf3, Wh_rbf3, 16, DDg);
    run_transpose(W_down, Wh_down, DDg, DTg);
    run_transpose(W_up_ca, Wh_up_ca, DTg, DDg);
    run_transpose(W_up_ac, Wh_up_ac, DTg, DDg);
    run_transpose(W_au_rbf, Wh_au_rbf, 16, DDg);
    run_transpose(W_cat, Wh_cat, 3 * DDg, DDg);
    permute_wbil_kernel<<<(NCBF * DTg * DTg) / 256, 256>>>(W_bil, WBPh);

    // ---- pipeline ----
    run_gemm(Mh, Wh_ba, nullptr, NEg, DDg, DDg, F_ACT | F_RBFMUL | F_HALF | F_NOF32,
             TMPh, nullptr, 1.f, nullptr, 1.f, nullptr, nullptr, nullptr, nullptr,
             R3h, Wh_rbf3, nullptr);
    run_gemm(TMPh, Wh_down, nullptr, NEg, DTg, DDg, F_ACT | F_HALF | F_NOF32, DWNh);
    run_gemm(Mh, Wh_dense_ca, XCA, NEg, DDg, DDg, F_ACT);

    triplet_tmp2_kernel<<<NEg / 16, 256>>>(DWNh, id3_ba, sph, rbf_w1, T2h);
    run_gemm(T2h, WBPh, nullptr, NEg, DTg, NCBF * DTg, F_HALF | F_NOF32, XBh);

    run_gemm(XBh, Wh_up_ca, UP2, NEg, 1024, DTg, F_ACT);
    combine_x_kernel<<<(NEg * 128) / 256, 256>>>(XCA, XCAh, UP2, id_swap);

    run_gemm(XCAh, Wh_bs, nullptr, NEg, DDg, DDg, F_ACT | F_HALF | F_NOF32, TMPh);
    run_gemm(TMPh, Wh_bs + W2, Mb, NEg, DDg, DDg, F_ACT | F_ADD1 | F_ADD2 | F_HALF,
             Mbh, XCA, C, m_in, C);

    run_gemm(Mbh, Wh_as + 0 * W2, nullptr, NEg, DDg, DDg, F_ACT | F_HALF | F_NOF32, TMPh);
    run_gemm(TMPh, Wh_as + 1 * W2, Mb, NEg, DDg, DDg, F_ACT | F_ADD1 | F_HALF,
             Mbh, Mb, C);
    run_gemm(Mbh, Wh_as + 2 * W2, nullptr, NEg, DDg, DDg, F_ACT | F_HALF | F_NOF32, TMPh);
    run_gemm(TMPh, Wh_as + 3 * W2, Mb, NEg, DDg, DDg, F_ACT | F_ADD1 | F_HALF | F_SCATH,
             Mbh, Mb, C, nullptr, 1.f, nullptr, nullptr, nullptr, nullptr,
             RHh, Wh_au_rbf, XCAh);

    cudaMemsetAsync(A1, 0, NA512 * sizeof(float));
    scatter_atoms_kernel<<<(NEg * 128) / 256, 256>>>(XCAh, idx_t, A1);
    run_conv(A1, A1h, NA512);
    run_gemm(A1h, Wh_au_d1, A2, NAg, DDg, DDg, F_ACT | F_HALF, A2h);
    run_gemm(A2h, Wh_au_res + 0 * W2, nullptr, NAg, DDg, DDg, F_ACT | F_HALF | F_NOF32, A3h);
    run_gemm(A3h, Wh_au_res + 1 * W2, A2, NAg, DDg, DDg, F_ACT | F_ADD1 | F_HALF,
             A2h, A2, C);
    run_gemm(A2h, Wh_au_res + 2 * W2, nullptr, NAg, DDg, DDg, F_ACT | F_HALF | F_NOF32, A3h);
    run_gemm(A3h, Wh_au_res + 3 * W2, A2, NAg, DDg, DDg, F_ACT | F_ADD1 | F_HALF,
             A2h, A2, C);
    run_gemm(A2h, Wh_au_res + 4 * W2, nullptr, NAg, DDg, DDg, F_ACT | F_HALF | F_NOF32, A3h);
    run_gemm(A3h, Wh_au_res + 5 * W2, OUT_H, NAg, DDg, DDg,
             F_ACT | F_ADD1 | F_ADD2 | F_HALF, OHh, A2, C, h_in, C);

    run_gemm(nullptr, Wh_cat, XCA, NEg, DDg, 3 * DDg, F_ACT | F_CAT | F_HALF,
             XCAh, nullptr, 1.f, nullptr, 1.f, OHh, idx_s, idx_t, Mbh);

    run_gemm(XCAh, Wh_res_m, nullptr, NEg, DDg, DDg, F_ACT | F_HALF | F_NOF32, TMPh);
    run_gemm(TMPh, Wh_res_m + W2, OUT_M, NEg, DDg, DDg, F_ACT | F_ADD1 | F_ADD2,
             nullptr, XCA, C, Mb, C);

    (void)in_sizes; (void)n_in; (void)out_size;
}

// round 14
// speedup vs baseline: 1.0480x; 1.0005x over previous
#include <cuda_runtime.h>
#include <cuda_fp16.h>
#include <cstdint>

// ---------------- problem constants ----------------
constexpr int NEg   = 100000;
constexpr int NAg   = 5000;
constexpr int DDg   = 512;
constexpr int DTg   = 64;
constexpr int NCBF  = 16;

constexpr float INV_SQRT2 = 0.70710678118654752f;
constexpr float ACT_SCALE = 1.0f / 0.6f;

// ---------------- scratch pool (float units) ----------------
constexpr size_t NE512  = (size_t)NEg * DDg;
constexpr size_t NE64   = (size_t)NEg * DTg;
constexpr size_t NE1024 = (size_t)NEg * 1024;
constexpr size_t NE16   = (size_t)NEg * 16;
constexpr size_t NA512  = (size_t)NAg * DDg;

constexpr size_t OFF_XCA  = 0;
constexpr size_t OFF_TMP  = OFF_XCA + NE512;
constexpr size_t OFF_UP   = OFF_TMP + NE512;
constexpr size_t OFF_MB   = OFF_UP  + NE512;
constexpr size_t OFF_A1   = OFF_MB  + NE512;
constexpr size_t OFF_A2   = OFF_A1  + NA512;
constexpr size_t OFF_MH   = OFF_A2   + NA512;
constexpr size_t OFF_TMPH = OFF_MH   + NE512 / 2;
constexpr size_t OFF_XCAH = OFF_TMPH + NE512 / 2;
constexpr size_t OFF_MBH  = OFF_XCAH + NE512 / 2;
constexpr size_t OFF_DWNH = OFF_MBH  + NE512 / 2;
constexpr size_t OFF_XBH  = OFF_DWNH + NE64 / 2;
constexpr size_t OFF_T2H  = OFF_XBH  + NE64 / 2;
constexpr size_t OFF_R3H  = OFF_T2H  + NE1024 / 2;
constexpr size_t OFF_RHH  = OFF_R3H  + NE16 / 2;
constexpr size_t OFF_A1H  = OFF_RHH  + NE16 / 2;
constexpr size_t OFF_A2H  = OFF_A1H  + NA512 / 2;
constexpr size_t OFF_A3H  = OFF_A2H  + NA512 / 2;
constexpr size_t OFF_OHH  = OFF_A3H  + NA512 / 2;
constexpr size_t OFF_WTSH = OFF_OHH  + NA512 / 2;
constexpr size_t WTSH_FLOATS = 3u * 1024 * 1024;
constexpr size_t POOL_TOTAL = OFF_WTSH + WTSH_FLOATS;

__device__ __align__(256) float g_pool[POOL_TOTAL];

// ---------------- helpers ----------------
__device__ __forceinline__ float scaled_silu(float x) {
    return x * (1.0f / (1.0f + __expf(-x))) * ACT_SCALE;
}
__device__ __forceinline__ void mma_f16(float4& d, const uint32_t a[4], const uint32_t b[2]) {
    asm volatile(
        "mma.sync.aligned.m16n8k16.row.col.f32.f16.f16.f32 "
        "{%0,%1,%2,%3}, {%4,%5,%6,%7}, {%8,%9}, {%0,%1,%2,%3};"
        : "+f"(d.x), "+f"(d.y), "+f"(d.z), "+f"(d.w)
        : "r"(a[0]), "r"(a[1]), "r"(a[2]), "r"(a[3]), "r"(b[0]), "r"(b[1]));
}
__device__ __forceinline__ void ldsm_x4(uint32_t& r0, uint32_t& r1, uint32_t& r2, uint32_t& r3,
                                        uint32_t addr) {
    asm volatile("ldmatrix.sync.aligned.m8n8.x4.shared.b16 {%0,%1,%2,%3}, [%4];"
                 : "=r"(r0), "=r"(r1), "=r"(r2), "=r"(r3) : "r"(addr));
}
__device__ __forceinline__ void cp16(uint32_t smem_dst, const void* gsrc, int szbytes) {
    asm volatile("cp.async.cg.shared.global [%0], [%1], 16, %2;"
                 :: "r"(smem_dst), "l"(gsrc), "r"(szbytes));
}
__device__ __forceinline__ void cp_commit() { asm volatile("cp.async.commit_group;"); }
template <int N> __device__ __forceinline__ void cp_wait() {
    asm volatile("cp.async.wait_group %0;" :: "n"(N));
}

// ---------------- fp16 tensor-core GEMM ----------------
enum { F_ACT = 1, F_MUL = 2, F_ADD1 = 4, F_ADD2 = 8, F_CAT = 16, F_HALF = 32, F_NOF32 = 64,
       F_RBFMUL = 128, F_SCATH = 256 };

constexpr int SAK = 40;
constexpr int NSTAGE = 4;
constexpr int AS_BYTES = 128 * SAK * 2;
constexpr int STAGE_BYTES = 2 * AS_BYTES;
constexpr int SMEM_DYN = NSTAGE * STAGE_BYTES;        // 81920

constexpr int RBS = 24;
constexpr int RB_BYTES = 128 * RBS * 2;
constexpr int RB_B_OFF = RB_BYTES;

__device__ __forceinline__ void epi2(float* C, __half* Ct, __half* Sc, size_t idx,
                                     float vx, float vy, float mx, float my,
                                     int flags, const float* Add1, float c1,
                                     const float* Add2, float c2) {
    if (flags & F_ACT)    { vx = scaled_silu(vx);       vy = scaled_silu(vy); }
    if (flags & F_RBFMUL) { vx *= mx;                   vy *= my; }
    if (flags & F_ADD1)   { vx = (Add1[idx] + vx) * c1; vy = (Add1[idx + 1] + vy) * c1; }
    if (flags & F_ADD2)   { vx = (vx + Add2[idx]) * c2; vy = (vy + Add2[idx + 1]) * c2; }
    if (flags & F_SCATH)  *(__half2*)(Sc + idx) = __floats2half2_rn(vx * mx, vy * my);
    if (flags & F_HALF)   *(__half2*)(Ct + idx) = __floats2half2_rn(vx, vy);
    if (!(flags & F_NOF32)) { C[idx] = vx; C[idx + 1] = vy; }
}

// NARROW=false: 128x128 tile, warp 64x32 (MT=4). NARROW=true: 128x64 tile, warp 32x32 (MT=2).
template <bool NARROW>
__global__ __launch_bounds__(256, 2)
void mma_gemm_kernel(const __half* __restrict__ A, const __half* __restrict__ Bt,
                     float* __restrict__ C, __half* __restrict__ Ct,
                     int M, int N, int K, int flags,
                     const float* __restrict__ Add1, float c1,
                     const float* __restrict__ Add2, float c2,
                     const __half* __restrict__ Hg, const int* __restrict__ idxs,
                     const int* __restrict__ idxt, const __half* __restrict__ Mg,
                     const __half* __restrict__ Rbf, const __half* __restrict__ Wrb,
                     __half* __restrict__ Scath)
{
    extern __shared__ __align__(16) char dyn_smem[];

    constexpr int MT = NARROW ? 2 : 4;

    const int t = threadIdx.x;
    const int lane = t & 31;
    const int warp = t >> 5;
    const int wm = NARROW ? (warp >> 1) * 32 : (warp >> 2) * 64;
    const int wn = NARROW ? (warp & 1) * 32 : (warp & 3) * 32;
    const int rowC0 = blockIdx.y * 128;
    const int colC0 = blockIdx.x * (NARROW ? 64 : 128);

    const uint32_t smem0 = (uint32_t)__cvta_generic_to_shared(dyn_smem);

    const int arow_l = t & 127;
    const int ako = (t >> 7) * 16;
    const int arow = rowC0 + arow_l;
    const bool aok = arow < M;
    int isg = 0, itg = 0;
    if ((flags & F_CAT) && aok) { isg = idxs[arow]; itg = idxt[arow]; }
    const uint32_t a_dst = smem0 + (uint32_t)(arow_l * SAK + ako) * 2;

    const int brow_l = t & 127;
    const bool bok = !NARROW ? ((colC0 + brow_l) < N) : (brow_l < 64 && (colC0 + brow_l) < N);
    // NOTE: no masking of brow_l here — R13's `& 63` corrupted all wide GEMMs.
    const __half* brp = Bt + (size_t)(bok ? (colC0 + brow_l) : 0) * K;
    const uint32_t b_dst = smem0 + AS_BYTES + (uint32_t)(brow_l * SAK + ako) * 2;

    const int a_row_lm = wm + (lane & 15);
    const int a_kh_lm  = (lane >> 4) * 8;
    const int b_row_lm = wn + (lane & 7) + (lane >> 4) * 8;
    const int b_kh_lm  = ((lane >> 3) & 1) * 8;

    float4 acc[MT][4];
#pragma unroll
    for (int i = 0; i < MT; i++)
#pragma unroll
        for (int j = 0; j < 4; j++) acc[i][j] = make_float4(0.f, 0.f, 0.f, 0.f);

    auto loadTile = [&](int s, int k0) {
        const uint32_t soff = (uint32_t)s * STAGE_BYTES;
        const __half* ap;
        if (!(flags & F_CAT)) {
            ap = A + (size_t)(aok ? arow : 0) * K + k0 + ako;
        } else {
            const int k = k0 + ako;
            if (k < 512)       ap = Hg + (size_t)isg * 512 + k;
            else if (k < 1024) ap = Hg + (size_t)itg * 512 + (k - 512);
            else               ap = Mg + (size_t)(aok ? arow : 0) * 512 + (k - 1024);
        }
#pragma unroll
        for (int ch = 0; ch < 2; ch++) {
            const bool ok = aok && (k0 + ako + ch * 8) < K;
            cp16(a_dst + soff + 16u * ch, ok ? (const void*)(ap + 8 * ch) : (const void*)A,
                 ok ? 16 : 0);
        }
        const __half* bp = brp + k0 + ako;
#pragma unroll
        for (int ch = 0; ch < 2; ch++) {
            const bool ok = bok && (k0 + ako + ch * 8) < K;
            cp16(b_dst + soff + 16u * ch, ok ? (const void*)(bp + 8 * ch) : (const void*)Bt,
                 ok ? 16 : 0);
        }
    };

    auto computeTile = [&](int s) {
        const uint32_t abase = smem0 + (uint32_t)s * STAGE_BYTES;
        const uint32_t bbase = abase + AS_BYTES;
#pragma unroll
        for (int g = 0; g < 2; g++) {
            uint32_t af[MT][4];
            uint32_t bf[4][2];
#pragma unroll
            for (int mt = 0; mt < MT; mt++)
                ldsm_x4(af[mt][0], af[mt][1], af[mt][2], af[mt][3],
                        abase + (uint32_t)((a_row_lm + mt * 16) * SAK + g * 16 + a_kh_lm) * 2);
#pragma unroll
            for (int p = 0; p < 2; p++)
                ldsm_x4(bf[2 * p][0], bf[2 * p][1], bf[2 * p + 1][0], bf[2 * p + 1][1],
                        bbase + (uint32_t)((b_row_lm + p * 16) * SAK + g * 16 + b_kh_lm) * 2);
#pragma unroll
            for (int mt = 0; mt < MT; mt++)
#pragma unroll
                for (int nt = 0; nt < 4; nt++)
                    mma_f16(acc[mt][nt], af[mt], bf[nt]);
        }
    };

    const int nK = (K + 31) >> 5;
    const int pre = nK < (NSTAGE - 1) ? nK : (NSTAGE - 1);
    for (int s = 0; s < pre; s++) { loadTile(s, s * 32); cp_commit(); }

    for (int i = 0; i < nK; ++i) {
        const int rem = nK - 1 - i;
        if (rem >= 2)      cp_wait<2>();
        else if (rem == 1) cp_wait<1>();
        else               cp_wait<0>();
        __syncthreads();
        if (i + NSTAGE - 1 < nK) { loadTile((i + NSTAGE - 1) & 3, (i + NSTAGE - 1) * 32); cp_commit(); }
        computeTile(i & 3);
    }

    // ---- optional rbf-multiplier epilogue tiles (K=16 MMA) ----
    const bool use_rbf = (flags & (F_RBFMUL | F_SCATH)) != 0;
    uint32_t bfr[4][2];
    if (use_rbf) {
        __syncthreads();
        {
            const int r = t & 127;
            const int off = (t >> 7) * 8;
            const int gr = rowC0 + r;
            uint4 av = make_uint4(0, 0, 0, 0);
            if (gr < M) av = *(const uint4*)(Rbf + (size_t)gr * 16 + off);
            *(uint4*)(dyn_smem + ((size_t)r * RBS + off) * 2) = av;
            const int gc = colC0 + r;
            uint4 bv = make_uint4(0, 0, 0, 0);
            if (gc < N) bv = *(const uint4*)(Wrb + (size_t)gc * 16 + off);
            *(uint4*)(dyn_smem + RB_B_OFF + ((size_t)r * RBS + off) * 2) = bv;
        }
        __syncthreads();
        const uint32_t bb = smem0 + RB_B_OFF;
#pragma unroll
        for (int p = 0; p < 2; p++)
            ldsm_x4(bfr[2 * p][0], bfr[2 * p][1], bfr[2 * p + 1][0], bfr[2 * p + 1][1],
                    bb + (uint32_t)((b_row_lm + p * 16) * RBS + b_kh_lm) * 2);
    }

    // epilogue
#pragma unroll
    for (int mt = 0; mt < MT; mt++) {
        float4 mul[4];
        if (use_rbf) {
            uint32_t afr[4];
            ldsm_x4(afr[0], afr[1], afr[2], afr[3],
                    smem0 + (uint32_t)((a_row_lm + mt * 16) * RBS + a_kh_lm) * 2);
#pragma unroll
            for (int nt = 0; nt < 4; nt++) {
                mul[nt] = make_float4(0.f, 0.f, 0.f, 0.f);
                mma_f16(mul[nt], afr, bfr[nt]);
            }
        } else {
#pragma unroll
            for (int nt = 0; nt < 4; nt++) mul[nt] = make_float4(1.f, 1.f, 1.f, 1.f);
        }
        const int r = rowC0 + wm + mt * 16 + (lane >> 2);
#pragma unroll
        for (int nt = 0; nt < 4; nt++) {
            const int cc = colC0 + wn + nt * 8 + (lane & 3) * 2;
            if (cc >= N) continue;
            const float4 v = acc[mt][nt];
            const float4 mv = mul[nt];
            if (r < M)
                epi2(C, Ct, Scath, (size_t)r * N + cc, v.x, v.y, mv.x, mv.y,
                     flags, Add1, c1, Add2, c2);
            if (r + 8 < M)
                epi2(C, Ct, Scath, (size_t)(r + 8) * N + cc, v.z, v.w, mv.z, mv.w,
                     flags, Add1, c1, Add2, c2);
        }
    }
}

// ---------------- fp32 -> fp16 conversion ----------------
__global__ void conv_half_kernel(const float* __restrict__ src, __half* __restrict__ dst, int n4) {
    const int i = blockIdx.x * blockDim.x + threadIdx.x;
    if (i >= n4) return;
    float4 v = ((const float4*)src)[i];
    __half2* d = (__half2*)dst + 2 * i;
    d[0] = __floats2half2_rn(v.x, v.y);
    d[1] = __floats2half2_rn(v.z, v.w);
}

// ---------------- batched 512x512 transpose ----------------
struct TPtrs { const float* src[16]; __half* dst[16]; };

__global__ void transpose512_batch_kernel(TPtrs p) {
    __shared__ float tile[32][33];
    const float* src = p.src[blockIdx.z];
    __half* dst = p.dst[blockIdx.z];
    const int kb = blockIdx.y * 32, nb = blockIdx.x * 32;
    const int tx = threadIdx.x, ty = threadIdx.y;
#pragma unroll
    for (int dy = 0; dy < 32; dy += 8)
        tile[ty + dy][tx] = src[(size_t)(kb + ty + dy) * 512 + nb + tx];
    __syncthreads();
#pragma unroll
    for (int dy = 0; dy < 32; dy += 8)
        dst[(size_t)(nb + ty + dy) * 512 + kb + tx] = __float2half_rn(tile[tx][ty + dy]);
}

__global__ void transpose_half_kernel(const float* __restrict__ src, __half* __restrict__ dst,
                                      int K, int N) {
    __shared__ float tile[32][33];
    const int kb = blockIdx.y * 32, nb = blockIdx.x * 32;
    const int tx = threadIdx.x, ty = threadIdx.y;
#pragma unroll
    for (int dy = 0; dy < 32; dy += 8) {
        const int k = kb + ty + dy, n = nb + tx;
        if (k < K && n < N) tile[ty + dy][tx] = src[(size_t)k * N + n];
    }
    __syncthreads();
#pragma unroll
    for (int dy = 0; dy < 32; dy += 8) {
        const int n = nb + ty + dy, k = kb + tx;
        if (n < N && k < K) dst[(size_t)n * K + k] = __float2half_rn(tile[tx][ty + dy]);
    }
}

// ---------------- triplet tmp2 ----------------
__global__ void triplet_tmp2_kernel(const __half* __restrict__ down,
                                    const int* __restrict__ id3_ba,
                                    const float* __restrict__ sph,
                                    const float* __restrict__ rbfw1,
                                    __half* __restrict__ t2)
{
    __shared__ int   sIdx[256];
    __shared__ float sS[16 * 112];
    __shared__ float sR[16 * 112];

    const int tid = threadIdx.x;
    const int e0 = blockIdx.x * 16;

    sIdx[tid] = id3_ba[(size_t)e0 * 16 + tid];
    for (int r = tid; r < 16 * 112; r += 256) {
        sS[r] = sph  [(size_t)e0 * 112 + r];
        sR[r] = rbfw1[(size_t)e0 * 112 + r];
    }
    __syncthreads();

    const int team = tid >> 4;
    const int j = tid & 15;
    const int edge = e0 + team;

    float4 G[16];
#pragma unroll
    for (int k = 0; k < 16; k++) {
        const int row = sIdx[team * 16 + k];
        const __half2* dp = (const __half2*)(down + (size_t)row * 64 + j * 4);
        float2 lo = __half22float2(dp[0]);
        float2 hi = __half22float2(dp[1]);
        G[k] = make_float4(lo.x, lo.y, hi.x, hi.y);
    }

    float4 t1[7];
#pragma unroll
    for (int s = 0; s < 7; s++) {
        float4 a = make_float4(0.f, 0.f, 0.f, 0.f);
#pragma unroll
        for (int k = 0; k < 16; k++) {
            const float f = sS[team * 112 + s * 16 + k];
            a.x = fmaf(f, G[k].x, a.x); a.y = fmaf(f, G[k].y, a.y);
            a.z = fmaf(f, G[k].z, a.z); a.w = fmaf(f, G[k].w, a.w);
        }
        t1[s] = a;
    }

#pragma unroll
    for (int i = 0; i < 16; i++) {
        float4 a = make_float4(0.f, 0.f, 0.f, 0.f);
#pragma unroll
        for (int s = 0; s < 7; s++) {
            const float f = sR[team * 112 + i * 7 + s];
            a.x = fmaf(f, t1[s].x, a.x); a.y = fmaf(f, t1[s].y, a.y);
            a.z = fmaf(f, t1[s].z, a.z); a.w = fmaf(f, t1[s].w, a.w);
        }
        __half2* out = (__half2*)(t2 + (size_t)edge * 1024 + i * 64 + j * 4);
        out[0] = __floats2half2_rn(a.x, a.y);
        out[1] = __floats2half2_rn(a.z, a.w);
    }
}

// W_bil[e,i,o] -> WBPh[o][i*64+e]
__global__ void permute_wbil_kernel(const float* __restrict__ wb, __half* __restrict__ out) {
    const int idx = blockIdx.x * blockDim.x + threadIdx.x;
    const int o = idx & 63;
    const int i = (idx >> 6) & 15;
    const int e = idx >> 10;
    out[(size_t)o * 1024 + i * 64 + e] = __float2half_rn(wb[((size_t)(e * 16 + i)) * 64 + o]);
}

// x = (xca_skip + (up2h[:,0:512] + up2h[id_swap,512:1024])*c)*c   (up2h is half)
__global__ void combine_x_kernel(float* xca, __half* xcah, const __half* __restrict__ up2h,
                                 const int* __restrict__ id_swap) {
    const int idx = blockIdx.x * blockDim.x + threadIdx.x;   // NE*128 float4s
    const int e = idx >> 7;
    const int c = idx & 127;
    const int es = id_swap[e];
    const __half2* ap = (const __half2*)(up2h + (size_t)e * 1024 + c * 4);
    const __half2* bp = (const __half2*)(up2h + (size_t)es * 1024 + 512 + c * 4);
    float2 a0 = __half22float2(ap[0]), a1 = __half22float2(ap[1]);
    float2 b0 = __half22float2(bp[0]), b1 = __half22float2(bp[1]);
    float4 x = ((float4*)xca)[idx];
    x.x = (x.x + (a0.x + b0.x) * INV_SQRT2) * INV_SQRT2;
    x.y = (x.y + (a0.y + b0.y) * INV_SQRT2) * INV_SQRT2;
    x.z = (x.z + (a1.x + b1.x) * INV_SQRT2) * INV_SQRT2;
    x.w = (x.w + (a1.y + b1.y) * INV_SQRT2) * INV_SQRT2;
    ((float4*)xca)[idx] = x;
    __half2* xh = (__half2*)xcah + 2 * idx;
    xh[0] = __floats2half2_rn(x.x, x.y);
    xh[1] = __floats2half2_rn(x.z, x.w);
}

// segment-sum: out[idx_t[e]] += scath[e]
__global__ void scatter_atoms_kernel(const __half* __restrict__ scath,
                                     const int* __restrict__ idx_t, float* out) {
    const int idx = blockIdx.x * blockDim.x + threadIdx.x;
    const int e = idx >> 7;
    const int c = idx & 127;
    const int t = idx_t[e];
    const __half2* bp = (const __half2*)scath + 2 * idx;
    float2 b0 = __half22float2(bp[0]);
    float2 b1 = __half22float2(bp[1]);
    float* dst = out + (size_t)t * 512 + c * 4;
    atomicAdd(dst + 0, b0.x);
    atomicAdd(dst + 1, b0.y);
    atomicAdd(dst + 2, b1.x);
    atomicAdd(dst + 3, b1.y);
}

// ---------------- host orchestration ----------------
static void run_gemm_impl(bool narrow,
                          const __half* A, const __half* Bt, float* C, int M, int N, int K,
                          int flags, __half* Ct,
                          const float* Ad1, float c1, const float* Ad2, float c2,
                          const __half* Hg, const int* isx, const int* itx, const __half* Mg,
                          const __half* Rbf, const __half* Wrb, __half* Scath)
{
    static bool attr_set = false;
    if (!attr_set) {
        cudaFuncSetAttribute(mma_gemm_kernel<false>, cudaFuncAttributeMaxDynamicSharedMemorySize, SMEM_DYN);
        cudaFuncSetAttribute(mma_gemm_kernel<true>,  cudaFuncAttributeMaxDynamicSharedMemorySize, SMEM_DYN);
        attr_set = true;
    }
    if (narrow) {
        dim3 grid((N + 63) / 64, (M + 127) / 128);
        mma_gemm_kernel<true><<<grid, 256, SMEM_DYN>>>(A, Bt, C, Ct, M, N, K, flags,
                                                       Ad1, c1, Ad2, c2, Hg, isx, itx, Mg,
                                                       Rbf, Wrb, Scath);
    } else {
        dim3 grid((N + 127) / 128, (M + 127) / 128);
        mma_gemm_kernel<false><<<grid, 256, SMEM_DYN>>>(A, Bt, C, Ct, M, N, K, flags,
                                                        Ad1, c1, Ad2, c2, Hg, isx, itx, Mg,
                                                        Rbf, Wrb, Scath);
    }
}
static void run_gemm(const __half* A, const __half* Bt, float* C, int M, int N, int K, int flags,
                     __half* Ct = nullptr,
                     const float* Ad1 = nullptr, float c1 = 1.f,
                     const float* Ad2 = nullptr, float c2 = 1.f,
                     const __half* Hg = nullptr, const int* isx = nullptr,
                     const int* itx = nullptr, const __half* Mg = nullptr,
                     const __half* Rbf = nullptr, const __half* Wrb = nullptr,
                     __half* Scath = nullptr)
{
    run_gemm_impl(N <= 64, A, Bt, C, M, N, K, flags, Ct, Ad1, c1, Ad2, c2,
                  Hg, isx, itx, Mg, Rbf, Wrb, Scath);
}
static void run_conv(const float* src, __half* dst, size_t n) {
    const int n4 = (int)(n / 4);
    conv_half_kernel<<<(n4 + 255) / 256, 256>>>(src, dst, n4);
}
static void run_transpose(const float* src, __half* dst, int K, int N) {
    dim3 grid((N + 31) / 32, (K + 31) / 32);
    transpose_half_kernel<<<grid, dim3(32, 8)>>>(src, dst, K, N);
}

extern "C" void kernel_launch(void* const* d_in, const int* in_sizes, int n_in,
                              void* d_out, int out_size)
{
    const float* h_in    = (const float*)d_in[0];
    const float* m_in    = (const float*)d_in[1];
    const float* rbf3    = (const float*)d_in[2];
    const float* rbf_w1  = (const float*)d_in[3];
    const float* sph     = (const float*)d_in[4];
    const float* rbf_h   = (const float*)d_in[5];
    const int*   id3_ba  = (const int*)d_in[6];
    const int*   id_swap = (const int*)d_in[9];
    const int*   idx_s   = (const int*)d_in[10];
    const int*   idx_t   = (const int*)d_in[11];
    const float* W_dense_ca = (const float*)d_in[12];
    const float* W_ba    = (const float*)d_in[13];
    const float* W_rbf3  = (const float*)d_in[14];
    const float* W_down  = (const float*)d_in[15];
    const float* W_bil   = (const float*)d_in[16];
    const float* W_up_ca = (const float*)d_in[17];
    const float* W_up_ac = (const float*)d_in[18];
    const float* W_bs    = (const float*)d_in[19];
    const float* W_as    = (const float*)d_in[20];
    const float* W_au_rbf= (const float*)d_in[21];
    const float* W_au_d1 = (const float*)d_in[22];
    const float* W_au_res= (const float*)d_in[23];
    const float* W_cat   = (const float*)d_in[24];
    const float* W_res_m = (const float*)d_in[25];

    float* pool = nullptr;
    cudaGetSymbolAddress((void**)&pool, g_pool);
    float*  XCA  = pool + OFF_XCA;
    float*  Mb   = pool + OFF_MB;
    float*  A1   = pool + OFF_A1;
    float*  A2   = pool + OFF_A2;
    __half* Mh   = (__half*)(pool + OFF_MH);
    __half* TMPh = (__half*)(pool + OFF_TMPH);
    __half* XCAh = (__half*)(pool + OFF_XCAH);
    __half* Mbh  = (__half*)(pool + OFF_MBH);
    __half* DWNh = (__half*)(pool + OFF_DWNH);
    __half* XBh  = (__half*)(pool + OFF_XBH);
    __half* T2h  = (__half*)(pool + OFF_T2H);   // reused as UP2h after bilinear
    __half* R3h  = (__half*)(pool + OFF_R3H);
    __half* RHh  = (__half*)(pool + OFF_RHH);
    __half* A1h  = (__half*)(pool + OFF_A1H);
    __half* A2h  = (__half*)(pool + OFF_A2H);
    __half* A3h  = (__half*)(pool + OFF_A3H);
    __half* OHh  = (__half*)(pool + OFF_OHH);
    __half* WH   = (__half*)(pool + OFF_WTSH);

    const size_t W2 = (size_t)DDg * DDg;
    __half* Wh_dense_ca = WH;            size_t woff = W2;
    __half* Wh_ba       = WH + woff;     woff += W2;
    __half* Wh_rbf3     = WH + woff;     woff += (size_t)DDg * 16;
    __half* Wh_down     = WH + woff;     woff += (size_t)DTg * DDg;
    __half* Wh_up_ca    = WH + woff;     woff += (size_t)DDg * DTg;
    __half* Wh_up_ac    = WH + woff;     woff += (size_t)DDg * DTg;
    __half* Wh_bs       = WH + woff;     woff += 2 * W2;
    __half* Wh_as       = WH + woff;     woff += 4 * W2;
    __half* Wh_au_rbf   = WH + woff;     woff += (size_t)DDg * 16;
    __half* Wh_au_d1    = WH + woff;     woff += W2;
    __half* Wh_au_res   = WH + woff;     woff += 6 * W2;
    __half* Wh_cat      = WH + woff;     woff += 3 * W2;
    __half* Wh_res_m    = WH + woff;     woff += 2 * W2;
    __half* WBPh        = WH + woff;     woff += (size_t)DTg * 1024;

    float* OUT_H = (float*)d_out;
    float* OUT_M = (float*)d_out + NA512;

    const float C = INV_SQRT2;

    // ---- pre-conversions ----
    run_conv(m_in, Mh, NE512);
    run_conv(rbf3, R3h, NE16);
    run_conv(rbf_h, RHh, NE16);
    {
        TPtrs tp{};
        int n = 0;
        tp.src[n] = W_dense_ca; tp.dst[n] = Wh_dense_ca; n++;
        tp.src[n] = W_ba;       tp.dst[n] = Wh_ba;       n++;
        tp.src[n] = W_au_d1;    tp.dst[n] = Wh_au_d1;    n++;
        for (int i = 0; i < 2; i++) { tp.src[n] = W_bs + i * W2;     tp.dst[n] = Wh_bs + i * W2;     n++; }
        for (int i = 0; i < 4; i++) { tp.src[n] = W_as + i * W2;     tp.dst[n] = Wh_as + i * W2;     n++; }
        for (int i = 0; i < 6; i++) { tp.src[n] = W_au_res + i * W2; tp.dst[n] = Wh_au_res + i * W2; n++; }
        transpose512_batch_kernel<<<dim3(16, 16, n), dim3(32, 8)>>>(tp);
    }
    {
        TPtrs tp{};
        tp.src[0] = W_res_m;      tp.dst[0] = Wh_res_m;
        tp.src[1] = W_res_m + W2; tp.dst[1] = Wh_res_m + W2;
        transpose512_batch_kernel<<<dim3(16, 16, 2), dim3(32, 8)>>>(tp);
    }
    run_transpose(W_rbf3, Wh_rbf3, 16, DDg);
    run_transpose(W_down, Wh_down, DDg, DTg);
    run_transpose(W_up_ca, Wh_up_ca, DTg, DDg);
    run_transpose(W_up_ac, Wh_up_ac, DTg, DDg);
    run_transpose(W_au_rbf, Wh_au_rbf, 16, DDg);
    run_transpose(W_cat, Wh_cat, 3 * DDg, DDg);
    permute_wbil_kernel<<<(NCBF * DTg * DTg) / 256, 256>>>(W_bil, WBPh);

    // ---- pipeline ----
    run_gemm(Mh, Wh_ba, nullptr, NEg, DDg, DDg, F_ACT | F_RBFMUL | F_HALF | F_NOF32,
             TMPh, nullptr, 1.f, nullptr, 1.f, nullptr, nullptr, nullptr, nullptr,
             R3h, Wh_rbf3, nullptr);
    run_gemm(TMPh, Wh_down, nullptr, NEg, DTg, DDg, F_ACT | F_HALF | F_NOF32, DWNh);
    run_gemm(Mh, Wh_dense_ca, XCA, NEg, DDg, DDg, F_ACT);

    triplet_tmp2_kernel<<<NEg / 16, 256>>>(DWNh, id3_ba, sph, rbf_w1, T2h);
    run_gemm(T2h, WBPh, nullptr, NEg, DTg, NCBF * DTg, F_HALF | F_NOF32, XBh);

    // merged up projection (N=1024), half output into T2h (dead after bilinear)
    run_gemm(XBh, Wh_up_ca, nullptr, NEg, 1024, DTg, F_ACT | F_HALF | F_NOF32, T2h);
    combine_x_kernel<<<(NEg * 128) / 256, 256>>>(XCA, XCAh, T2h, id_swap);

    run_gemm(XCAh, Wh_bs, nullptr, NEg, DDg, DDg, F_ACT | F_HALF | F_NOF32, TMPh);
    run_gemm(TMPh, Wh_bs + W2, Mb, NEg, DDg, DDg, F_ACT | F_ADD1 | F_ADD2 | F_HALF,
             Mbh, XCA, C, m_in, C);

    run_gemm(Mbh, Wh_as + 0 * W2, nullptr, NEg, DDg, DDg, F_ACT | F_HALF | F_NOF32, TMPh);
    run_gemm(TMPh, Wh_as + 1 * W2, Mb, NEg, DDg, DDg, F_ACT | F_ADD1 | F_HALF,
             Mbh, Mb, C);
    run_gemm(Mbh, Wh_as + 2 * W2, nullptr, NEg, DDg, DDg, F_ACT | F_HALF | F_NOF32, TMPh);
    run_gemm(TMPh, Wh_as + 3 * W2, Mb, NEg, DDg, DDg, F_ACT | F_ADD1 | F_HALF | F_SCATH,
             Mbh, Mb, C, nullptr, 1.f, nullptr, nullptr, nullptr, nullptr,
             RHh, Wh_au_rbf, XCAh);

    cudaMemsetAsync(A1, 0, NA512 * sizeof(float));
    scatter_atoms_kernel<<<(NEg * 128) / 256, 256>>>(XCAh, idx_t, A1);
    run_conv(A1, A1h, NA512);
    run_gemm(A1h, Wh_au_d1, A2, NAg, DDg, DDg, F_ACT | F_HALF, A2h);
    run_gemm(A2h, Wh_au_res + 0 * W2, nullptr, NAg, DDg, DDg, F_ACT | F_HALF | F_NOF32, A3h);
    run_gemm(A3h, Wh_au_res + 1 * W2, A2, NAg, DDg, DDg, F_ACT | F_ADD1 | F_HALF,
             A2h, A2, C);
    run_gemm(A2h, Wh_au_res + 2 * W2, nullptr, NAg, DDg, DDg, F_ACT | F_HALF | F_NOF32, A3h);
    run_gemm(A3h, Wh_au_res + 3 * W2, A2, NAg, DDg, DDg, F_ACT | F_ADD1 | F_HALF,
             A2h, A2, C);
    run_gemm(A2h, Wh_au_res + 4 * W2, nullptr, NAg, DDg, DDg, F_ACT | F_HALF | F_NOF32, A3h);
    run_gemm(A3h, Wh_au_res + 5 * W2, OUT_H, NAg, DDg, DDg,
             F_ACT | F_ADD1 | F_ADD2 | F_HALF, OHh, A2, C, h_in, C);

    run_gemm(nullptr, Wh_cat, XCA, NEg, DDg, 3 * DDg, F_ACT | F_CAT | F_HALF,
             XCAh, nullptr, 1.f, nullptr, 1.f, OHh, idx_s, idx_t, Mbh);

    run_gemm(XCAh, Wh_res_m, nullptr, NEg, DDg, DDg, F_ACT | F_HALF | F_NOF32, TMPh);
    run_gemm(TMPh, Wh_res_m + W2, OUT_M, NEg, DDg, DDg, F_ACT | F_ADD1 | F_ADD2,
             nullptr, XCA, C, Mb, C);

    (void)in_sizes; (void)n_in; (void)out_size;
}

// round 15
// speedup vs baseline: 1.1046x; 1.0540x over previous
#include <cuda_runtime.h>
#include <cuda_fp16.h>
#include <cstdint>

// ---------------- problem constants ----------------
constexpr int NEg   = 100000;
constexpr int NAg   = 5000;
constexpr int DDg   = 512;
constexpr int DTg   = 64;
constexpr int NCBF  = 16;

constexpr float INV_SQRT2 = 0.70710678118654752f;
constexpr float ACT_SCALE = 1.0f / 0.6f;

// ---------------- scratch pool (float units) ----------------
constexpr size_t NE512  = (size_t)NEg * DDg;
constexpr size_t NE64   = (size_t)NEg * DTg;
constexpr size_t NE1024 = (size_t)NEg * 1024;
constexpr size_t NE16   = (size_t)NEg * 16;
constexpr size_t NA512  = (size_t)NAg * DDg;

constexpr size_t OFF_XCA  = 0;
constexpr size_t OFF_TMP  = OFF_XCA + NE512;
constexpr size_t OFF_UP   = OFF_TMP + NE512;
constexpr size_t OFF_MB   = OFF_UP  + NE512;
constexpr size_t OFF_A1   = OFF_MB  + NE512;
constexpr size_t OFF_A2   = OFF_A1  + NA512;
constexpr size_t OFF_MH   = OFF_A2   + NA512;
constexpr size_t OFF_TMPH = OFF_MH   + NE512 / 2;
constexpr size_t OFF_XCAH = OFF_TMPH + NE512 / 2;
constexpr size_t OFF_MBH  = OFF_XCAH + NE512 / 2;
constexpr size_t OFF_DWNH = OFF_MBH  + NE512 / 2;
constexpr size_t OFF_XBH  = OFF_DWNH + NE64 / 2;
constexpr size_t OFF_T2H  = OFF_XBH  + NE64 / 2;
constexpr size_t OFF_R3H  = OFF_T2H  + NE1024 / 2;
constexpr size_t OFF_RHH  = OFF_R3H  + NE16 / 2;
constexpr size_t OFF_A1H  = OFF_RHH  + NE16 / 2;
constexpr size_t OFF_A2H  = OFF_A1H  + NA512 / 2;
constexpr size_t OFF_A3H  = OFF_A2H  + NA512 / 2;
constexpr size_t OFF_OHH  = OFF_A3H  + NA512 / 2;
constexpr size_t OFF_WTSH = OFF_OHH  + NA512 / 2;
constexpr size_t WTSH_FLOATS = 3u * 1024 * 1024;
constexpr size_t POOL_TOTAL = OFF_WTSH + WTSH_FLOATS;

__device__ __align__(256) float g_pool[POOL_TOTAL];

// ---------------- helpers ----------------
__device__ __forceinline__ float scaled_silu(float x) {
    return x * (1.0f / (1.0f + __expf(-x))) * ACT_SCALE;
}
__device__ __forceinline__ void mma_f16(float4& d, const uint32_t a[4], const uint32_t b[2]) {
    asm volatile(
        "mma.sync.aligned.m16n8k16.row.col.f32.f16.f16.f32 "
        "{%0,%1,%2,%3}, {%4,%5,%6,%7}, {%8,%9}, {%0,%1,%2,%3};"
        : "+f"(d.x), "+f"(d.y), "+f"(d.z), "+f"(d.w)
        : "r"(a[0]), "r"(a[1]), "r"(a[2]), "r"(a[3]), "r"(b[0]), "r"(b[1]));
}
__device__ __forceinline__ void ldsm_x4(uint32_t& r0, uint32_t& r1, uint32_t& r2, uint32_t& r3,
                                        uint32_t addr) {
    asm volatile("ldmatrix.sync.aligned.m8n8.x4.shared.b16 {%0,%1,%2,%3}, [%4];"
                 : "=r"(r0), "=r"(r1), "=r"(r2), "=r"(r3) : "r"(addr));
}
__device__ __forceinline__ void cp16(uint32_t smem_dst, const void* gsrc, int szbytes) {
    asm volatile("cp.async.cg.shared.global [%0], [%1], 16, %2;"
                 :: "r"(smem_dst), "l"(gsrc), "r"(szbytes));
}
__device__ __forceinline__ void cp_commit() { asm volatile("cp.async.commit_group;"); }
template <int N> __device__ __forceinline__ void cp_wait() {
    asm volatile("cp.async.wait_group %0;" :: "n"(N));
}

// ---------------- fp16 tensor-core GEMM ----------------
enum { F_ACT = 1, F_MUL = 2, F_ADD1 = 4, F_ADD2 = 8, F_HALF = 32, F_NOF32 = 64,
       F_RBFMUL = 128, F_SCATH = 256, F_GATH = 512 };

constexpr int SAK = 40;
constexpr int NSTAGE = 4;
constexpr int AS_BYTES = 128 * SAK * 2;
constexpr int STAGE_BYTES = 2 * AS_BYTES;
constexpr int SMEM_DYN = NSTAGE * STAGE_BYTES;        // 81920

constexpr int RBS = 24;
constexpr int RB_BYTES = 128 * RBS * 2;
constexpr int RB_B_OFF = RB_BYTES;

__device__ __forceinline__ void epi2(float* C, __half* Ct, __half* Sc, size_t idx,
                                     float vx, float vy, float mx, float my,
                                     int flags, const float* Add1, float c1,
                                     const float* Add2, float c2) {
    if (flags & F_ACT)    { vx = scaled_silu(vx);       vy = scaled_silu(vy); }
    if (flags & F_RBFMUL) { vx *= mx;                   vy *= my; }
    if (flags & F_ADD1)   { vx = (Add1[idx] + vx) * c1; vy = (Add1[idx + 1] + vy) * c1; }
    if (flags & F_ADD2)   { vx = (vx + Add2[idx]) * c2; vy = (vy + Add2[idx + 1]) * c2; }
    if (flags & F_SCATH)  *(__half2*)(Sc + idx) = __floats2half2_rn(vx * mx, vy * my);
    if (flags & F_HALF)   *(__half2*)(Ct + idx) = __floats2half2_rn(vx, vy);
    if (!(flags & F_NOF32)) { C[idx] = vx; C[idx + 1] = vy; }
}

// NARROW=false: 128x128 tile, warp 64x32 (MT=4). NARROW=true: 128x64 tile, warp 32x32 (MT=2).
template <bool NARROW>
__global__ __launch_bounds__(256, 2)
void mma_gemm_kernel(const __half* __restrict__ A, const __half* __restrict__ Bt,
                     float* __restrict__ C, __half* __restrict__ Ct,
                     int M, int N, int K, int flags,
                     const float* __restrict__ Add1, float c1,
                     const float* __restrict__ Add2, float c2,
                     const int* __restrict__ idxs, const int* __restrict__ idxt,
                     const __half* __restrict__ Rbf, const __half* __restrict__ Wrb,
                     __half* __restrict__ Scath)
{
    extern __shared__ __align__(16) char dyn_smem[];

    constexpr int MT = NARROW ? 2 : 4;

    const int t = threadIdx.x;
    const int lane = t & 31;
    const int warp = t >> 5;
    const int wm = NARROW ? (warp >> 1) * 32 : (warp >> 2) * 64;
    const int wn = NARROW ? (warp & 1) * 32 : (warp & 3) * 32;
    const int rowC0 = blockIdx.y * 128;
    const int colC0 = blockIdx.x * (NARROW ? 64 : 128);

    const uint32_t smem0 = (uint32_t)__cvta_generic_to_shared(dyn_smem);

    const int arow_l = t & 127;
    const int ako = (t >> 7) * 16;
    const int arow = rowC0 + arow_l;
    const bool aok = arow < M;
    const uint32_t a_dst = smem0 + (uint32_t)(arow_l * SAK + ako) * 2;

    const int brow_l = t & 127;
    const bool bok = !NARROW ? ((colC0 + brow_l) < N) : (brow_l < 64 && (colC0 + brow_l) < N);
    const __half* brp = Bt + (size_t)(bok ? (colC0 + brow_l) : 0) * K;
    const uint32_t b_dst = smem0 + AS_BYTES + (uint32_t)(brow_l * SAK + ako) * 2;

    const int a_row_lm = wm + (lane & 15);
    const int a_kh_lm  = (lane >> 4) * 8;
    const int b_row_lm = wn + (lane & 7) + (lane >> 4) * 8;
    const int b_kh_lm  = ((lane >> 3) & 1) * 8;

    float4 acc[MT][4];
#pragma unroll
    for (int i = 0; i < MT; i++)
#pragma unroll
        for (int j = 0; j < 4; j++) acc[i][j] = make_float4(0.f, 0.f, 0.f, 0.f);

    auto loadTile = [&](int s, int k0) {
        const uint32_t soff = (uint32_t)s * STAGE_BYTES;
        const __half* ap = A + (size_t)(aok ? arow : 0) * K + k0 + ako;
#pragma unroll
        for (int ch = 0; ch < 2; ch++) {
            const bool ok = aok && (k0 + ako + ch * 8) < K;
            cp16(a_dst + soff + 16u * ch, ok ? (const void*)(ap + 8 * ch) : (const void*)A,
                 ok ? 16 : 0);
        }
        const __half* bp = brp + k0 + ako;
#pragma unroll
        for (int ch = 0; ch < 2; ch++) {
            const bool ok = bok && (k0 + ako + ch * 8) < K;
            cp16(b_dst + soff + 16u * ch, ok ? (const void*)(bp + 8 * ch) : (const void*)Bt,
                 ok ? 16 : 0);
        }
    };

    auto computeTile = [&](int s) {
        const uint32_t abase = smem0 + (uint32_t)s * STAGE_BYTES;
        const uint32_t bbase = abase + AS_BYTES;
#pragma unroll
        for (int g = 0; g < 2; g++) {
            uint32_t af[MT][4];
            uint32_t bf[4][2];
#pragma unroll
            for (int mt = 0; mt < MT; mt++)
                ldsm_x4(af[mt][0], af[mt][1], af[mt][2], af[mt][3],
                        abase + (uint32_t)((a_row_lm + mt * 16) * SAK + g * 16 + a_kh_lm) * 2);
#pragma unroll
            for (int p = 0; p < 2; p++)
                ldsm_x4(bf[2 * p][0], bf[2 * p][1], bf[2 * p + 1][0], bf[2 * p + 1][1],
                        bbase + (uint32_t)((b_row_lm + p * 16) * SAK + g * 16 + b_kh_lm) * 2);
#pragma unroll
            for (int mt = 0; mt < MT; mt++)
#pragma unroll
                for (int nt = 0; nt < 4; nt++)
                    mma_f16(acc[mt][nt], af[mt], bf[nt]);
        }
    };

    const int nK = (K + 31) >> 5;
    const int pre = nK < (NSTAGE - 1) ? nK : (NSTAGE - 1);
    for (int s = 0; s < pre; s++) { loadTile(s, s * 32); cp_commit(); }

    for (int i = 0; i < nK; ++i) {
        const int rem = nK - 1 - i;
        if (rem >= 2)      cp_wait<2>();
        else if (rem == 1) cp_wait<1>();
        else               cp_wait<0>();
        __syncthreads();
        if (i + NSTAGE - 1 < nK) { loadTile((i + NSTAGE - 1) & 3, (i + NSTAGE - 1) * 32); cp_commit(); }
        computeTile(i & 3);
    }

    // ---- optional rbf-multiplier epilogue tiles (K=16 MMA) ----
    const bool use_rbf = (flags & (F_RBFMUL | F_SCATH)) != 0;
    uint32_t bfr[4][2];
    if (use_rbf) {
        __syncthreads();
        {
            const int r = t & 127;
            const int off = (t >> 7) * 8;
            const int gr = rowC0 + r;
            uint4 av = make_uint4(0, 0, 0, 0);
            if (gr < M) av = *(const uint4*)(Rbf + (size_t)gr * 16 + off);
            *(uint4*)(dyn_smem + ((size_t)r * RBS + off) * 2) = av;
            const int gc = colC0 + r;
            uint4 bv = make_uint4(0, 0, 0, 0);
            if (gc < N) bv = *(const uint4*)(Wrb + (size_t)gc * 16 + off);
            *(uint4*)(dyn_smem + RB_B_OFF + ((size_t)r * RBS + off) * 2) = bv;
        }
        __syncthreads();
        const uint32_t bb = smem0 + RB_B_OFF;
#pragma unroll
        for (int p = 0; p < 2; p++)
            ldsm_x4(bfr[2 * p][0], bfr[2 * p][1], bfr[2 * p + 1][0], bfr[2 * p + 1][1],
                    bb + (uint32_t)((b_row_lm + p * 16) * RBS + b_kh_lm) * 2);
    }

    // epilogue
#pragma unroll
    for (int mt = 0; mt < MT; mt++) {
        float4 mul[4];
        if (use_rbf) {
            uint32_t afr[4];
            ldsm_x4(afr[0], afr[1], afr[2], afr[3],
                    smem0 + (uint32_t)((a_row_lm + mt * 16) * RBS + a_kh_lm) * 2);
#pragma unroll
            for (int nt = 0; nt < 4; nt++) {
                mul[nt] = make_float4(0.f, 0.f, 0.f, 0.f);
                mma_f16(mul[nt], afr, bfr[nt]);
            }
        } else {
#pragma unroll
            for (int nt = 0; nt < 4; nt++) mul[nt] = make_float4(1.f, 1.f, 1.f, 1.f);
        }
        const int r = rowC0 + wm + mt * 16 + (lane >> 2);
        // F_GATH: per-row gather bases into HS (Add1) / HT (Add2) tables
        const float* g0a = nullptr; const float* g0b = nullptr;
        const float* g1a = nullptr; const float* g1b = nullptr;
        if (flags & F_GATH) {
            if (r < M)     { g0a = Add1 + (size_t)idxs[r] * 512;     g0b = Add2 + (size_t)idxt[r] * 512; }
            if (r + 8 < M) { g1a = Add1 + (size_t)idxs[r + 8] * 512; g1b = Add2 + (size_t)idxt[r + 8] * 512; }
        }
#pragma unroll
        for (int nt = 0; nt < 4; nt++) {
            const int cc = colC0 + wn + nt * 8 + (lane & 3) * 2;
            if (cc >= N) continue;
            float4 v = acc[mt][nt];
            const float4 mv = mul[nt];
            if (flags & F_GATH) {
                if (g0a) { v.x += g0a[cc] + g0b[cc]; v.y += g0a[cc + 1] + g0b[cc + 1]; }
                if (g1a) { v.z += g1a[cc] + g1b[cc]; v.w += g1a[cc + 1] + g1b[cc + 1]; }
            }
            const int fl = flags & ~(F_ADD1 | F_ADD2 * ((flags & F_GATH) ? 1 : 0));
            if (r < M)
                epi2(C, Ct, Scath, (size_t)r * N + cc, v.x, v.y, mv.x, mv.y,
                     (flags & F_GATH) ? (flags & ~(F_ADD1 | F_ADD2)) : flags, Add1, c1, Add2, c2);
            if (r + 8 < M)
                epi2(C, Ct, Scath, (size_t)(r + 8) * N + cc, v.z, v.w, mv.z, mv.w,
                     (flags & F_GATH) ? (flags & ~(F_ADD1 | F_ADD2)) : flags, Add1, c1, Add2, c2);
            (void)fl;
        }
    }
}

// ---------------- fp32 -> fp16 conversion ----------------
__global__ void conv_half_kernel(const float* __restrict__ src, __half* __restrict__ dst, int n4) {
    const int i = blockIdx.x * blockDim.x + threadIdx.x;
    if (i >= n4) return;
    float4 v = ((const float4*)src)[i];
    __half2* d = (__half2*)dst + 2 * i;
    d[0] = __floats2half2_rn(v.x, v.y);
    d[1] = __floats2half2_rn(v.z, v.w);
}

// ---------------- batched 512x512 transpose ----------------
struct TPtrs { const float* src[16]; __half* dst[16]; };

__global__ void transpose512_batch_kernel(TPtrs p) {
    __shared__ float tile[32][33];
    const float* src = p.src[blockIdx.z];
    __half* dst = p.dst[blockIdx.z];
    const int kb = blockIdx.y * 32, nb = blockIdx.x * 32;
    const int tx = threadIdx.x, ty = threadIdx.y;
#pragma unroll
    for (int dy = 0; dy < 32; dy += 8)
        tile[ty + dy][tx] = src[(size_t)(kb + ty + dy) * 512 + nb + tx];
    __syncthreads();
#pragma unroll
    for (int dy = 0; dy < 32; dy += 8)
        dst[(size_t)(nb + ty + dy) * 512 + kb + tx] = __float2half_rn(tile[tx][ty + dy]);
}

__global__ void transpose_half_kernel(const float* __restrict__ src, __half* __restrict__ dst,
                                      int K, int N) {
    __shared__ float tile[32][33];
    const int kb = blockIdx.y * 32, nb = blockIdx.x * 32;
    const int tx = threadIdx.x, ty = threadIdx.y;
#pragma unroll
    for (int dy = 0; dy < 32; dy += 8) {
        const int k = kb + ty + dy, n = nb + tx;
        if (k < K && n < N) tile[ty + dy][tx] = src[(size_t)k * N + n];
    }
    __syncthreads();
#pragma unroll
    for (int dy = 0; dy < 32; dy += 8) {
        const int n = nb + ty + dy, k = kb + tx;
        if (n < N && k < K) dst[(size_t)n * K + k] = __float2half_rn(tile[tx][ty + dy]);
    }
}

// ---------------- triplet tmp2 ----------------
__global__ void triplet_tmp2_kernel(const __half* __restrict__ down,
                                    const int* __restrict__ id3_ba,
                                    const float* __restrict__ sph,
                                    const float* __restrict__ rbfw1,
                                    __half* __restrict__ t2)
{
    __shared__ int   sIdx[256];
    __shared__ float sS[16 * 112];
    __shared__ float sR[16 * 112];

    const int tid = threadIdx.x;
    const int e0 = blockIdx.x * 16;

    sIdx[tid] = id3_ba[(size_t)e0 * 16 + tid];
    for (int r = tid; r < 16 * 112; r += 256) {
        sS[r] = sph  [(size_t)e0 * 112 + r];
        sR[r] = rbfw1[(size_t)e0 * 112 + r];
    }
    __syncthreads();

    const int team = tid >> 4;
    const int j = tid & 15;
    const int edge = e0 + team;

    float4 G[16];
#pragma unroll
    for (int k = 0; k < 16; k++) {
        const int row = sIdx[team * 16 + k];
        const __half2* dp = (const __half2*)(down + (size_t)row * 64 + j * 4);
        float2 lo = __half22float2(dp[0]);
        float2 hi = __half22float2(dp[1]);
        G[k] = make_float4(lo.x, lo.y, hi.x, hi.y);
    }

    float4 t1[7];
#pragma unroll
    for (int s = 0; s < 7; s++) {
        float4 a = make_float4(0.f, 0.f, 0.f, 0.f);
#pragma unroll
        for (int k = 0; k < 16; k++) {
            const float f = sS[team * 112 + s * 16 + k];
            a.x = fmaf(f, G[k].x, a.x); a.y = fmaf(f, G[k].y, a.y);
            a.z = fmaf(f, G[k].z, a.z); a.w = fmaf(f, G[k].w, a.w);
        }
        t1[s] = a;
    }

#pragma unroll
    for (int i = 0; i < 16; i++) {
        float4 a = make_float4(0.f, 0.f, 0.f, 0.f);
#pragma unroll
        for (int s = 0; s < 7; s++) {
            const float f = sR[team * 112 + i * 7 + s];
            a.x = fmaf(f, t1[s].x, a.x); a.y = fmaf(f, t1[s].y, a.y);
            a.z = fmaf(f, t1[s].z, a.z); a.w = fmaf(f, t1[s].w, a.w);
        }
        __half2* out = (__half2*)(t2 + (size_t)edge * 1024 + i * 64 + j * 4);
        out[0] = __floats2half2_rn(a.x, a.y);
        out[1] = __floats2half2_rn(a.z, a.w);
    }
}

// W_bil[e,i,o] -> WBPh[o][i*64+e]
__global__ void permute_wbil_kernel(const float* __restrict__ wb, __half* __restrict__ out) {
    const int idx = blockIdx.x * blockDim.x + threadIdx.x;
    const int o = idx & 63;
    const int i = (idx >> 6) & 15;
    const int e = idx >> 10;
    out[(size_t)o * 1024 + i * 64 + e] = __float2half_rn(wb[((size_t)(e * 16 + i)) * 64 + o]);
}

// x = (xca_skip + (up2h[:,0:512] + up2h[id_swap,512:1024])*c)*c   (up2h is half)
__global__ void combine_x_kernel(float* xca, __half* xcah, const __half* __restrict__ up2h,
                                 const int* __restrict__ id_swap) {
    const int idx = blockIdx.x * blockDim.x + threadIdx.x;
    const int e = idx >> 7;
    const int c = idx & 127;
    const int es = id_swap[e];
    const __half2* ap = (const __half2*)(up2h + (size_t)e * 1024 + c * 4);
    const __half2* bp = (const __half2*)(up2h + (size_t)es * 1024 + 512 + c * 4);
    float2 a0 = __half22float2(ap[0]), a1 = __half22float2(ap[1]);
    float2 b0 = __half22float2(bp[0]), b1 = __half22float2(bp[1]);
    float4 x = ((float4*)xca)[idx];
    x.x = (x.x + (a0.x + b0.x) * INV_SQRT2) * INV_SQRT2;
    x.y = (x.y + (a0.y + b0.y) * INV_SQRT2) * INV_SQRT2;
    x.z = (x.z + (a1.x + b1.x) * INV_SQRT2) * INV_SQRT2;
    x.w = (x.w + (a1.y + b1.y) * INV_SQRT2) * INV_SQRT2;
    ((float4*)xca)[idx] = x;
    __half2* xh = (__half2*)xcah + 2 * idx;
    xh[0] = __floats2half2_rn(x.x, x.y);
    xh[1] = __floats2half2_rn(x.z, x.w);
}

// segment-sum: out[idx_t[e]] += scath[e]
__global__ void scatter_atoms_kernel(const __half* __restrict__ scath,
                                     const int* __restrict__ idx_t, float* out) {
    const int idx = blockIdx.x * blockDim.x + threadIdx.x;
    const int e = idx >> 7;
    const int c = idx & 127;
    const int t = idx_t[e];
    const __half2* bp = (const __half2*)scath + 2 * idx;
    float2 b0 = __half22float2(bp[0]);
    float2 b1 = __half22float2(bp[1]);
    float* dst = out + (size_t)t * 512 + c * 4;
    atomicAdd(dst + 0, b0.x);
    atomicAdd(dst + 1, b0.y);
    atomicAdd(dst + 2, b1.x);
    atomicAdd(dst + 3, b1.y);
}

// ---------------- host orchestration ----------------
static void run_gemm_impl(bool narrow,
                          const __half* A, const __half* Bt, float* C, int M, int N, int K,
                          int flags, __half* Ct,
                          const float* Ad1, float c1, const float* Ad2, float c2,
                          const int* isx, const int* itx,
                          const __half* Rbf, const __half* Wrb, __half* Scath)
{
    static bool attr_set = false;
    if (!attr_set) {
        cudaFuncSetAttribute(mma_gemm_kernel<false>, cudaFuncAttributeMaxDynamicSharedMemorySize, SMEM_DYN);
        cudaFuncSetAttribute(mma_gemm_kernel<true>,  cudaFuncAttributeMaxDynamicSharedMemorySize, SMEM_DYN);
        attr_set = true;
    }
    if (narrow) {
        dim3 grid((N + 63) / 64, (M + 127) / 128);
        mma_gemm_kernel<true><<<grid, 256, SMEM_DYN>>>(A, Bt, C, Ct, M, N, K, flags,
                                                       Ad1, c1, Ad2, c2, isx, itx,
                                                       Rbf, Wrb, Scath);
    } else {
        dim3 grid((N + 127) / 128, (M + 127) / 128);
        mma_gemm_kernel<false><<<grid, 256, SMEM_DYN>>>(A, Bt, C, Ct, M, N, K, flags,
                                                        Ad1, c1, Ad2, c2, isx, itx,
                                                        Rbf, Wrb, Scath);
    }
}
static void run_gemm(const __half* A, const __half* Bt, float* C, int M, int N, int K, int flags,
                     __half* Ct = nullptr,
                     const float* Ad1 = nullptr, float c1 = 1.f,
                     const float* Ad2 = nullptr, float c2 = 1.f,
                     const int* isx = nullptr, const int* itx = nullptr,
                     const __half* Rbf = nullptr, const __half* Wrb = nullptr,
                     __half* Scath = nullptr)
{
    run_gemm_impl(N <= 64, A, Bt, C, M, N, K, flags, Ct, Ad1, c1, Ad2, c2,
                  isx, itx, Rbf, Wrb, Scath);
}
static void run_conv(const float* src, __half* dst, size_t n) {
    const int n4 = (int)(n / 4);
    conv_half_kernel<<<(n4 + 255) / 256, 256>>>(src, dst, n4);
}
static void run_transpose(const float* src, __half* dst, int K, int N) {
    dim3 grid((N + 31) / 32, (K + 31) / 32);
    transpose_half_kernel<<<grid, dim3(32, 8)>>>(src, dst, K, N);
}

extern "C" void kernel_launch(void* const* d_in, const int* in_sizes, int n_in,
                              void* d_out, int out_size)
{
    const float* h_in    = (const float*)d_in[0];
    const float* m_in    = (const float*)d_in[1];
    const float* rbf3    = (const float*)d_in[2];
    const float* rbf_w1  = (const float*)d_in[3];
    const float* sph     = (const float*)d_in[4];
    const float* rbf_h   = (const float*)d_in[5];
    const int*   id3_ba  = (const int*)d_in[6];
    const int*   id_swap = (const int*)d_in[9];
    const int*   idx_s   = (const int*)d_in[10];
    const int*   idx_t   = (const int*)d_in[11];
    const float* W_dense_ca = (const float*)d_in[12];
    const float* W_ba    = (const float*)d_in[13];
    const float* W_rbf3  = (const float*)d_in[14];
    const float* W_down  = (const float*)d_in[15];
    const float* W_bil   = (const float*)d_in[16];
    const float* W_up_ca = (const float*)d_in[17];
    const float* W_up_ac = (const float*)d_in[18];
    const float* W_bs    = (const float*)d_in[19];
    const float* W_as    = (const float*)d_in[20];
    const float* W_au_rbf= (const float*)d_in[21];
    const float* W_au_d1 = (const float*)d_in[22];
    const float* W_au_res= (const float*)d_in[23];
    const float* W_cat   = (const float*)d_in[24];
    const float* W_res_m = (const float*)d_in[25];

    float* pool = nullptr;
    cudaGetSymbolAddress((void**)&pool, g_pool);
    float*  XCA  = pool + OFF_XCA;
    float*  Mb   = pool + OFF_MB;
    float*  A1   = pool + OFF_A1;
    float*  A2   = pool + OFF_A2;
    float*  HS   = pool + OFF_TMP;               // [5000][512] fp32 (TMP fp32 region, free)
    float*  HT   = pool + OFF_UP;                // [5000][512] fp32 (UP fp32 region, free)
    __half* Mh   = (__half*)(pool + OFF_MH);
    __half* TMPh = (__half*)(pool + OFF_TMPH);
    __half* XCAh = (__half*)(pool + OFF_XCAH);
    __half* Mbh  = (__half*)(pool + OFF_MBH);
    __half* DWNh = (__half*)(pool + OFF_DWNH);
    __half* XBh  = (__half*)(pool + OFF_XBH);
    __half* T2h  = (__half*)(pool + OFF_T2H);
    __half* R3h  = (__half*)(pool + OFF_R3H);
    __half* RHh  = (__half*)(pool + OFF_RHH);
    __half* A1h  = (__half*)(pool + OFF_A1H);
    __half* A2h  = (__half*)(pool + OFF_A2H);
    __half* A3h  = (__half*)(pool + OFF_A3H);
    __half* OHh  = (__half*)(pool + OFF_OHH);
    __half* WH   = (__half*)(pool + OFF_WTSH);

    const size_t W2 = (size_t)DDg * DDg;
    __half* Wh_dense_ca = WH;            size_t woff = W2;
    __half* Wh_ba       = WH + woff;     woff += W2;
    __half* Wh_rbf3     = WH + woff;     woff += (size_t)DDg * 16;
    __half* Wh_down     = WH + woff;     woff += (size_t)DTg * DDg;
    __half* Wh_up_ca    = WH + woff;     woff += (size_t)DDg * DTg;
    __half* Wh_up_ac    = WH + woff;     woff += (size_t)DDg * DTg;
    __half* Wh_bs       = WH + woff;     woff += 2 * W2;
    __half* Wh_as       = WH + woff;     woff += 4 * W2;
    __half* Wh_au_rbf   = WH + woff;     woff += (size_t)DDg * 16;
    __half* Wh_au_d1    = WH + woff;     woff += W2;
    __half* Wh_au_res   = WH + woff;     woff += 6 * W2;
    __half* Wh_cat1     = WH + woff;     woff += W2;
    __half* Wh_cat2     = WH + woff;     woff += W2;
    __half* Wh_cat3     = WH + woff;     woff += W2;
    __half* Wh_res_m    = WH + woff;     woff += 2 * W2;
    __half* WBPh        = WH + woff;     woff += (size_t)DTg * 1024;

    float* OUT_H = (float*)d_out;
    float* OUT_M = (float*)d_out + NA512;

    const float C = INV_SQRT2;

    // ---- pre-conversions ----
    run_conv(m_in, Mh, NE512);
    run_conv(rbf3, R3h, NE16);
    run_conv(rbf_h, RHh, NE16);
    {
        TPtrs tp{};
        int n = 0;
        tp.src[n] = W_dense_ca; tp.dst[n] = Wh_dense_ca; n++;
        tp.src[n] = W_ba;       tp.dst[n] = Wh_ba;       n++;
        tp.src[n] = W_au_d1;    tp.dst[n] = Wh_au_d1;    n++;
        for (int i = 0; i < 2; i++) { tp.src[n] = W_bs + i * W2;     tp.dst[n] = Wh_bs + i * W2;     n++; }
        for (int i = 0; i < 4; i++) { tp.src[n] = W_as + i * W2;     tp.dst[n] = Wh_as + i * W2;     n++; }
        for (int i = 0; i < 6; i++) { tp.src[n] = W_au_res + i * W2; tp.dst[n] = Wh_au_res + i * W2; n++; }
        tp.src[n] = W_cat;      tp.dst[n] = Wh_cat1;     n++;   // n=16
        transpose512_batch_kernel<<<dim3(16, 16, n), dim3(32, 8)>>>(tp);
    }
    {
        TPtrs tp{};
        tp.src[0] = W_cat + W2;      tp.dst[0] = Wh_cat2;
        tp.src[1] = W_cat + 2 * W2;  tp.dst[1] = Wh_cat3;
        tp.src[2] = W_res_m;         tp.dst[2] = Wh_res_m;
        tp.src[3] = W_res_m + W2;    tp.dst[3] = Wh_res_m + W2;
        transpose512_batch_kernel<<<dim3(16, 16, 4), dim3(32, 8)>>>(tp);
    }
    run_transpose(W_rbf3, Wh_rbf3, 16, DDg);
    run_transpose(W_down, Wh_down, DDg, DTg);
    run_transpose(W_up_ca, Wh_up_ca, DTg, DDg);
    run_transpose(W_up_ac, Wh_up_ac, DTg, DDg);
    run_transpose(W_au_rbf, Wh_au_rbf, 16, DDg);
    permute_wbil_kernel<<<(NCBF * DTg * DTg) / 256, 256>>>(W_bil, WBPh);

    // ---- pipeline ----
    run_gemm(Mh, Wh_ba, nullptr, NEg, DDg, DDg, F_ACT | F_RBFMUL | F_HALF | F_NOF32,
             TMPh, nullptr, 1.f, nullptr, 1.f, nullptr, nullptr,
             R3h, Wh_rbf3, nullptr);
    run_gemm(TMPh, Wh_down, nullptr, NEg, DTg, DDg, F_ACT | F_HALF | F_NOF32, DWNh);
    run_gemm(Mh, Wh_dense_ca, XCA, NEg, DDg, DDg, F_ACT);

    triplet_tmp2_kernel<<<NEg / 16, 256>>>(DWNh, id3_ba, sph, rbf_w1, T2h);
    run_gemm(T2h, WBPh, nullptr, NEg, DTg, NCBF * DTg, F_HALF | F_NOF32, XBh);

    // merged up projection (N=1024), half output into T2h (dead after bilinear)
    run_gemm(XBh, Wh_up_ca, nullptr, NEg, 1024, DTg, F_ACT | F_HALF | F_NOF32, T2h);
    combine_x_kernel<<<(NEg * 128) / 256, 256>>>(XCA, XCAh, T2h, id_swap);

    run_gemm(XCAh, Wh_bs, nullptr, NEg, DDg, DDg, F_ACT | F_HALF | F_NOF32, TMPh);
    run_gemm(TMPh, Wh_bs + W2, Mb, NEg, DDg, DDg, F_ACT | F_ADD1 | F_ADD2 | F_HALF,
             Mbh, XCA, C, m_in, C);

    run_gemm(Mbh, Wh_as + 0 * W2, nullptr, NEg, DDg, DDg, F_ACT | F_HALF | F_NOF32, TMPh);
    run_gemm(TMPh, Wh_as + 1 * W2, Mb, NEg, DDg, DDg, F_ACT | F_ADD1 | F_HALF,
             Mbh, Mb, C);
    run_gemm(Mbh, Wh_as + 2 * W2, nullptr, NEg, DDg, DDg, F_ACT | F_HALF | F_NOF32, TMPh);
    run_gemm(TMPh, Wh_as + 3 * W2, Mb, NEg, DDg, DDg, F_ACT | F_ADD1 | F_HALF | F_SCATH,
             Mbh, Mb, C, nullptr, 1.f, nullptr, nullptr,
             RHh, Wh_au_rbf, XCAh);

    cudaMemsetAsync(A1, 0, NA512 * sizeof(float));
    scatter_atoms_kernel<<<(NEg * 128) / 256, 256>>>(XCAh, idx_t, A1);
    run_conv(A1, A1h, NA512);
    run_gemm(A1h, Wh_au_d1, A2, NAg, DDg, DDg, F_ACT | F_HALF, A2h);
    run_gemm(A2h, Wh_au_res + 0 * W2, nullptr, NAg, DDg, DDg, F_ACT | F_HALF | F_NOF32, A3h);
    run_gemm(A3h, Wh_au_res + 1 * W2, A2, NAg, DDg, DDg, F_ACT | F_ADD1 | F_HALF,
             A2h, A2, C);
    run_gemm(A2h, Wh_au_res + 2 * W2, nullptr, NAg, DDg, DDg, F_ACT | F_HALF | F_NOF32, A3h);
    run_gemm(A3h, Wh_au_res + 3 * W2, A2, NAg, DDg, DDg, F_ACT | F_ADD1 | F_HALF,
             A2h, A2, C);
    run_gemm(A2h, Wh_au_res + 4 * W2, nullptr, NAg, DDg, DDg, F_ACT | F_HALF | F_NOF32, A3h);
    run_gemm(A3h, Wh_au_res + 5 * W2, OUT_H, NAg, DDg, DDg,
             F_ACT | F_ADD1 | F_ADD2 | F_HALF, OHh, A2, C, h_in, C);

    // EdgeEmbedding via decomposition: HS = h@W1, HT = h@W2 (atom-sized), then
    // m-part edge GEMM with gather-add epilogue.
    run_gemm(OHh, Wh_cat1, HS, NAg, DDg, DDg, 0);
    run_gemm(OHh, Wh_cat2, HT, NAg, DDg, DDg, 0);
    run_gemm(Mbh, Wh_cat3, XCA, NEg, DDg, DDg, F_ACT | F_GATH | F_HALF,
             XCAh, HS, 1.f, HT, 1.f, idx_s, idx_t);

    run_gemm(XCAh, Wh_res_m, nullptr, NEg, DDg, DDg, F_ACT | F_HALF | F_NOF32, TMPh);
    run_gemm(TMPh, Wh_res_m + W2, OUT_M, NEg, DDg, DDg, F_ACT | F_ADD1 | F_ADD2,
             nullptr, XCA, C, Mb, C);

    (void)in_sizes; (void)n_in; (void)out_size;
}

// round 16
// speedup vs baseline: 1.1221x; 1.0159x over previous
#include <cuda_runtime.h>
#include <cuda_fp16.h>
#include <cstdint>

// ---------------- problem constants ----------------
constexpr int NEg   = 100000;
constexpr int NAg   = 5000;
constexpr int DDg   = 512;
constexpr int DTg   = 64;
constexpr int NCBF  = 16;

constexpr float INV_SQRT2 = 0.70710678118654752f;
constexpr float ACT_SCALE = 1.0f / 0.6f;

// ---------------- scratch pool (float units) ----------------
constexpr size_t NE512  = (size_t)NEg * DDg;
constexpr size_t NE64   = (size_t)NEg * DTg;
constexpr size_t NE1024 = (size_t)NEg * 1024;
constexpr size_t NE16   = (size_t)NEg * 16;
constexpr size_t NA512  = (size_t)NAg * DDg;

constexpr size_t OFF_XCA  = 0;
constexpr size_t OFF_TMP  = OFF_XCA + NE512;          // also hosts HST [5000][1024]
constexpr size_t OFF_UP   = OFF_TMP + NE512;
constexpr size_t OFF_MB   = OFF_UP  + NE512;
constexpr size_t OFF_A1   = OFF_MB  + NE512;
constexpr size_t OFF_A2   = OFF_A1  + NA512;
constexpr size_t OFF_MH   = OFF_A2   + NA512;
constexpr size_t OFF_TMPH = OFF_MH   + NE512 / 2;
constexpr size_t OFF_XCAH = OFF_TMPH + NE512 / 2;
constexpr size_t OFF_MBH  = OFF_XCAH + NE512 / 2;
constexpr size_t OFF_DWNH = OFF_MBH  + NE512 / 2;
constexpr size_t OFF_XBH  = OFF_DWNH + NE64 / 2;
constexpr size_t OFF_T2H  = OFF_XBH  + NE64 / 2;
constexpr size_t OFF_R3H  = OFF_T2H  + NE1024 / 2;
constexpr size_t OFF_RHH  = OFF_R3H  + NE16 / 2;
constexpr size_t OFF_A1H  = OFF_RHH  + NE16 / 2;
constexpr size_t OFF_A2H  = OFF_A1H  + NA512 / 2;
constexpr size_t OFF_A3H  = OFF_A2H  + NA512 / 2;
constexpr size_t OFF_OHH  = OFF_A3H  + NA512 / 2;
constexpr size_t OFF_WTSH = OFF_OHH  + NA512 / 2;
constexpr size_t WTSH_FLOATS = 3u * 1024 * 1024;
constexpr size_t OFF_CSR  = OFF_WTSH + WTSH_FLOATS;   // ints region
constexpr size_t CSR_FLOATS = 120000;                 // cnt/off/wof (3*5008) + elist(100000)
constexpr size_t POOL_TOTAL = OFF_CSR + CSR_FLOATS;

__device__ __align__(256) float g_pool[POOL_TOTAL];

// ---------------- helpers ----------------
__device__ __forceinline__ float scaled_silu(float x) {
    return x * (1.0f / (1.0f + __expf(-x))) * ACT_SCALE;
}
__device__ __forceinline__ void mma_f16(float4& d, const uint32_t a[4], const uint32_t b[2]) {
    asm volatile(
        "mma.sync.aligned.m16n8k16.row.col.f32.f16.f16.f32 "
        "{%0,%1,%2,%3}, {%4,%5,%6,%7}, {%8,%9}, {%0,%1,%2,%3};"
        : "+f"(d.x), "+f"(d.y), "+f"(d.z), "+f"(d.w)
        : "r"(a[0]), "r"(a[1]), "r"(a[2]), "r"(a[3]), "r"(b[0]), "r"(b[1]));
}
__device__ __forceinline__ void ldsm_x4(uint32_t& r0, uint32_t& r1, uint32_t& r2, uint32_t& r3,
                                        uint32_t addr) {
    asm volatile("ldmatrix.sync.aligned.m8n8.x4.shared.b16 {%0,%1,%2,%3}, [%4];"
                 : "=r"(r0), "=r"(r1), "=r"(r2), "=r"(r3) : "r"(addr));
}
__device__ __forceinline__ void cp16(uint32_t smem_dst, const void* gsrc, int szbytes) {
    asm volatile("cp.async.cg.shared.global [%0], [%1], 16, %2;"
                 :: "r"(smem_dst), "l"(gsrc), "r"(szbytes));
}
__device__ __forceinline__ void cp_commit() { asm volatile("cp.async.commit_group;"); }
template <int N> __device__ __forceinline__ void cp_wait() {
    asm volatile("cp.async.wait_group %0;" :: "n"(N));
}

// ---------------- fp16 tensor-core GEMM ----------------
enum { F_ACT = 1, F_MUL = 2, F_ADD1 = 4, F_ADD2 = 8, F_HALF = 32, F_NOF32 = 64,
       F_RBFMUL = 128, F_SCATH = 256, F_GATH = 512 };

constexpr int SAK = 40;
constexpr int NSTAGE = 4;
constexpr int AS_BYTES = 128 * SAK * 2;
constexpr int STAGE_BYTES = 2 * AS_BYTES;
constexpr int SMEM_DYN = NSTAGE * STAGE_BYTES;        // 81920

constexpr int RBS = 24;
constexpr int RB_BYTES = 128 * RBS * 2;
constexpr int RB_B_OFF = RB_BYTES;

__device__ __forceinline__ void epi2(float* C, __half* Ct, __half* Sc, size_t idx,
                                     float vx, float vy, float mx, float my,
                                     int flags, const float* Add1, float c1,
                                     const float* Add2, float c2) {
    if (flags & F_ACT)    { vx = scaled_silu(vx);       vy = scaled_silu(vy); }
    if (flags & F_RBFMUL) { vx *= mx;                   vy *= my; }
    if (flags & F_ADD1)   { vx = (Add1[idx] + vx) * c1; vy = (Add1[idx + 1] + vy) * c1; }
    if (flags & F_ADD2)   { vx = (vx + Add2[idx]) * c2; vy = (vy + Add2[idx + 1]) * c2; }
    if (flags & F_SCATH)  *(__half2*)(Sc + idx) = __floats2half2_rn(vx * mx, vy * my);
    if (flags & F_HALF)   *(__half2*)(Ct + idx) = __floats2half2_rn(vx, vy);
    if (!(flags & F_NOF32)) { C[idx] = vx; C[idx + 1] = vy; }
}

// NARROW=false: 128x128 tile, warp 64x32 (MT=4). NARROW=true: 128x64 tile, warp 32x32 (MT=2).
template <bool NARROW>
__global__ __launch_bounds__(256, 2)
void mma_gemm_kernel(const __half* __restrict__ A, const __half* __restrict__ Bt,
                     float* __restrict__ C, __half* __restrict__ Ct,
                     int M, int N, int K, int flags,
                     const float* __restrict__ Add1, float c1,
                     const float* __restrict__ Add2, float c2,
                     const int* __restrict__ idxs, const int* __restrict__ idxt,
                     const __half* __restrict__ Rbf, const __half* __restrict__ Wrb,
                     __half* __restrict__ Scath)
{
    extern __shared__ __align__(16) char dyn_smem[];

    constexpr int MT = NARROW ? 2 : 4;

    const int t = threadIdx.x;
    const int lane = t & 31;
    const int warp = t >> 5;
    const int wm = NARROW ? (warp >> 1) * 32 : (warp >> 2) * 64;
    const int wn = NARROW ? (warp & 1) * 32 : (warp & 3) * 32;
    const int rowC0 = blockIdx.y * 128;
    const int colC0 = blockIdx.x * (NARROW ? 64 : 128);

    const uint32_t smem0 = (uint32_t)__cvta_generic_to_shared(dyn_smem);

    const int arow_l = t & 127;
    const int ako = (t >> 7) * 16;
    const int arow = rowC0 + arow_l;
    const bool aok = arow < M;
    const uint32_t a_dst = smem0 + (uint32_t)(arow_l * SAK + ako) * 2;

    const int brow_l = t & 127;
    const bool bok = !NARROW ? ((colC0 + brow_l) < N) : (brow_l < 64 && (colC0 + brow_l) < N);
    const __half* brp = Bt + (size_t)(bok ? (colC0 + brow_l) : 0) * K;
    const uint32_t b_dst = smem0 + AS_BYTES + (uint32_t)(brow_l * SAK + ako) * 2;

    const int a_row_lm = wm + (lane & 15);
    const int a_kh_lm  = (lane >> 4) * 8;
    const int b_row_lm = wn + (lane & 7) + (lane >> 4) * 8;
    const int b_kh_lm  = ((lane >> 3) & 1) * 8;

    float4 acc[MT][4];
#pragma unroll
    for (int i = 0; i < MT; i++)
#pragma unroll
        for (int j = 0; j < 4; j++) acc[i][j] = make_float4(0.f, 0.f, 0.f, 0.f);

    auto loadTile = [&](int s, int k0) {
        const uint32_t soff = (uint32_t)s * STAGE_BYTES;
        const __half* ap = A + (size_t)(aok ? arow : 0) * K + k0 + ako;
#pragma unroll
        for (int ch = 0; ch < 2; ch++) {
            const bool ok = aok && (k0 + ako + ch * 8) < K;
            cp16(a_dst + soff + 16u * ch, ok ? (const void*)(ap + 8 * ch) : (const void*)A,
                 ok ? 16 : 0);
        }
        const __half* bp = brp + k0 + ako;
#pragma unroll
        for (int ch = 0; ch < 2; ch++) {
            const bool ok = bok && (k0 + ako + ch * 8) < K;
            cp16(b_dst + soff + 16u * ch, ok ? (const void*)(bp + 8 * ch) : (const void*)Bt,
                 ok ? 16 : 0);
        }
    };

    auto computeTile = [&](int s) {
        const uint32_t abase = smem0 + (uint32_t)s * STAGE_BYTES;
        const uint32_t bbase = abase + AS_BYTES;
#pragma unroll
        for (int g = 0; g < 2; g++) {
            uint32_t af[MT][4];
            uint32_t bf[4][2];
#pragma unroll
            for (int mt = 0; mt < MT; mt++)
                ldsm_x4(af[mt][0], af[mt][1], af[mt][2], af[mt][3],
                        abase + (uint32_t)((a_row_lm + mt * 16) * SAK + g * 16 + a_kh_lm) * 2);
#pragma unroll
            for (int p = 0; p < 2; p++)
                ldsm_x4(bf[2 * p][0], bf[2 * p][1], bf[2 * p + 1][0], bf[2 * p + 1][1],
                        bbase + (uint32_t)((b_row_lm + p * 16) * SAK + g * 16 + b_kh_lm) * 2);
#pragma unroll
            for (int mt = 0; mt < MT; mt++)
#pragma unroll
                for (int nt = 0; nt < 4; nt++)
                    mma_f16(acc[mt][nt], af[mt], bf[nt]);
        }
    };

    const int nK = (K + 31) >> 5;
    const int pre = nK < (NSTAGE - 1) ? nK : (NSTAGE - 1);
    for (int s = 0; s < pre; s++) { loadTile(s, s * 32); cp_commit(); }

    for (int i = 0; i < nK; ++i) {
        const int rem = nK - 1 - i;
        if (rem >= 2)      cp_wait<2>();
        else if (rem == 1) cp_wait<1>();
        else               cp_wait<0>();
        __syncthreads();
        if (i + NSTAGE - 1 < nK) { loadTile((i + NSTAGE - 1) & 3, (i + NSTAGE - 1) * 32); cp_commit(); }
        computeTile(i & 3);
    }

    // ---- optional rbf-multiplier epilogue tiles (K=16 MMA) ----
    const bool use_rbf = (flags & (F_RBFMUL | F_SCATH)) != 0;
    uint32_t bfr[4][2];
    if (use_rbf) {
        __syncthreads();
        {
            const int r = t & 127;
            const int off = (t >> 7) * 8;
            const int gr = rowC0 + r;
            uint4 av = make_uint4(0, 0, 0, 0);
            if (gr < M) av = *(const uint4*)(Rbf + (size_t)gr * 16 + off);
            *(uint4*)(dyn_smem + ((size_t)r * RBS + off) * 2) = av;
            const int gc = colC0 + r;
            uint4 bv = make_uint4(0, 0, 0, 0);
            if (gc < N) bv = *(const uint4*)(Wrb + (size_t)gc * 16 + off);
            *(uint4*)(dyn_smem + RB_B_OFF + ((size_t)r * RBS + off) * 2) = bv;
        }
        __syncthreads();
        const uint32_t bb = smem0 + RB_B_OFF;
#pragma unroll
        for (int p = 0; p < 2; p++)
            ldsm_x4(bfr[2 * p][0], bfr[2 * p][1], bfr[2 * p + 1][0], bfr[2 * p + 1][1],
                    bb + (uint32_t)((b_row_lm + p * 16) * RBS + b_kh_lm) * 2);
    }

    // epilogue
#pragma unroll
    for (int mt = 0; mt < MT; mt++) {
        float4 mul[4];
        if (use_rbf) {
            uint32_t afr[4];
            ldsm_x4(afr[0], afr[1], afr[2], afr[3],
                    smem0 + (uint32_t)((a_row_lm + mt * 16) * RBS + a_kh_lm) * 2);
#pragma unroll
            for (int nt = 0; nt < 4; nt++) {
                mul[nt] = make_float4(0.f, 0.f, 0.f, 0.f);
                mma_f16(mul[nt], afr, bfr[nt]);
            }
        } else {
#pragma unroll
            for (int nt = 0; nt < 4; nt++) mul[nt] = make_float4(1.f, 1.f, 1.f, 1.f);
        }
        const int r = rowC0 + wm + mt * 16 + (lane >> 2);
        // F_GATH: per-row gather bases into HST table (stride 1024: [*,0:512]=HS, [*,512:1024]=HT)
        const float* g0a = nullptr; const float* g0b = nullptr;
        const float* g1a = nullptr; const float* g1b = nullptr;
        if (flags & F_GATH) {
            if (r < M)     { g0a = Add1 + (size_t)idxs[r] * 1024;     g0b = Add2 + (size_t)idxt[r] * 1024; }
            if (r + 8 < M) { g1a = Add1 + (size_t)idxs[r + 8] * 1024; g1b = Add2 + (size_t)idxt[r + 8] * 1024; }
        }
#pragma unroll
        for (int nt = 0; nt < 4; nt++) {
            const int cc = colC0 + wn + nt * 8 + (lane & 3) * 2;
            if (cc >= N) continue;
            float4 v = acc[mt][nt];
            const float4 mv = mul[nt];
            if (flags & F_GATH) {
                if (g0a) { v.x += g0a[cc] + g0b[cc]; v.y += g0a[cc + 1] + g0b[cc + 1]; }
                if (g1a) { v.z += g1a[cc] + g1b[cc]; v.w += g1a[cc + 1] + g1b[cc + 1]; }
            }
            if (r < M)
                epi2(C, Ct, Scath, (size_t)r * N + cc, v.x, v.y, mv.x, mv.y,
                     (flags & F_GATH) ? (flags & ~(F_ADD1 | F_ADD2)) : flags, Add1, c1, Add2, c2);
            if (r + 8 < M)
                epi2(C, Ct, Scath, (size_t)(r + 8) * N + cc, v.z, v.w, mv.z, mv.w,
                     (flags & F_GATH) ? (flags & ~(F_ADD1 | F_ADD2)) : flags, Add1, c1, Add2, c2);
        }
    }
}

// ---------------- fp32 -> fp16 conversion ----------------
__global__ void conv_half_kernel(const float* __restrict__ src, __half* __restrict__ dst, int n4) {
    const int i = blockIdx.x * blockDim.x + threadIdx.x;
    if (i >= n4) return;
    float4 v = ((const float4*)src)[i];
    __half2* d = (__half2*)dst + 2 * i;
    d[0] = __floats2half2_rn(v.x, v.y);
    d[1] = __floats2half2_rn(v.z, v.w);
}

// ---------------- batched 512x512 transpose ----------------
struct TPtrs { const float* src[16]; __half* dst[16]; };

__global__ void transpose512_batch_kernel(TPtrs p) {
    __shared__ float tile[32][33];
    const float* src = p.src[blockIdx.z];
    __half* dst = p.dst[blockIdx.z];
    const int kb = blockIdx.y * 32, nb = blockIdx.x * 32;
    const int tx = threadIdx.x, ty = threadIdx.y;
#pragma unroll
    for (int dy = 0; dy < 32; dy += 8)
        tile[ty + dy][tx] = src[(size_t)(kb + ty + dy) * 512 + nb + tx];
    __syncthreads();
#pragma unroll
    for (int dy = 0; dy < 32; dy += 8)
        dst[(size_t)(nb + ty + dy) * 512 + kb + tx] = __float2half_rn(tile[tx][ty + dy]);
}

__global__ void transpose_half_kernel(const float* __restrict__ src, __half* __restrict__ dst,
                                      int K, int N) {
    __shared__ float tile[32][33];
    const int kb = blockIdx.y * 32, nb = blockIdx.x * 32;
    const int tx = threadIdx.x, ty = threadIdx.y;
#pragma unroll
    for (int dy = 0; dy < 32; dy += 8) {
        const int k = kb + ty + dy, n = nb + tx;
        if (k < K && n < N) tile[ty + dy][tx] = src[(size_t)k * N + n];
    }
    __syncthreads();
#pragma unroll
    for (int dy = 0; dy < 32; dy += 8) {
        const int n = nb + ty + dy, k = kb + tx;
        if (n < N && k < K) dst[(size_t)n * K + k] = __float2half_rn(tile[tx][ty + dy]);
    }
}

// ---------------- triplet tmp2 ----------------
__global__ void triplet_tmp2_kernel(const __half* __restrict__ down,
                                    const int* __restrict__ id3_ba,
                                    const float* __restrict__ sph,
                                    const float* __restrict__ rbfw1,
                                    __half* __restrict__ t2)
{
    __shared__ int   sIdx[256];
    __shared__ float sS[16 * 112];
    __shared__ float sR[16 * 112];

    const int tid = threadIdx.x;
    const int e0 = blockIdx.x * 16;

    sIdx[tid] = id3_ba[(size_t)e0 * 16 + tid];
    for (int r = tid; r < 16 * 112; r += 256) {
        sS[r] = sph  [(size_t)e0 * 112 + r];
        sR[r] = rbfw1[(size_t)e0 * 112 + r];
    }
    __syncthreads();

    const int team = tid >> 4;
    const int j = tid & 15;
    const int edge = e0 + team;

    float4 G[16];
#pragma unroll
    for (int k = 0; k < 16; k++) {
        const int row = sIdx[team * 16 + k];
        const __half2* dp = (const __half2*)(down + (size_t)row * 64 + j * 4);
        float2 lo = __half22float2(dp[0]);
        float2 hi = __half22float2(dp[1]);
        G[k] = make_float4(lo.x, lo.y, hi.x, hi.y);
    }

    float4 t1[7];
#pragma unroll
    for (int s = 0; s < 7; s++) {
        float4 a = make_float4(0.f, 0.f, 0.f, 0.f);
#pragma unroll
        for (int k = 0; k < 16; k++) {
            const float f = sS[team * 112 + s * 16 + k];
            a.x = fmaf(f, G[k].x, a.x); a.y = fmaf(f, G[k].y, a.y);
            a.z = fmaf(f, G[k].z, a.z); a.w = fmaf(f, G[k].w, a.w);
        }
        t1[s] = a;
    }

#pragma unroll
    for (int i = 0; i < 16; i++) {
        float4 a = make_float4(0.f, 0.f, 0.f, 0.f);
#pragma unroll
        for (int s = 0; s < 7; s++) {
            const float f = sR[team * 112 + i * 7 + s];
            a.x = fmaf(f, t1[s].x, a.x); a.y = fmaf(f, t1[s].y, a.y);
            a.z = fmaf(f, t1[s].z, a.z); a.w = fmaf(f, t1[s].w, a.w);
        }
        __half2* out = (__half2*)(t2 + (size_t)edge * 1024 + i * 64 + j * 4);
        out[0] = __floats2half2_rn(a.x, a.y);
        out[1] = __floats2half2_rn(a.z, a.w);
    }
}

// W_bil[e,i,o] -> WBPh[o][i*64+e]
__global__ void permute_wbil_kernel(const float* __restrict__ wb, __half* __restrict__ out) {
    const int idx = blockIdx.x * blockDim.x + threadIdx.x;
    const int o = idx & 63;
    const int i = (idx >> 6) & 15;
    const int e = idx >> 10;
    out[(size_t)o * 1024 + i * 64 + e] = __float2half_rn(wb[((size_t)(e * 16 + i)) * 64 + o]);
}

// x = (xca_skip + (up2h[:,0:512] + up2h[id_swap,512:1024])*c)*c
__global__ void combine_x_kernel(float* xca, __half* xcah, const __half* __restrict__ up2h,
                                 const int* __restrict__ id_swap) {
    const int idx = blockIdx.x * blockDim.x + threadIdx.x;
    const int e = idx >> 7;
    const int c = idx & 127;
    const int es = id_swap[e];
    const __half2* ap = (const __half2*)(up2h + (size_t)e * 1024 + c * 4);
    const __half2* bp = (const __half2*)(up2h + (size_t)es * 1024 + 512 + c * 4);
    float2 a0 = __half22float2(ap[0]), a1 = __half22float2(ap[1]);
    float2 b0 = __half22float2(bp[0]), b1 = __half22float2(bp[1]);
    float4 x = ((float4*)xca)[idx];
    x.x = (x.x + (a0.x + b0.x) * INV_SQRT2) * INV_SQRT2;
    x.y = (x.y + (a0.y + b0.y) * INV_SQRT2) * INV_SQRT2;
    x.z = (x.z + (a1.x + b1.x) * INV_SQRT2) * INV_SQRT2;
    x.w = (x.w + (a1.y + b1.y) * INV_SQRT2) * INV_SQRT2;
    ((float4*)xca)[idx] = x;
    __half2* xh = (__half2*)xcah + 2 * idx;
    xh[0] = __floats2half2_rn(x.x, x.y);
    xh[1] = __floats2half2_rn(x.z, x.w);
}

// ---------------- CSR build + gather segment-sum ----------------
__global__ void csr_count_kernel(const int* __restrict__ idx_t, int* __restrict__ cnt) {
    const int e = blockIdx.x * blockDim.x + threadIdx.x;
    if (e < NEg) atomicAdd(&cnt[idx_t[e]], 1);
}

// single-block exclusive scan over NAg counters (1024 threads, chunk 5)
__global__ void csr_scan_kernel(const int* __restrict__ cnt, int* __restrict__ off) {
    __shared__ int s[1024];
    const int tid = threadIdx.x;
    const int base = tid * 5;
    int local[5];
    int sum = 0;
#pragma unroll
    for (int i = 0; i < 5; i++) {
        const int idx = base + i;
        const int v = (idx < NAg) ? cnt[idx] : 0;
        local[i] = sum;
        sum += v;
    }
    s[tid] = sum;
    __syncthreads();
    for (int d = 1; d < 1024; d <<= 1) {
        int v = (tid >= d) ? s[tid - d] : 0;
        __syncthreads();
        s[tid] += v;
        __syncthreads();
    }
    const int prev = (tid > 0) ? s[tid - 1] : 0;
#pragma unroll
    for (int i = 0; i < 5; i++) {
        const int idx = base + i;
        if (idx < NAg) off[idx] = prev + local[i];
    }
    if (tid == 1023) off[NAg] = s[1023];
}

__global__ void csr_fill_kernel(const int* __restrict__ idx_t, int* __restrict__ wof,
                                int* __restrict__ elist) {
    const int e = blockIdx.x * blockDim.x + threadIdx.x;
    if (e < NEg) {
        const int p = atomicAdd(&wof[idx_t[e]], 1);
        elist[p] = e;
    }
}

// gather: one atom per block; 128 thr x 4ch; a1h[a] = half(sum_e scath[e])
__global__ void gather_atoms_kernel(const __half* __restrict__ scath,
                                    const int* __restrict__ off,
                                    const int* __restrict__ elist,
                                    __half* __restrict__ a1h) {
    const int a = blockIdx.x;
    const int t = threadIdx.x;
    const int s = off[a], e = off[a + 1];
    float4 acc = make_float4(0.f, 0.f, 0.f, 0.f);
    for (int i = s; i < e; i++) {
        const int ed = elist[i];
        const __half2* p = (const __half2*)(scath + (size_t)ed * 512 + t * 4);
        float2 x0 = __half22float2(p[0]);
        float2 x1 = __half22float2(p[1]);
        acc.x += x0.x; acc.y += x0.y; acc.z += x1.x; acc.w += x1.y;
    }
    __half2* o = (__half2*)(a1h + (size_t)a * 512 + t * 4);
    o[0] = __floats2half2_rn(acc.x, acc.y);
    o[1] = __floats2half2_rn(acc.z, acc.w);
}

// ---------------- host orchestration ----------------
static void run_gemm_impl(bool narrow,
                          const __half* A, const __half* Bt, float* C, int M, int N, int K,
                          int flags, __half* Ct,
                          const float* Ad1, float c1, const float* Ad2, float c2,
                          const int* isx, const int* itx,
                          const __half* Rbf, const __half* Wrb, __half* Scath)
{
    static bool attr_set = false;
    if (!attr_set) {
        cudaFuncSetAttribute(mma_gemm_kernel<false>, cudaFuncAttributeMaxDynamicSharedMemorySize, SMEM_DYN);
        cudaFuncSetAttribute(mma_gemm_kernel<true>,  cudaFuncAttributeMaxDynamicSharedMemorySize, SMEM_DYN);
        attr_set = true;
    }
    if (narrow) {
        dim3 grid((N + 63) / 64, (M + 127) / 128);
        mma_gemm_kernel<true><<<grid, 256, SMEM_DYN>>>(A, Bt, C, Ct, M, N, K, flags,
                                                       Ad1, c1, Ad2, c2, isx, itx,
                                                       Rbf, Wrb, Scath);
    } else {
        dim3 grid((N + 127) / 128, (M + 127) / 128);
        mma_gemm_kernel<false><<<grid, 256, SMEM_DYN>>>(A, Bt, C, Ct, M, N, K, flags,
                                                        Ad1, c1, Ad2, c2, isx, itx,
                                                        Rbf, Wrb, Scath);
    }
}
static void run_gemm(const __half* A, const __half* Bt, float* C, int M, int N, int K, int flags,
                     __half* Ct = nullptr,
                     const float* Ad1 = nullptr, float c1 = 1.f,
                     const float* Ad2 = nullptr, float c2 = 1.f,
                     const int* isx = nullptr, const int* itx = nullptr,
                     const __half* Rbf = nullptr, const __half* Wrb = nullptr,
                     __half* Scath = nullptr)
{
    run_gemm_impl(N <= 64, A, Bt, C, M, N, K, flags, Ct, Ad1, c1, Ad2, c2,
                  isx, itx, Rbf, Wrb, Scath);
}
static void run_conv(const float* src, __half* dst, size_t n) {
    const int n4 = (int)(n / 4);
    conv_half_kernel<<<(n4 + 255) / 256, 256>>>(src, dst, n4);
}
static void run_transpose(const float* src, __half* dst, int K, int N) {
    dim3 grid((N + 31) / 32, (K + 31) / 32);
    transpose_half_kernel<<<grid, dim3(32, 8)>>>(src, dst, K, N);
}

extern "C" void kernel_launch(void* const* d_in, const int* in_sizes, int n_in,
                              void* d_out, int out_size)
{
    const float* h_in    = (const float*)d_in[0];
    const float* m_in    = (const float*)d_in[1];
    const float* rbf3    = (const float*)d_in[2];
    const float* rbf_w1  = (const float*)d_in[3];
    const float* sph     = (const float*)d_in[4];
    const float* rbf_h   = (const float*)d_in[5];
    const int*   id3_ba  = (const int*)d_in[6];
    const int*   id_swap = (const int*)d_in[9];
    const int*   idx_s   = (const int*)d_in[10];
    const int*   idx_t   = (const int*)d_in[11];
    const float* W_dense_ca = (const float*)d_in[12];
    const float* W_ba    = (const float*)d_in[13];
    const float* W_rbf3  = (const float*)d_in[14];
    const float* W_down  = (const float*)d_in[15];
    const float* W_bil   = (const float*)d_in[16];
    const float* W_up_ca = (const float*)d_in[17];
    const float* W_up_ac = (const float*)d_in[18];
    const float* W_bs    = (const float*)d_in[19];
    const float* W_as    = (const float*)d_in[20];
    const float* W_au_rbf= (const float*)d_in[21];
    const float* W_au_d1 = (const float*)d_in[22];
    const float* W_au_res= (const float*)d_in[23];
    const float* W_cat   = (const float*)d_in[24];
    const float* W_res_m = (const float*)d_in[25];

    float* pool = nullptr;
    cudaGetSymbolAddress((void**)&pool, g_pool);
    float*  XCA  = pool + OFF_XCA;
    float*  Mb   = pool + OFF_MB;
    float*  A2   = pool + OFF_A1;                 // reuse A1 region for A2 chain
    float*  HST  = pool + OFF_TMP;                // [5000][1024] fp32
    __half* Mh   = (__half*)(pool + OFF_MH);
    __half* TMPh = (__half*)(pool + OFF_TMPH);
    __half* XCAh = (__half*)(pool + OFF_XCAH);
    __half* Mbh  = (__half*)(pool + OFF_MBH);
    __half* DWNh = (__half*)(pool + OFF_DWNH);
    __half* XBh  = (__half*)(pool + OFF_XBH);
    __half* T2h  = (__half*)(pool + OFF_T2H);
    __half* R3h  = (__half*)(pool + OFF_R3H);
    __half* RHh  = (__half*)(pool + OFF_RHH);
    __half* A1h  = (__half*)(pool + OFF_A1H);
    __half* A2h  = (__half*)(pool + OFF_A2H);
    __half* A3h  = (__half*)(pool + OFF_A3H);
    __half* OHh  = (__half*)(pool + OFF_OHH);
    __half* WH   = (__half*)(pool + OFF_WTSH);
    int*    csr_cnt   = (int*)(pool + OFF_CSR);
    int*    csr_off   = csr_cnt + 5008;
    int*    csr_wof   = csr_off + 5008;
    int*    csr_elist = csr_wof + 5008;

    const size_t W2 = (size_t)DDg * DDg;
    __half* Wh_dense_ca = WH;            size_t woff = W2;
    __half* Wh_ba       = WH + woff;     woff += W2;
    __half* Wh_rbf3     = WH + woff;     woff += (size_t)DDg * 16;
    __half* Wh_down     = WH + woff;     woff += (size_t)DTg * DDg;
    __half* Wh_up_ca    = WH + woff;     woff += (size_t)DDg * DTg;
    __half* Wh_up_ac    = WH + woff;     woff += (size_t)DDg * DTg;
    __half* Wh_bs       = WH + woff;     woff += 2 * W2;
    __half* Wh_as       = WH + woff;     woff += 4 * W2;
    __half* Wh_au_rbf   = WH + woff;     woff += (size_t)DDg * 16;
    __half* Wh_au_d1    = WH + woff;     woff += W2;
    __half* Wh_au_res   = WH + woff;     woff += 6 * W2;
    __half* Wh_cat1     = WH + woff;     woff += W2;   // contiguous with cat2
    __half* Wh_cat2     = WH + woff;     woff += W2;
    __half* Wh_cat3     = WH + woff;     woff += W2;
    __half* Wh_res_m    = WH + woff;     woff += 2 * W2;
    __half* WBPh        = WH + woff;     woff += (size_t)DTg * 1024;

    float* OUT_H = (float*)d_out;
    float* OUT_M = (float*)d_out + NA512;

    const float C = INV_SQRT2;

    // ---- CSR build (depends only on idx_t) ----
    cudaMemsetAsync(csr_cnt, 0, 5008 * sizeof(int));
    csr_count_kernel<<<(NEg + 255) / 256, 256>>>(idx_t, csr_cnt);
    csr_scan_kernel<<<1, 1024>>>(csr_cnt, csr_off);
    cudaMemcpyAsync(csr_wof, csr_off, 5008 * sizeof(int), cudaMemcpyDeviceToDevice);
    csr_fill_kernel<<<(NEg + 255) / 256, 256>>>(idx_t, csr_wof, csr_elist);

    // ---- pre-conversions ----
    run_conv(m_in, Mh, NE512);
    run_conv(rbf3, R3h, NE16);
    run_conv(rbf_h, RHh, NE16);
    {
        TPtrs tp{};
        int n = 0;
        tp.src[n] = W_dense_ca; tp.dst[n] = Wh_dense_ca; n++;
        tp.src[n] = W_ba;       tp.dst[n] = Wh_ba;       n++;
        tp.src[n] = W_au_d1;    tp.dst[n] = Wh_au_d1;    n++;
        for (int i = 0; i < 2; i++) { tp.src[n] = W_bs + i * W2;     tp.dst[n] = Wh_bs + i * W2;     n++; }
        for (int i = 0; i < 4; i++) { tp.src[n] = W_as + i * W2;     tp.dst[n] = Wh_as + i * W2;     n++; }
        for (int i = 0; i < 6; i++) { tp.src[n] = W_au_res + i * W2; tp.dst[n] = Wh_au_res + i * W2; n++; }
        tp.src[n] = W_cat;      tp.dst[n] = Wh_cat1;     n++;   // n=16
        transpose512_batch_kernel<<<dim3(16, 16, n), dim3(32, 8)>>>(tp);
    }
    {
        TPtrs tp{};
        tp.src[0] = W_cat + W2;      tp.dst[0] = Wh_cat2;
        tp.src[1] = W_cat + 2 * W2;  tp.dst[1] = Wh_cat3;
        tp.src[2] = W_res_m;         tp.dst[2] = Wh_res_m;
        tp.src[3] = W_res_m + W2;    tp.dst[3] = Wh_res_m + W2;
        transpose512_batch_kernel<<<dim3(16, 16, 4), dim3(32, 8)>>>(tp);
    }
    run_transpose(W_rbf3, Wh_rbf3, 16, DDg);
    run_transpose(W_down, Wh_down, DDg, DTg);
    run_transpose(W_up_ca, Wh_up_ca, DTg, DDg);
    run_transpose(W_up_ac, Wh_up_ac, DTg, DDg);
    run_transpose(W_au_rbf, Wh_au_rbf, 16, DDg);
    permute_wbil_kernel<<<(NCBF * DTg * DTg) / 256, 256>>>(W_bil, WBPh);

    // ---- pipeline ----
    run_gemm(Mh, Wh_ba, nullptr, NEg, DDg, DDg, F_ACT | F_RBFMUL | F_HALF | F_NOF32,
             TMPh, nullptr, 1.f, nullptr, 1.f, nullptr, nullptr,
             R3h, Wh_rbf3, nullptr);
    run_gemm(TMPh, Wh_down, nullptr, NEg, DTg, DDg, F_ACT | F_HALF | F_NOF32, DWNh);
    run_gemm(Mh, Wh_dense_ca, XCA, NEg, DDg, DDg, F_ACT);

    triplet_tmp2_kernel<<<NEg / 16, 256>>>(DWNh, id3_ba, sph, rbf_w1, T2h);
    run_gemm(T2h, WBPh, nullptr, NEg, DTg, NCBF * DTg, F_HALF | F_NOF32, XBh);

    run_gemm(XBh, Wh_up_ca, nullptr, NEg, 1024, DTg, F_ACT | F_HALF | F_NOF32, T2h);
    combine_x_kernel<<<(NEg * 128) / 256, 256>>>(XCA, XCAh, T2h, id_swap);

    run_gemm(XCAh, Wh_bs, nullptr, NEg, DDg, DDg, F_ACT | F_HALF | F_NOF32, TMPh);
    run_gemm(TMPh, Wh_bs + W2, Mb, NEg, DDg, DDg, F_ACT | F_ADD1 | F_ADD2 | F_HALF,
             Mbh, XCA, C, m_in, C);

    run_gemm(Mbh, Wh_as + 0 * W2, nullptr, NEg, DDg, DDg, F_ACT | F_HALF | F_NOF32, TMPh);
    run_gemm(TMPh, Wh_as + 1 * W2, Mb, NEg, DDg, DDg, F_ACT | F_ADD1 | F_HALF,
             Mbh, Mb, C);
    run_gemm(Mbh, Wh_as + 2 * W2, nullptr, NEg, DDg, DDg, F_ACT | F_HALF | F_NOF32, TMPh);
    run_gemm(TMPh, Wh_as + 3 * W2, Mb, NEg, DDg, DDg, F_ACT | F_ADD1 | F_HALF | F_SCATH,
             Mbh, Mb, C, nullptr, 1.f, nullptr, nullptr,
             RHh, Wh_au_rbf, XCAh);

    // AtomUpdate: CSR gather replaces memset + 51M atomics + conv
    gather_atoms_kernel<<<NAg, 128>>>(XCAh, csr_off, csr_elist, A1h);
    run_gemm(A1h, Wh_au_d1, A2, NAg, DDg, DDg, F_ACT | F_HALF, A2h);
    run_gemm(A2h, Wh_au_res + 0 * W2, nullptr, NAg, DDg, DDg, F_ACT | F_HALF | F_NOF32, A3h);
    run_gemm(A3h, Wh_au_res + 1 * W2, A2, NAg, DDg, DDg, F_ACT | F_ADD1 | F_HALF,
             A2h, A2, C);
    run_gemm(A2h, Wh_au_res + 2 * W2, nullptr, NAg, DDg, DDg, F_ACT | F_HALF | F_NOF32, A3h);
    run_gemm(A3h, Wh_au_res + 3 * W2, A2, NAg, DDg, DDg, F_ACT | F_ADD1 | F_HALF,
             A2h, A2, C);
    run_gemm(A2h, Wh_au_res + 4 * W2, nullptr, NAg, DDg, DDg, F_ACT | F_HALF | F_NOF32, A3h);
    run_gemm(A3h, Wh_au_res + 5 * W2, OUT_H, NAg, DDg, DDg,
             F_ACT | F_ADD1 | F_ADD2 | F_HALF, OHh, A2, C, h_in, C);

    // EdgeEmbedding: merged HS/HT (N=1024) + m-part edge GEMM w/ gather-add
    run_gemm(OHh, Wh_cat1, HST, NAg, 1024, DDg, 0);
    run_gemm(Mbh, Wh_cat3, XCA, NEg, DDg, DDg, F_ACT | F_GATH | F_HALF,
             XCAh, HST, 1.f, HST + 512, 1.f, idx_s, idx_t);

    run_gemm(XCAh, Wh_res_m, nullptr, NEg, DDg, DDg, F_ACT | F_HALF | F_NOF32, TMPh);
    run_gemm(TMPh, Wh_res_m + W2, OUT_M, NEg, DDg, DDg, F_ACT | F_ADD1 | F_ADD2,
             nullptr, XCA, C, Mb, C);

    (void)in_sizes; (void)n_in; (void)out_size;
}

// round 17
// speedup vs baseline: 1.1253x; 1.0029x over previous
#include <cuda_runtime.h>
#include <cuda_fp16.h>
#include <cstdint>

// ---------------- problem constants ----------------
constexpr int NEg   = 100000;
constexpr int NAg   = 5000;
constexpr int DDg   = 512;
constexpr int DTg   = 64;
constexpr int NCBF  = 16;

constexpr float INV_SQRT2 = 0.70710678118654752f;
constexpr float ACT_SCALE = 1.0f / 0.6f;

// ---------------- scratch pool (float units) ----------------
constexpr size_t NE512  = (size_t)NEg * DDg;
constexpr size_t NE64   = (size_t)NEg * DTg;
constexpr size_t NE1024 = (size_t)NEg * 1024;
constexpr size_t NE16   = (size_t)NEg * 16;
constexpr size_t NA512  = (size_t)NAg * DDg;

constexpr size_t OFF_XCA  = 0;
constexpr size_t OFF_TMP  = OFF_XCA + NE512;          // also hosts HST [5000][1024]
constexpr size_t OFF_UP   = OFF_TMP + NE512;
constexpr size_t OFF_MB   = OFF_UP  + NE512;
constexpr size_t OFF_A1   = OFF_MB  + NE512;
constexpr size_t OFF_A2   = OFF_A1  + NA512;
constexpr size_t OFF_MH   = OFF_A2   + NA512;
constexpr size_t OFF_TMPH = OFF_MH   + NE512 / 2;
constexpr size_t OFF_XCAH = OFF_TMPH + NE512 / 2;
constexpr size_t OFF_MBH  = OFF_XCAH + NE512 / 2;
constexpr size_t OFF_DWNH = OFF_MBH  + NE512 / 2;
constexpr size_t OFF_XBH  = OFF_DWNH + NE64 / 2;
constexpr size_t OFF_T2H  = OFF_XBH  + NE64 / 2;
constexpr size_t OFF_R3H  = OFF_T2H  + NE1024 / 2;
constexpr size_t OFF_RHH  = OFF_R3H  + NE16 / 2;
constexpr size_t OFF_A1H  = OFF_RHH  + NE16 / 2;
constexpr size_t OFF_A2H  = OFF_A1H  + NA512 / 2;
constexpr size_t OFF_A3H  = OFF_A2H  + NA512 / 2;
constexpr size_t OFF_OHH  = OFF_A3H  + NA512 / 2;
constexpr size_t OFF_WTSH = OFF_OHH  + NA512 / 2;
constexpr size_t WTSH_FLOATS = 3u * 1024 * 1024;
constexpr size_t OFF_CSR  = OFF_WTSH + WTSH_FLOATS;
constexpr size_t CSR_FLOATS = 120000;
constexpr size_t POOL_TOTAL = OFF_CSR + CSR_FLOATS;

__device__ __align__(256) float g_pool[POOL_TOTAL];

// ---------------- helpers ----------------
__device__ __forceinline__ float scaled_silu(float x) {
    return x * (1.0f / (1.0f + __expf(-x))) * ACT_SCALE;
}
__device__ __forceinline__ void mma_f16(float4& d, const uint32_t a[4], const uint32_t b[2]) {
    asm volatile(
        "mma.sync.aligned.m16n8k16.row.col.f32.f16.f16.f32 "
        "{%0,%1,%2,%3}, {%4,%5,%6,%7}, {%8,%9}, {%0,%1,%2,%3};"
        : "+f"(d.x), "+f"(d.y), "+f"(d.z), "+f"(d.w)
        : "r"(a[0]), "r"(a[1]), "r"(a[2]), "r"(a[3]), "r"(b[0]), "r"(b[1]));
}
__device__ __forceinline__ void ldsm_x4(uint32_t& r0, uint32_t& r1, uint32_t& r2, uint32_t& r3,
                                        uint32_t addr) {
    asm volatile("ldmatrix.sync.aligned.m8n8.x4.shared.b16 {%0,%1,%2,%3}, [%4];"
                 : "=r"(r0), "=r"(r1), "=r"(r2), "=r"(r3) : "r"(addr));
}
__device__ __forceinline__ void cp16(uint32_t smem_dst, const void* gsrc, int szbytes) {
    asm volatile("cp.async.cg.shared.global [%0], [%1], 16, %2;"
                 :: "r"(smem_dst), "l"(gsrc), "r"(szbytes));
}
__device__ __forceinline__ void cp_commit() { asm volatile("cp.async.commit_group;"); }
template <int N> __device__ __forceinline__ void cp_wait() {
    asm volatile("cp.async.wait_group %0;" :: "n"(N));
}

// ---------------- fp16 tensor-core GEMM ----------------
enum { F_ACT = 1, F_MUL = 2, F_ADD1 = 4, F_ADD2 = 8, F_HALF = 32, F_NOF32 = 64,
       F_RBFMUL = 128, F_SCATH = 256, F_GATH = 512, F_SPLIT = 1024 };

constexpr int SAK = 40;
constexpr int NSTAGE = 4;
constexpr int AS_BYTES = 128 * SAK * 2;
constexpr int STAGE_BYTES = 2 * AS_BYTES;
constexpr int SMEM_DYN = NSTAGE * STAGE_BYTES;        // 81920

constexpr int RBS = 24;
constexpr int RB_BYTES = 128 * RBS * 2;
constexpr int RB_B_OFF = RB_BYTES;

__device__ __forceinline__ void epi2(float* C, __half* Ct, __half* Sc, size_t idx,
                                     float vx, float vy, float mx, float my,
                                     int flags, const float* Add1, float c1,
                                     const float* Add2, float c2) {
    if (flags & F_ACT)    { vx = scaled_silu(vx);       vy = scaled_silu(vy); }
    if (flags & F_RBFMUL) { vx *= mx;                   vy *= my; }
    if (flags & F_ADD1)   { vx = (Add1[idx] + vx) * c1; vy = (Add1[idx + 1] + vy) * c1; }
    if (flags & F_ADD2)   { vx = (vx + Add2[idx]) * c2; vy = (vy + Add2[idx + 1]) * c2; }
    if (flags & F_SCATH)  *(__half2*)(Sc + idx) = __floats2half2_rn(vx * mx, vy * my);
    if (flags & F_HALF)   *(__half2*)(Ct + idx) = __floats2half2_rn(vx, vy);
    if (!(flags & F_NOF32)) { C[idx] = vx; C[idx + 1] = vy; }
}

// NARROW=false: 128x128 tile, warp 64x32 (MT=4). NARROW=true: 128x64 tile, warp 32x32 (MT=2).
template <bool NARROW>
__global__ __launch_bounds__(256, 2)
void mma_gemm_kernel(const __half* __restrict__ A, const __half* __restrict__ Bt,
                     float* __restrict__ C, __half* __restrict__ Ct,
                     int M, int N, int K, int flags,
                     const float* __restrict__ Add1, float c1,
                     const float* __restrict__ Add2, float c2,
                     const int* __restrict__ idxs, const int* __restrict__ idxt,
                     const __half* __restrict__ Rbf, const __half* __restrict__ Wrb,
                     __half* __restrict__ Scath)
{
    extern __shared__ __align__(16) char dyn_smem[];

    constexpr int MT = NARROW ? 2 : 4;

    const int t = threadIdx.x;
    const int lane = t & 31;
    const int warp = t >> 5;
    const int wm = NARROW ? (warp >> 1) * 32 : (warp >> 2) * 64;
    const int wn = NARROW ? (warp & 1) * 32 : (warp & 3) * 32;
    const int rowC0 = blockIdx.y * 128;
    const int colC0 = blockIdx.x * (NARROW ? 64 : 128);

    const uint32_t smem0 = (uint32_t)__cvta_generic_to_shared(dyn_smem);

    const int arow_l = t & 127;
    const int ako = (t >> 7) * 16;
    const int arow = rowC0 + arow_l;
    const bool aok = arow < M;
    const uint32_t a_dst = smem0 + (uint32_t)(arow_l * SAK + ako) * 2;

    const int brow_l = t & 127;
    const bool bok = !NARROW ? ((colC0 + brow_l) < N) : (brow_l < 64 && (colC0 + brow_l) < N);
    const __half* brp = Bt + (size_t)(bok ? (colC0 + brow_l) : 0) * K;
    const uint32_t b_dst = smem0 + AS_BYTES + (uint32_t)(brow_l * SAK + ako) * 2;

    const int a_row_lm = wm + (lane & 15);
    const int a_kh_lm  = (lane >> 4) * 8;
    const int b_row_lm = wn + (lane & 7) + (lane >> 4) * 8;
    const int b_kh_lm  = ((lane >> 3) & 1) * 8;

    float4 acc[MT][4];
#pragma unroll
    for (int i = 0; i < MT; i++)
#pragma unroll
        for (int j = 0; j < 4; j++) acc[i][j] = make_float4(0.f, 0.f, 0.f, 0.f);

    auto loadTile = [&](int s, int k0) {
        const uint32_t soff = (uint32_t)s * STAGE_BYTES;
        const __half* ap = A + (size_t)(aok ? arow : 0) * K + k0 + ako;
#pragma unroll
        for (int ch = 0; ch < 2; ch++) {
            const bool ok = aok && (k0 + ako + ch * 8) < K;
            cp16(a_dst + soff + 16u * ch, ok ? (const void*)(ap + 8 * ch) : (const void*)A,
                 ok ? 16 : 0);
        }
        const __half* bp = brp + k0 + ako;
#pragma unroll
        for (int ch = 0; ch < 2; ch++) {
            const bool ok = bok && (k0 + ako + ch * 8) < K;
            cp16(b_dst + soff + 16u * ch, ok ? (const void*)(bp + 8 * ch) : (const void*)Bt,
                 ok ? 16 : 0);
        }
    };

    auto computeTile = [&](int s) {
        const uint32_t abase = smem0 + (uint32_t)s * STAGE_BYTES;
        const uint32_t bbase = abase + AS_BYTES;
#pragma unroll
        for (int g = 0; g < 2; g++) {
            uint32_t af[MT][4];
            uint32_t bf[4][2];
#pragma unroll
            for (int mt = 0; mt < MT; mt++)
                ldsm_x4(af[mt][0], af[mt][1], af[mt][2], af[mt][3],
                        abase + (uint32_t)((a_row_lm + mt * 16) * SAK + g * 16 + a_kh_lm) * 2);
#pragma unroll
            for (int p = 0; p < 2; p++)
                ldsm_x4(bf[2 * p][0], bf[2 * p][1], bf[2 * p + 1][0], bf[2 * p + 1][1],
                        bbase + (uint32_t)((b_row_lm + p * 16) * SAK + g * 16 + b_kh_lm) * 2);
#pragma unroll
            for (int mt = 0; mt < MT; mt++)
#pragma unroll
                for (int nt = 0; nt < 4; nt++)
                    mma_f16(acc[mt][nt], af[mt], bf[nt]);
        }
    };

    const int nK = (K + 31) >> 5;
    const int pre = nK < (NSTAGE - 1) ? nK : (NSTAGE - 1);
    for (int s = 0; s < pre; s++) { loadTile(s, s * 32); cp_commit(); }

    for (int i = 0; i < nK; ++i) {
        const int rem = nK - 1 - i;
        if (rem >= 2)      cp_wait<2>();
        else if (rem == 1) cp_wait<1>();
        else               cp_wait<0>();
        __syncthreads();
        if (i + NSTAGE - 1 < nK) { loadTile((i + NSTAGE - 1) & 3, (i + NSTAGE - 1) * 32); cp_commit(); }
        computeTile(i & 3);
    }

    // ---- optional rbf-multiplier epilogue tiles (K=16 MMA) ----
    const bool use_rbf = (flags & (F_RBFMUL | F_SCATH | F_SPLIT)) != 0;
    uint32_t bfr[4][2];
    if (use_rbf) {
        __syncthreads();
        {
            const int r = t & 127;
            const int off = (t >> 7) * 8;
            const int gr = rowC0 + r;
            uint4 av = make_uint4(0, 0, 0, 0);
            if (gr < M) av = *(const uint4*)(Rbf + (size_t)gr * 16 + off);
            *(uint4*)(dyn_smem + ((size_t)r * RBS + off) * 2) = av;
            const int gc = colC0 + r;
            uint4 bv = make_uint4(0, 0, 0, 0);
            if (flags & F_SPLIT) {
                // rbf multiplier applies to cols [512,1024) -> Wrb row gc-512
                if (gc >= 512 && gc < 1024)
                    bv = *(const uint4*)(Wrb + (size_t)(gc - 512) * 16 + off);
            } else {
                if (gc < N) bv = *(const uint4*)(Wrb + (size_t)gc * 16 + off);
            }
            *(uint4*)(dyn_smem + RB_B_OFF + ((size_t)r * RBS + off) * 2) = bv;
        }
        __syncthreads();
        const uint32_t bb = smem0 + RB_B_OFF;
#pragma unroll
        for (int p = 0; p < 2; p++)
            ldsm_x4(bfr[2 * p][0], bfr[2 * p][1], bfr[2 * p + 1][0], bfr[2 * p + 1][1],
                    bb + (uint32_t)((b_row_lm + p * 16) * RBS + b_kh_lm) * 2);
    }

    // epilogue
#pragma unroll
    for (int mt = 0; mt < MT; mt++) {
        float4 mul[4];
        if (use_rbf) {
            uint32_t afr[4];
            ldsm_x4(afr[0], afr[1], afr[2], afr[3],
                    smem0 + (uint32_t)((a_row_lm + mt * 16) * RBS + a_kh_lm) * 2);
#pragma unroll
            for (int nt = 0; nt < 4; nt++) {
                mul[nt] = make_float4(0.f, 0.f, 0.f, 0.f);
                mma_f16(mul[nt], afr, bfr[nt]);
            }
        } else {
#pragma unroll
            for (int nt = 0; nt < 4; nt++) mul[nt] = make_float4(1.f, 1.f, 1.f, 1.f);
        }
        const int r = rowC0 + wm + mt * 16 + (lane >> 2);
        const float* g0a = nullptr; const float* g0b = nullptr;
        const float* g1a = nullptr; const float* g1b = nullptr;
        if (flags & F_GATH) {
            if (r < M)     { g0a = Add1 + (size_t)idxs[r] * 1024;     g0b = Add2 + (size_t)idxt[r] * 1024; }
            if (r + 8 < M) { g1a = Add1 + (size_t)idxs[r + 8] * 1024; g1b = Add2 + (size_t)idxt[r + 8] * 1024; }
        }
#pragma unroll
        for (int nt = 0; nt < 4; nt++) {
            const int cc = colC0 + wn + nt * 8 + (lane & 3) * 2;
            if (cc >= N) continue;
            float4 v = acc[mt][nt];
            const float4 mv = mul[nt];
            if (flags & F_SPLIT) {
                // cols [0,512): fp32 act -> C (stride 512); cols [512,1024): half act*mul -> Ct
                if (cc < 512) {
                    if (r < M) {
                        C[(size_t)r * 512 + cc]     = scaled_silu(v.x);
                        C[(size_t)r * 512 + cc + 1] = scaled_silu(v.y);
                    }
                    if (r + 8 < M) {
                        C[(size_t)(r + 8) * 512 + cc]     = scaled_silu(v.z);
                        C[(size_t)(r + 8) * 512 + cc + 1] = scaled_silu(v.w);
                    }
                } else {
                    const int c2 = cc - 512;
                    if (r < M)
                        *(__half2*)(Ct + (size_t)r * 512 + c2) =
                            __floats2half2_rn(scaled_silu(v.x) * mv.x, scaled_silu(v.y) * mv.y);
                    if (r + 8 < M)
                        *(__half2*)(Ct + (size_t)(r + 8) * 512 + c2) =
                            __floats2half2_rn(scaled_silu(v.z) * mv.z, scaled_silu(v.w) * mv.w);
                }
                continue;
            }
            if (flags & F_GATH) {
                if (g0a) { v.x += g0a[cc] + g0b[cc]; v.y += g0a[cc + 1] + g0b[cc + 1]; }
                if (g1a) { v.z += g1a[cc] + g1b[cc]; v.w += g1a[cc + 1] + g1b[cc + 1]; }
            }
            if (r < M)
                epi2(C, Ct, Scath, (size_t)r * N + cc, v.x, v.y, mv.x, mv.y,
                     (flags & F_GATH) ? (flags & ~(F_ADD1 | F_ADD2)) : flags, Add1, c1, Add2, c2);
            if (r + 8 < M)
                epi2(C, Ct, Scath, (size_t)(r + 8) * N + cc, v.z, v.w, mv.z, mv.w,
                     (flags & F_GATH) ? (flags & ~(F_ADD1 | F_ADD2)) : flags, Add1, c1, Add2, c2);
        }
    }
}

// ---------------- fp32 -> fp16 conversion ----------------
__global__ void conv_half_kernel(const float* __restrict__ src, __half* __restrict__ dst, int n4) {
    const int i = blockIdx.x * blockDim.x + threadIdx.x;
    if (i >= n4) return;
    float4 v = ((const float4*)src)[i];
    __half2* d = (__half2*)dst + 2 * i;
    d[0] = __floats2half2_rn(v.x, v.y);
    d[1] = __floats2half2_rn(v.z, v.w);
}

// ---------------- batched 512x512 transpose ----------------
struct TPtrs { const float* src[16]; __half* dst[16]; };

__global__ void transpose512_batch_kernel(TPtrs p) {
    __shared__ float tile[32][33];
    const float* src = p.src[blockIdx.z];
    __half* dst = p.dst[blockIdx.z];
    const int kb = blockIdx.y * 32, nb = blockIdx.x * 32;
    const int tx = threadIdx.x, ty = threadIdx.y;
#pragma unroll
    for (int dy = 0; dy < 32; dy += 8)
        tile[ty + dy][tx] = src[(size_t)(kb + ty + dy) * 512 + nb + tx];
    __syncthreads();
#pragma unroll
    for (int dy = 0; dy < 32; dy += 8)
        dst[(size_t)(nb + ty + dy) * 512 + kb + tx] = __float2half_rn(tile[tx][ty + dy]);
}

__global__ void transpose_half_kernel(const float* __restrict__ src, __half* __restrict__ dst,
                                      int K, int N) {
    __shared__ float tile[32][33];
    const int kb = blockIdx.y * 32, nb = blockIdx.x * 32;
    const int tx = threadIdx.x, ty = threadIdx.y;
#pragma unroll
    for (int dy = 0; dy < 32; dy += 8) {
        const int k = kb + ty + dy, n = nb + tx;
        if (k < K && n < N) tile[ty + dy][tx] = src[(size_t)k * N + n];
    }
    __syncthreads();
#pragma unroll
    for (int dy = 0; dy < 32; dy += 8) {
        const int n = nb + ty + dy, k = kb + tx;
        if (n < N && k < K) dst[(size_t)n * K + k] = __float2half_rn(tile[tx][ty + dy]);
    }
}

// ---------------- triplet tmp2 ----------------
__global__ void triplet_tmp2_kernel(const __half* __restrict__ down,
                                    const int* __restrict__ id3_ba,
                                    const float* __restrict__ sph,
                                    const float* __restrict__ rbfw1,
                                    __half* __restrict__ t2)
{
    __shared__ int   sIdx[256];
    __shared__ float sS[16 * 112];
    __shared__ float sR[16 * 112];

    const int tid = threadIdx.x;
    const int e0 = blockIdx.x * 16;

    sIdx[tid] = id3_ba[(size_t)e0 * 16 + tid];
    for (int r = tid; r < 16 * 112; r += 256) {
        sS[r] = sph  [(size_t)e0 * 112 + r];
        sR[r] = rbfw1[(size_t)e0 * 112 + r];
    }
    __syncthreads();

    const int team = tid >> 4;
    const int j = tid & 15;
    const int edge = e0 + team;

    float4 G[16];
#pragma unroll
    for (int k = 0; k < 16; k++) {
        const int row = sIdx[team * 16 + k];
        const __half2* dp = (const __half2*)(down + (size_t)row * 64 + j * 4);
        float2 lo = __half22float2(dp[0]);
        float2 hi = __half22float2(dp[1]);
        G[k] = make_float4(lo.x, lo.y, hi.x, hi.y);
    }

    float4 t1[7];
#pragma unroll
    for (int s = 0; s < 7; s++) {
        float4 a = make_float4(0.f, 0.f, 0.f, 0.f);
#pragma unroll
        for (int k = 0; k < 16; k++) {
            const float f = sS[team * 112 + s * 16 + k];
            a.x = fmaf(f, G[k].x, a.x); a.y = fmaf(f, G[k].y, a.y);
            a.z = fmaf(f, G[k].z, a.z); a.w = fmaf(f, G[k].w, a.w);
        }
        t1[s] = a;
    }

#pragma unroll
    for (int i = 0; i < 16; i++) {
        float4 a = make_float4(0.f, 0.f, 0.f, 0.f);
#pragma unroll
        for (int s = 0; s < 7; s++) {
            const float f = sR[team * 112 + i * 7 + s];
            a.x = fmaf(f, t1[s].x, a.x); a.y = fmaf(f, t1[s].y, a.y);
            a.z = fmaf(f, t1[s].z, a.z); a.w = fmaf(f, t1[s].w, a.w);
        }
        __half2* out = (__half2*)(t2 + (size_t)edge * 1024 + i * 64 + j * 4);
        out[0] = __floats2half2_rn(a.x, a.y);
        out[1] = __floats2half2_rn(a.z, a.w);
    }
}

// W_bil[e,i,o] -> WBPh[o][i*64+e]
__global__ void permute_wbil_kernel(const float* __restrict__ wb, __half* __restrict__ out) {
    const int idx = blockIdx.x * blockDim.x + threadIdx.x;
    const int o = idx & 63;
    const int i = (idx >> 6) & 15;
    const int e = idx >> 10;
    out[(size_t)o * 1024 + i * 64 + e] = __float2half_rn(wb[((size_t)(e * 16 + i)) * 64 + o]);
}

// x = (xca_skip + (up2h[:,0:512] + up2h[id_swap,512:1024])*c)*c
__global__ void combine_x_kernel(float* xca, __half* xcah, const __half* __restrict__ up2h,
                                 const int* __restrict__ id_swap) {
    const int idx = blockIdx.x * blockDim.x + threadIdx.x;
    const int e = idx >> 7;
    const int c = idx & 127;
    const int es = id_swap[e];
    const __half2* ap = (const __half2*)(up2h + (size_t)e * 1024 + c * 4);
    const __half2* bp = (const __half2*)(up2h + (size_t)es * 1024 + 512 + c * 4);
    float2 a0 = __half22float2(ap[0]), a1 = __half22float2(ap[1]);
    float2 b0 = __half22float2(bp[0]), b1 = __half22float2(bp[1]);
    float4 x = ((float4*)xca)[idx];
    x.x = (x.x + (a0.x + b0.x) * INV_SQRT2) * INV_SQRT2;
    x.y = (x.y + (a0.y + b0.y) * INV_SQRT2) * INV_SQRT2;
    x.z = (x.z + (a1.x + b1.x) * INV_SQRT2) * INV_SQRT2;
    x.w = (x.w + (a1.y + b1.y) * INV_SQRT2) * INV_SQRT2;
    ((float4*)xca)[idx] = x;
    __half2* xh = (__half2*)xcah + 2 * idx;
    xh[0] = __floats2half2_rn(x.x, x.y);
    xh[1] = __floats2half2_rn(x.z, x.w);
}

// ---------------- CSR build + gather segment-sum ----------------
__global__ void csr_count_kernel(const int* __restrict__ idx_t, int* __restrict__ cnt) {
    const int e = blockIdx.x * blockDim.x + threadIdx.x;
    if (e < NEg) atomicAdd(&cnt[idx_t[e]], 1);
}

__global__ void csr_scan_kernel(const int* __restrict__ cnt, int* __restrict__ off) {
    __shared__ int s[1024];
    const int tid = threadIdx.x;
    const int base = tid * 5;
    int local[5];
    int sum = 0;
#pragma unroll
    for (int i = 0; i < 5; i++) {
        const int idx = base + i;
        const int v = (idx < NAg) ? cnt[idx] : 0;
        local[i] = sum;
        sum += v;
    }
    s[tid] = sum;
    __syncthreads();
    for (int d = 1; d < 1024; d <<= 1) {
        int v = (tid >= d) ? s[tid - d] : 0;
        __syncthreads();
        s[tid] += v;
        __syncthreads();
    }
    const int prev = (tid > 0) ? s[tid - 1] : 0;
#pragma unroll
    for (int i = 0; i < 5; i++) {
        const int idx = base + i;
        if (idx < NAg) off[idx] = prev + local[i];
    }
    if (tid == 1023) off[NAg] = s[1023];
}

__global__ void csr_fill_kernel(const int* __restrict__ idx_t, int* __restrict__ wof,
                                int* __restrict__ elist) {
    const int e = blockIdx.x * blockDim.x + threadIdx.x;
    if (e < NEg) {
        const int p = atomicAdd(&wof[idx_t[e]], 1);
        elist[p] = e;
    }
}

__global__ void gather_atoms_kernel(const __half* __restrict__ scath,
                                    const int* __restrict__ off,
                                    const int* __restrict__ elist,
                                    __half* __restrict__ a1h) {
    const int a = blockIdx.x;
    const int t = threadIdx.x;
    const int s = off[a], e = off[a + 1];
    float4 acc = make_float4(0.f, 0.f, 0.f, 0.f);
    for (int i = s; i < e; i++) {
        const int ed = elist[i];
        const __half2* p = (const __half2*)(scath + (size_t)ed * 512 + t * 4);
        float2 x0 = __half22float2(p[0]);
        float2 x1 = __half22float2(p[1]);
        acc.x += x0.x; acc.y += x0.y; acc.z += x1.x; acc.w += x1.y;
    }
    __half2* o = (__half2*)(a1h + (size_t)a * 512 + t * 4);
    o[0] = __floats2half2_rn(acc.x, acc.y);
    o[1] = __floats2half2_rn(acc.z, acc.w);
}

// ---------------- host orchestration ----------------
static void run_gemm_impl(bool narrow,
                          const __half* A, const __half* Bt, float* C, int M, int N, int K,
                          int flags, __half* Ct,
                          const float* Ad1, float c1, const float* Ad2, float c2,
                          const int* isx, const int* itx,
                          const __half* Rbf, const __half* Wrb, __half* Scath)
{
    static bool attr_set = false;
    if (!attr_set) {
        cudaFuncSetAttribute(mma_gemm_kernel<false>, cudaFuncAttributeMaxDynamicSharedMemorySize, SMEM_DYN);
        cudaFuncSetAttribute(mma_gemm_kernel<true>,  cudaFuncAttributeMaxDynamicSharedMemorySize, SMEM_DYN);
        attr_set = true;
    }
    if (narrow) {
        dim3 grid((N + 63) / 64, (M + 127) / 128);
        mma_gemm_kernel<true><<<grid, 256, SMEM_DYN>>>(A, Bt, C, Ct, M, N, K, flags,
                                                       Ad1, c1, Ad2, c2, isx, itx,
                                                       Rbf, Wrb, Scath);
    } else {
        dim3 grid((N + 127) / 128, (M + 127) / 128);
        mma_gemm_kernel<false><<<grid, 256, SMEM_DYN>>>(A, Bt, C, Ct, M, N, K, flags,
                                                        Ad1, c1, Ad2, c2, isx, itx,
                                                        Rbf, Wrb, Scath);
    }
}
static void run_gemm(const __half* A, const __half* Bt, float* C, int M, int N, int K, int flags,
                     __half* Ct = nullptr,
                     const float* Ad1 = nullptr, float c1 = 1.f,
                     const float* Ad2 = nullptr, float c2 = 1.f,
                     const int* isx = nullptr, const int* itx = nullptr,
                     const __half* Rbf = nullptr, const __half* Wrb = nullptr,
                     __half* Scath = nullptr)
{
    run_gemm_impl(N <= 64, A, Bt, C, M, N, K, flags, Ct, Ad1, c1, Ad2, c2,
                  isx, itx, Rbf, Wrb, Scath);
}
static void run_conv(const float* src, __half* dst, size_t n) {
    const int n4 = (int)(n / 4);
    conv_half_kernel<<<(n4 + 255) / 256, 256>>>(src, dst, n4);
}
static void run_transpose(const float* src, __half* dst, int K, int N) {
    dim3 grid((N + 31) / 32, (K + 31) / 32);
    transpose_half_kernel<<<grid, dim3(32, 8)>>>(src, dst, K, N);
}

extern "C" void kernel_launch(void* const* d_in, const int* in_sizes, int n_in,
                              void* d_out, int out_size)
{
    const float* h_in    = (const float*)d_in[0];
    const float* m_in    = (const float*)d_in[1];
    const float* rbf3    = (const float*)d_in[2];
    const float* rbf_w1  = (const float*)d_in[3];
    const float* sph     = (const float*)d_in[4];
    const float* rbf_h   = (const float*)d_in[5];
    const int*   id3_ba  = (const int*)d_in[6];
    const int*   id_swap = (const int*)d_in[9];
    const int*   idx_s   = (const int*)d_in[10];
    const int*   idx_t   = (const int*)d_in[11];
    const float* W_dense_ca = (const float*)d_in[12];
    const float* W_ba    = (const float*)d_in[13];
    const float* W_rbf3  = (const float*)d_in[14];
    const float* W_down  = (const float*)d_in[15];
    const float* W_bil   = (const float*)d_in[16];
    const float* W_up_ca = (const float*)d_in[17];
    const float* W_up_ac = (const float*)d_in[18];
    const float* W_bs    = (const float*)d_in[19];
    const float* W_as    = (const float*)d_in[20];
    const float* W_au_rbf= (const float*)d_in[21];
    const float* W_au_d1 = (const float*)d_in[22];
    const float* W_au_res= (const float*)d_in[23];
    const float* W_cat   = (const float*)d_in[24];
    const float* W_res_m = (const float*)d_in[25];

    float* pool = nullptr;
    cudaGetSymbolAddress((void**)&pool, g_pool);
    float*  XCA  = pool + OFF_XCA;
    float*  Mb   = pool + OFF_MB;
    float*  A2   = pool + OFF_A1;
    float*  HST  = pool + OFF_TMP;
    __half* Mh   = (__half*)(pool + OFF_MH);
    __half* TMPh = (__half*)(pool + OFF_TMPH);
    __half* XCAh = (__half*)(pool + OFF_XCAH);
    __half* Mbh  = (__half*)(pool + OFF_MBH);
    __half* DWNh = (__half*)(pool + OFF_DWNH);
    __half* XBh  = (__half*)(pool + OFF_XBH);
    __half* T2h  = (__half*)(pool + OFF_T2H);
    __half* R3h  = (__half*)(pool + OFF_R3H);
    __half* RHh  = (__half*)(pool + OFF_RHH);
    __half* A1h  = (__half*)(pool + OFF_A1H);
    __half* A2h  = (__half*)(pool + OFF_A2H);
    __half* A3h  = (__half*)(pool + OFF_A3H);
    __half* OHh  = (__half*)(pool + OFF_OHH);
    __half* WH   = (__half*)(pool + OFF_WTSH);
    int*    csr_cnt   = (int*)(pool + OFF_CSR);
    int*    csr_off   = csr_cnt + 5008;
    int*    csr_wof   = csr_off + 5008;
    int*    csr_elist = csr_wof + 5008;

    const size_t W2 = (size_t)DDg * DDg;
    __half* Wh_dense_ca = WH;            size_t woff = W2;   // [0:512) of split B
    __half* Wh_ba       = WH + woff;     woff += W2;         // [512:1024) of split B
    __half* Wh_rbf3     = WH + woff;     woff += (size_t)DDg * 16;
    __half* Wh_down     = WH + woff;     woff += (size_t)DTg * DDg;
    __half* Wh_up_ca    = WH + woff;     woff += (size_t)DDg * DTg;
    __half* Wh_up_ac    = WH + woff;     woff += (size_t)DDg * DTg;
    __half* Wh_bs       = WH + woff;     woff += 2 * W2;
    __half* Wh_as       = WH + woff;     woff += 4 * W2;
    __half* Wh_au_rbf   = WH + woff;     woff += (size_t)DDg * 16;
    __half* Wh_au_d1    = WH + woff;     woff += W2;
    __half* Wh_au_res   = WH + woff;     woff += 6 * W2;
    __half* Wh_cat1     = WH + woff;     woff += W2;
    __half* Wh_cat2     = WH + woff;     woff += W2;
    __half* Wh_cat3     = WH + woff;     woff += W2;
    __half* Wh_res_m    = WH + woff;     woff += 2 * W2;
    __half* WBPh        = WH + woff;     woff += (size_t)DTg * 1024;

    float* OUT_H = (float*)d_out;
    float* OUT_M = (float*)d_out + NA512;

    const float C = INV_SQRT2;

    // ---- CSR build ----
    cudaMemsetAsync(csr_cnt, 0, 5008 * sizeof(int));
    csr_count_kernel<<<(NEg + 255) / 256, 256>>>(idx_t, csr_cnt);
    csr_scan_kernel<<<1, 1024>>>(csr_cnt, csr_off);
    cudaMemcpyAsync(csr_wof, csr_off, 5008 * sizeof(int), cudaMemcpyDeviceToDevice);
    csr_fill_kernel<<<(NEg + 255) / 256, 256>>>(idx_t, csr_wof, csr_elist);

    // ---- pre-conversions ----
    run_conv(m_in, Mh, NE512);
    run_conv(rbf3, R3h, NE16);
    run_conv(rbf_h, RHh, NE16);
    {
        TPtrs tp{};
        int n = 0;
        tp.src[n] = W_dense_ca; tp.dst[n] = Wh_dense_ca; n++;
        tp.src[n] = W_ba;       tp.dst[n] = Wh_ba;       n++;
        tp.src[n] = W_au_d1;    tp.dst[n] = Wh_au_d1;    n++;
        for (int i = 0; i < 2; i++) { tp.src[n] = W_bs + i * W2;     tp.dst[n] = Wh_bs + i * W2;     n++; }
        for (int i = 0; i < 4; i++) { tp.src[n] = W_as + i * W2;     tp.dst[n] = Wh_as + i * W2;     n++; }
        for (int i = 0; i < 6; i++) { tp.src[n] = W_au_res + i * W2; tp.dst[n] = Wh_au_res + i * W2; n++; }
        tp.src[n] = W_cat;      tp.dst[n] = Wh_cat1;     n++;   // n=16
        transpose512_batch_kernel<<<dim3(16, 16, n), dim3(32, 8)>>>(tp);
    }
    {
        TPtrs tp{};
        tp.src[0] = W_cat + W2;      tp.dst[0] = Wh_cat2;
        tp.src[1] = W_cat + 2 * W2;  tp.dst[1] = Wh_cat3;
        tp.src[2] = W_res_m;         tp.dst[2] = Wh_res_m;
        tp.src[3] = W_res_m + W2;    tp.dst[3] = Wh_res_m + W2;
        transpose512_batch_kernel<<<dim3(16, 16, 4), dim3(32, 8)>>>(tp);
    }
    run_transpose(W_rbf3, Wh_rbf3, 16, DDg);
    run_transpose(W_down, Wh_down, DDg, DTg);
    run_transpose(W_up_ca, Wh_up_ca, DTg, DDg);
    run_transpose(W_up_ac, Wh_up_ac, DTg, DDg);
    run_transpose(W_au_rbf, Wh_au_rbf, 16, DDg);
    permute_wbil_kernel<<<(NCBF * DTg * DTg) / 256, 256>>>(W_bil, WBPh);

    // ---- pipeline ----
    // merged split GEMM: cols 0-511 -> XCA = act(m@W_dense_ca) (fp32),
    //                    cols 512-1023 -> TMPh = half(act(m@W_ba) * rbfmul)
    run_gemm(Mh, Wh_dense_ca, XCA, NEg, 1024, DDg, F_SPLIT,
             TMPh, nullptr, 1.f, nullptr, 1.f, nullptr, nullptr,
             R3h, Wh_rbf3, nullptr);
    run_gemm(TMPh, Wh_down, nullptr, NEg, DTg, DDg, F_ACT | F_HALF | F_NOF32, DWNh);

    triplet_tmp2_kernel<<<NEg / 16, 256>>>(DWNh, id3_ba, sph, rbf_w1, T2h);
    run_gemm(T2h, WBPh, nullptr, NEg, DTg, NCBF * DTg, F_HALF | F_NOF32, XBh);

    run_gemm(XBh, Wh_up_ca, nullptr, NEg, 1024, DTg, F_ACT | F_HALF | F_NOF32, T2h);
    combine_x_kernel<<<(NEg * 128) / 256, 256>>>(XCA, XCAh, T2h, id_swap);

    run_gemm(XCAh, Wh_bs, nullptr, NEg, DDg, DDg, F_ACT | F_HALF | F_NOF32, TMPh);
    run_gemm(TMPh, Wh_bs + W2, Mb, NEg, DDg, DDg, F_ACT | F_ADD1 | F_ADD2 | F_HALF,
             Mbh, XCA, C, m_in, C);

    run_gemm(Mbh, Wh_as + 0 * W2, nullptr, NEg, DDg, DDg, F_ACT | F_HALF | F_NOF32, TMPh);
    run_gemm(TMPh, Wh_as + 1 * W2, Mb, NEg, DDg, DDg, F_ACT | F_ADD1 | F_HALF,
             Mbh, Mb, C);
    run_gemm(Mbh, Wh_as + 2 * W2, nullptr, NEg, DDg, DDg, F_ACT | F_HALF | F_NOF32, TMPh);
    run_gemm(TMPh, Wh_as + 3 * W2, Mb, NEg, DDg, DDg, F_ACT | F_ADD1 | F_HALF | F_SCATH,
             Mbh, Mb, C, nullptr, 1.f, nullptr, nullptr,
             RHh, Wh_au_rbf, XCAh);

    gather_atoms_kernel<<<NAg, 128>>>(XCAh, csr_off, csr_elist, A1h);
    run_gemm(A1h, Wh_au_d1, A2, NAg, DDg, DDg, F_ACT | F_HALF, A2h);
    run_gemm(A2h, Wh_au_res + 0 * W2, nullptr, NAg, DDg, DDg, F_ACT | F_HALF | F_NOF32, A3h);
    run_gemm(A3h, Wh_au_res + 1 * W2, A2, NAg, DDg, DDg, F_ACT | F_ADD1 | F_HALF,
             A2h, A2, C);
    run_gemm(A2h, Wh_au_res + 2 * W2, nullptr, NAg, DDg, DDg, F_ACT | F_HALF | F_NOF32, A3h);
    run_gemm(A3h, Wh_au_res + 3 * W2, A2, NAg, DDg, DDg, F_ACT | F_ADD1 | F_HALF,
             A2h, A2, C);
    run_gemm(A2h, Wh_au_res + 4 * W2, nullptr, NAg, DDg, DDg, F_ACT | F_HALF | F_NOF32, A3h);
    run_gemm(A3h, Wh_au_res + 5 * W2, OUT_H, NAg, DDg, DDg,
             F_ACT | F_ADD1 | F_ADD2 | F_HALF, OHh, A2, C, h_in, C);

    run_gemm(OHh, Wh_cat1, HST, NAg, 1024, DDg, 0);
    run_gemm(Mbh, Wh_cat3, XCA, NEg, DDg, DDg, F_ACT | F_GATH | F_HALF,
             XCAh, HST, 1.f, HST + 512, 1.f, idx_s, idx_t);

    run_gemm(XCAh, Wh_res_m, nullptr, NEg, DDg, DDg, F_ACT | F_HALF | F_NOF32, TMPh);
    run_gemm(TMPh, Wh_res_m + W2, OUT_M, NEg, DDg, DDg, F_ACT | F_ADD1 | F_ADD2,
             nullptr, XCA, C, Mb, C);

    (void)in_sizes; (void)n_in; (void)out_size;
}